// round 1
// baseline (speedup 1.0000x reference)
#include <cuda_runtime.h>
#include <math.h>

#define BS   2
#define SEQ  2048
#define DIM  1024
#define HID  4096
#define NH   16
#define DPH  64
#define MROWS (BS*SEQ)   // 4096

// ---------------- scratch (no allocation allowed) ----------------
__device__ float g_q  [MROWS*DIM];
__device__ float g_k  [MROWS*DIM];
__device__ float g_v  [MROWS*DIM];
__device__ float g_ctx[MROWS*DIM];
__device__ float g_h1 [MROWS*DIM];
__device__ float g_ffn[MROWS*HID];

__device__ __forceinline__ float gelu_f(float x) {
    return 0.5f * x * (1.0f + erff(x * 0.70710678118654752f));
}

// ---------------- GEMM: C[M,N] = A[M,K] @ W[K,N] + bias, optional GELU ----
// 64x64 block tile, 256 threads, 4x4 microtile, BK=16
template<int ACT>
__global__ void gemm_bias_kernel(const float* __restrict__ A,
                                 const float* __restrict__ W,
                                 const float* __restrict__ bias,
                                 float* __restrict__ C,
                                 int M, int K, int N) {
    __shared__ float As[16][68];   // As[k][m], padded
    __shared__ float Bs[16][64];   // Bs[k][n]
    const int tid = threadIdx.x;
    const int tx = tid & 15, ty = tid >> 4;
    const int m0 = blockIdx.y * 64, n0 = blockIdx.x * 64;

    float acc[4][4] = {};

    for (int k0 = 0; k0 < K; k0 += 16) {
        #pragma unroll
        for (int i = 0; i < 4; i++) {
            int idx = tid + i * 256;          // 0..1023
            int am = idx >> 4, ak = idx & 15;
            As[ak][am] = A[(size_t)(m0 + am) * K + k0 + ak];
            int bk = idx >> 6, bn = idx & 63;
            Bs[bk][bn] = W[(size_t)(k0 + bk) * N + n0 + bn];
        }
        __syncthreads();
        #pragma unroll
        for (int kk = 0; kk < 16; kk++) {
            float4 a4 = *(const float4*)&As[kk][ty * 4];
            float4 b4 = *(const float4*)&Bs[kk][tx * 4];
            float av[4] = {a4.x, a4.y, a4.z, a4.w};
            float bv[4] = {b4.x, b4.y, b4.z, b4.w};
            #pragma unroll
            for (int i = 0; i < 4; i++)
                #pragma unroll
                for (int j = 0; j < 4; j++)
                    acc[i][j] += av[i] * bv[j];
        }
        __syncthreads();
    }

    #pragma unroll
    for (int i = 0; i < 4; i++) {
        int row = m0 + ty * 4 + i;
        float4 o;
        float* po = (float*)&o;
        #pragma unroll
        for (int j = 0; j < 4; j++) {
            int col = n0 + tx * 4 + j;
            float v = acc[i][j] + bias[col];
            if (ACT == 1) v = gelu_f(v);
            po[j] = v;
        }
        *(float4*)&C[(size_t)row * N + n0 + tx * 4] = o;
    }
}

// ---------------- Flash attention ----------------
// grid: (SEQ/64, NH, BS); 256 threads. Q pre-scaled by 1/8 at load.
__global__ void attn_kernel(const float* __restrict__ Q,
                            const float* __restrict__ K,
                            const float* __restrict__ V,
                            const int*   __restrict__ mask,
                            float* __restrict__ ctx) {
    extern __shared__ float sm[];
    float* Qt    = sm;                 // [64][68]  Qt[d][r]
    float* Kt    = Qt + 64 * 68;       // [64][68]  Kt[d][c]
    float* Vs    = Kt + 64 * 68;       // [64][68]  Vs[c][d]
    float* Pt    = Vs + 64 * 68;       // [64][68]  Pt[c][r]
    float* smask = Pt + 64 * 68;       // [64]

    const int tid = threadIdx.x;
    const int tx = tid & 15, ty = tid >> 4;
    const int q0 = blockIdx.x * 64;
    const int h  = blockIdx.y;
    const int b  = blockIdx.z;
    const size_t base = (size_t)b * SEQ * DIM + h * DPH;

    // load Q tile transposed, scaled by 1/sqrt(dph)=0.125
    for (int idx = tid; idx < 64 * 64; idx += 256) {
        int r = idx >> 6, d = idx & 63;
        Qt[d * 68 + r] = Q[base + (size_t)(q0 + r) * DIM + d] * 0.125f;
    }

    float acc[4][4] = {};
    float mrow[4], lrow[4];
    #pragma unroll
    for (int i = 0; i < 4; i++) { mrow[i] = -INFINITY; lrow[i] = 0.0f; }

    for (int kv0 = 0; kv0 < SEQ; kv0 += 64) {
        for (int idx = tid; idx < 64 * 64; idx += 256) {
            int c = idx >> 6, d = idx & 63;
            size_t g = base + (size_t)(kv0 + c) * DIM + d;
            Kt[d * 68 + c] = K[g];
            Vs[c * 68 + d] = V[g];
        }
        if (tid < 64)
            smask[tid] = (mask[b * SEQ + kv0 + tid] == 0) ? -INFINITY : 0.0f;
        __syncthreads();

        // S = Q K^T  (4x4 per thread)
        float s[4][4] = {};
        #pragma unroll 8
        for (int d = 0; d < 64; d++) {
            float4 qa = *(const float4*)&Qt[d * 68 + ty * 4];
            float4 kb = *(const float4*)&Kt[d * 68 + tx * 4];
            float qv[4] = {qa.x, qa.y, qa.z, qa.w};
            float kv[4] = {kb.x, kb.y, kb.z, kb.w};
            #pragma unroll
            for (int i = 0; i < 4; i++)
                #pragma unroll
                for (int j = 0; j < 4; j++)
                    s[i][j] += qv[i] * kv[j];
        }
        // mask
        #pragma unroll
        for (int j = 0; j < 4; j++) {
            float mj = smask[tx * 4 + j];
            #pragma unroll
            for (int i = 0; i < 4; i++) s[i][j] += mj;
        }

        // online softmax per row (16 lanes own one row)
        #pragma unroll
        for (int i = 0; i < 4; i++) {
            float mt = fmaxf(fmaxf(s[i][0], s[i][1]), fmaxf(s[i][2], s[i][3]));
            #pragma unroll
            for (int off = 8; off >= 1; off >>= 1)
                mt = fmaxf(mt, __shfl_xor_sync(0xffffffffu, mt, off));
            float mnew = fmaxf(mrow[i], mt);
            float alpha = __expf(mrow[i] - mnew);
            float lsum = 0.0f;
            #pragma unroll
            for (int j = 0; j < 4; j++) {
                float p = __expf(s[i][j] - mnew);
                s[i][j] = p;
                lsum += p;
            }
            #pragma unroll
            for (int off = 8; off >= 1; off >>= 1)
                lsum += __shfl_xor_sync(0xffffffffu, lsum, off);
            lrow[i] = lrow[i] * alpha + lsum;
            mrow[i] = mnew;
            #pragma unroll
            for (int j = 0; j < 4; j++) acc[i][j] *= alpha;
        }

        // write P transposed
        #pragma unroll
        for (int i = 0; i < 4; i++)
            #pragma unroll
            for (int j = 0; j < 4; j++)
                Pt[(tx * 4 + j) * 68 + ty * 4 + i] = s[i][j];
        __syncthreads();

        // O += P @ V
        #pragma unroll 8
        for (int c = 0; c < 64; c++) {
            float4 pa = *(const float4*)&Pt[c * 68 + ty * 4];
            float4 vb = *(const float4*)&Vs[c * 68 + tx * 4];
            float pv[4] = {pa.x, pa.y, pa.z, pa.w};
            float vv[4] = {vb.x, vb.y, vb.z, vb.w};
            #pragma unroll
            for (int i = 0; i < 4; i++)
                #pragma unroll
                for (int j = 0; j < 4; j++)
                    acc[i][j] += pv[i] * vv[j];
        }
        __syncthreads();
    }

    // normalize + write ctx (b, s, h, d) layout
    #pragma unroll
    for (int i = 0; i < 4; i++) {
        float inv = 1.0f / lrow[i];
        int row = q0 + ty * 4 + i;
        float4 o;
        o.x = acc[i][0] * inv; o.y = acc[i][1] * inv;
        o.z = acc[i][2] * inv; o.w = acc[i][3] * inv;
        *(float4*)&ctx[base + (size_t)row * DIM + tx * 4] = o;
    }
}

// ---------------- residual + LayerNorm ----------------
__global__ void ln_residual_kernel(const float* __restrict__ a,
                                   const float* __restrict__ r,
                                   const float* __restrict__ gamma,
                                   const float* __restrict__ beta,
                                   float* __restrict__ out) {
    const int row = blockIdx.x;
    const int tid = threadIdx.x;
    const float* pa = a + (size_t)row * DIM;
    const float* pr = r + (size_t)row * DIM;

    float v[4];
    float sum = 0.0f, sq = 0.0f;
    #pragma unroll
    for (int i = 0; i < 4; i++) {
        int c = tid + i * 256;
        float t = pa[c] + pr[c];
        v[i] = t;
        sum += t;
        sq  += t * t;
    }
    #pragma unroll
    for (int off = 16; off >= 1; off >>= 1) {
        sum += __shfl_xor_sync(0xffffffffu, sum, off);
        sq  += __shfl_xor_sync(0xffffffffu, sq,  off);
    }
    __shared__ float ssum[8], ssq[8];
    int warp = tid >> 5, lane = tid & 31;
    if (lane == 0) { ssum[warp] = sum; ssq[warp] = sq; }
    __syncthreads();
    sum = 0.0f; sq = 0.0f;
    #pragma unroll
    for (int i = 0; i < 8; i++) { sum += ssum[i]; sq += ssq[i]; }

    const float invN = 1.0f / (float)DIM;
    float mu  = sum * invN;
    float var = fmaxf(sq * invN - mu * mu, 0.0f);
    float rstd = rsqrtf(var + 1e-12f);

    #pragma unroll
    for (int i = 0; i < 4; i++) {
        int c = tid + i * 256;
        out[(size_t)row * DIM + c] = (v[i] - mu) * rstd * gamma[c] + beta[c];
    }
}

// ---------------- launch ----------------
extern "C" void kernel_launch(void* const* d_in, const int* in_sizes, int n_in,
                              void* d_out, int out_size) {
    const float* x    = (const float*)d_in[0];
    const int*   mask = (const int*)  d_in[1];
    const float* Wq   = (const float*)d_in[2];
    const float* bq   = (const float*)d_in[3];
    const float* Wk   = (const float*)d_in[4];
    const float* bk   = (const float*)d_in[5];
    const float* Wv   = (const float*)d_in[6];
    const float* bv   = (const float*)d_in[7];
    const float* Wo   = (const float*)d_in[8];
    const float* bo   = (const float*)d_in[9];
    const float* ln1g = (const float*)d_in[10];
    const float* ln1b = (const float*)d_in[11];
    const float* W1   = (const float*)d_in[12];
    const float* b1   = (const float*)d_in[13];
    const float* W2   = (const float*)d_in[14];
    const float* b2   = (const float*)d_in[15];
    const float* ln2g = (const float*)d_in[16];
    const float* ln2b = (const float*)d_in[17];
    float* out = (float*)d_out;

    float *q, *k, *v, *ctx, *h1, *ffn;
    cudaGetSymbolAddress((void**)&q,   g_q);
    cudaGetSymbolAddress((void**)&k,   g_k);
    cudaGetSymbolAddress((void**)&v,   g_v);
    cudaGetSymbolAddress((void**)&ctx, g_ctx);
    cudaGetSymbolAddress((void**)&h1,  g_h1);
    cudaGetSymbolAddress((void**)&ffn, g_ffn);

    const dim3 gD(DIM / 64, MROWS / 64);   // N=1024 gemms
    const dim3 gH(HID / 64, MROWS / 64);   // N=4096 gemm

    // QKV projections
    gemm_bias_kernel<0><<<gD, 256>>>(x, Wq, bq, q, MROWS, DIM, DIM);
    gemm_bias_kernel<0><<<gD, 256>>>(x, Wk, bk, k, MROWS, DIM, DIM);
    gemm_bias_kernel<0><<<gD, 256>>>(x, Wv, bv, v, MROWS, DIM, DIM);

    // attention
    int smem = (4 * 64 * 68 + 64) * (int)sizeof(float);  // 69888 B
    cudaFuncSetAttribute(attn_kernel, cudaFuncAttributeMaxDynamicSharedMemorySize, smem);
    attn_kernel<<<dim3(SEQ / 64, NH, BS), 256, smem>>>(q, k, v, mask, ctx);

    // output projection (reuse q as sa_out)
    gemm_bias_kernel<0><<<gD, 256>>>(ctx, Wo, bo, q, MROWS, DIM, DIM);

    // LN1(sa_out + x) -> h1
    ln_residual_kernel<<<MROWS, 256>>>(q, x, ln1g, ln1b, h1);

    // FFN
    gemm_bias_kernel<1><<<gH, 256>>>(h1, W1, b1, ffn, MROWS, DIM, HID);
    gemm_bias_kernel<0><<<gD, 256>>>(ffn, W2, b2, k, MROWS, HID, DIM);

    // LN2(ffn_out + h1) -> out
    ln_residual_kernel<<<MROWS, 256>>>(k, h1, ln2g, ln2b, out);
}

// round 4
// speedup vs baseline: 1.8718x; 1.8718x over previous
#include <cuda_runtime.h>
#include <math.h>
#include <stdint.h>

#define BS   2
#define SEQ  2048
#define DIM  1024
#define HID  4096
#define NH   16
#define DPH  64
#define MROWS (BS*SEQ)   // 4096

// ---------------- scratch (no allocation allowed) ----------------
__device__ float g_q  [MROWS*DIM];
__device__ float g_k  [MROWS*DIM];
__device__ float g_v  [MROWS*DIM];
__device__ float g_ctx[MROWS*DIM];
__device__ float g_h1 [MROWS*DIM];
__device__ float g_ffn[MROWS*HID];

__device__ __forceinline__ uint32_t f2tf32(float f) {
    uint32_t r;
    asm("cvt.rna.tf32.f32 %0, %1;" : "=r"(r) : "f"(f));
    return r;
}

__device__ __forceinline__ void mma_tf32(float* d,
                                         uint32_t a0, uint32_t a1, uint32_t a2, uint32_t a3,
                                         uint32_t b0, uint32_t b1) {
    asm volatile(
        "mma.sync.aligned.m16n8k8.row.col.f32.tf32.tf32.f32 "
        "{%0,%1,%2,%3}, {%4,%5,%6,%7}, {%8,%9}, {%0,%1,%2,%3};"
        : "+f"(d[0]), "+f"(d[1]), "+f"(d[2]), "+f"(d[3])
        : "r"(a0), "r"(a1), "r"(a2), "r"(a3), "r"(b0), "r"(b1));
}

__device__ __forceinline__ float gelu_f(float x) {
    return 0.5f * x * (1.0f + erff(x * 0.70710678118654752f));
}

// ---------------- tf32 mma.sync GEMM: C[M,N] = A[M,K] @ W[K,N] + bias ----------------
// CTA 128x128, BK=32, 256 threads (8 warps), warp tile 32(M) x 64(N).
// As[m][k] stride 36 (fragment LDS conflict-free, 16B-aligned rows)
// Bs[k][n] stride 136 (fragment LDS conflict-free, 16B-aligned rows)
#define AS_STRIDE 36
#define BS_STRIDE 136

template<int ACT>
__global__ void __launch_bounds__(256)
gemm_mma(const float* __restrict__ A, const float* __restrict__ W,
         const float* __restrict__ bias, float* __restrict__ C,
         int M, int K, int N) {
    __shared__ uint32_t As[128 * AS_STRIDE];   // 18432 B
    __shared__ uint32_t Bsm[32 * BS_STRIDE];   // 17408 B

    const int tid  = threadIdx.x;
    const int wid  = tid >> 5;
    const int lane = tid & 31;
    const int grp  = lane >> 2;      // 0..7
    const int t4   = lane & 3;       // 0..3
    const int m0 = blockIdx.y * 128, n0 = blockIdx.x * 128;
    const int wm = (wid & 3) * 32;   // warp m offset in tile
    const int wn = (wid >> 2) * 64;  // warp n offset in tile

    float acc[2][8][4];
    #pragma unroll
    for (int i = 0; i < 2; i++)
        #pragma unroll
        for (int j = 0; j < 8; j++)
            #pragma unroll
            for (int c = 0; c < 4; c++) acc[i][j][c] = 0.0f;

    const int nit = K / 32;
    for (int it = 0; it < nit; it++) {
        // ---- load A tile 128x32 (row-major), cvt to tf32, STS.128 ----
        const float* Ab = A + (size_t)m0 * K + (size_t)it * 32;
        #pragma unroll
        for (int i = 0; i < 4; i++) {
            int idx = tid + i * 256;
            int row = idx >> 3, c4 = idx & 7;
            float4 v = *(const float4*)(Ab + (size_t)row * K + c4 * 4);
            uint4 u;
            u.x = f2tf32(v.x); u.y = f2tf32(v.y); u.z = f2tf32(v.z); u.w = f2tf32(v.w);
            *(uint4*)&As[row * AS_STRIDE + c4 * 4] = u;
        }
        // ---- load B tile 32x128 (row n-major), cvt, STS.128 ----
        const float* Wb = W + (size_t)(it * 32) * N + n0;
        #pragma unroll
        for (int i = 0; i < 4; i++) {
            int idx = tid + i * 256;
            int k = idx >> 5, nq = idx & 31;
            float4 v = *(const float4*)(Wb + (size_t)k * N + nq * 4);
            uint4 u;
            u.x = f2tf32(v.x); u.y = f2tf32(v.y); u.z = f2tf32(v.z); u.w = f2tf32(v.w);
            *(uint4*)&Bsm[k * BS_STRIDE + nq * 4] = u;
        }
        __syncthreads();

        // ---- compute: 4 k-steps of m16n8k8 ----
        #pragma unroll
        for (int kk = 0; kk < 4; kk++) {
            const int kb = kk * 8;
            uint32_t afr[2][4];
            #pragma unroll
            for (int mt = 0; mt < 2; mt++) {
                const int rb = wm + mt * 16;
                afr[mt][0] = As[(rb + grp)     * AS_STRIDE + kb + t4];
                afr[mt][1] = As[(rb + grp + 8) * AS_STRIDE + kb + t4];
                afr[mt][2] = As[(rb + grp)     * AS_STRIDE + kb + t4 + 4];
                afr[mt][3] = As[(rb + grp + 8) * AS_STRIDE + kb + t4 + 4];
            }
            uint32_t bfr[8][2];
            #pragma unroll
            for (int nt = 0; nt < 8; nt++) {
                const int col = wn + nt * 8 + grp;
                bfr[nt][0] = Bsm[(kb + t4)     * BS_STRIDE + col];
                bfr[nt][1] = Bsm[(kb + t4 + 4) * BS_STRIDE + col];
            }
            #pragma unroll
            for (int mt = 0; mt < 2; mt++)
                #pragma unroll
                for (int nt = 0; nt < 8; nt++)
                    mma_tf32(acc[mt][nt], afr[mt][0], afr[mt][1], afr[mt][2], afr[mt][3],
                             bfr[nt][0], bfr[nt][1]);
        }
        __syncthreads();
    }

    // ---- epilogue: bias (+gelu), write float2 pairs ----
    #pragma unroll
    for (int mt = 0; mt < 2; mt++) {
        #pragma unroll
        for (int nt = 0; nt < 8; nt++) {
            const int col = n0 + wn + nt * 8 + t4 * 2;
            const float b0v = bias[col], b1v = bias[col + 1];
            const int r0 = m0 + wm + mt * 16 + grp;
            float v0 = acc[mt][nt][0] + b0v;
            float v1 = acc[mt][nt][1] + b1v;
            float v2 = acc[mt][nt][2] + b0v;
            float v3 = acc[mt][nt][3] + b1v;
            if (ACT == 1) { v0 = gelu_f(v0); v1 = gelu_f(v1); v2 = gelu_f(v2); v3 = gelu_f(v3); }
            float2 p0 = make_float2(v0, v1);
            float2 p1 = make_float2(v2, v3);
            *(float2*)&C[(size_t)r0 * N + col]       = p0;
            *(float2*)&C[(size_t)(r0 + 8) * N + col] = p1;
        }
    }
}

// ---------------- Flash attention (fp32, unchanged) ----------------
__global__ void attn_kernel(const float* __restrict__ Q,
                            const float* __restrict__ K,
                            const float* __restrict__ V,
                            const int*   __restrict__ mask,
                            float* __restrict__ ctx) {
    extern __shared__ float sm[];
    float* Qt    = sm;
    float* Kt    = Qt + 64 * 68;
    float* Vs    = Kt + 64 * 68;
    float* Pt    = Vs + 64 * 68;
    float* smask = Pt + 64 * 68;

    const int tid = threadIdx.x;
    const int tx = tid & 15, ty = tid >> 4;
    const int q0 = blockIdx.x * 64;
    const int h  = blockIdx.y;
    const int b  = blockIdx.z;
    const size_t base = (size_t)b * SEQ * DIM + h * DPH;

    for (int idx = tid; idx < 64 * 64; idx += 256) {
        int r = idx >> 6, d = idx & 63;
        Qt[d * 68 + r] = Q[base + (size_t)(q0 + r) * DIM + d] * 0.125f;
    }

    float acc[4][4] = {};
    float mrow[4], lrow[4];
    #pragma unroll
    for (int i = 0; i < 4; i++) { mrow[i] = -INFINITY; lrow[i] = 0.0f; }

    for (int kv0 = 0; kv0 < SEQ; kv0 += 64) {
        for (int idx = tid; idx < 64 * 64; idx += 256) {
            int c = idx >> 6, d = idx & 63;
            size_t g = base + (size_t)(kv0 + c) * DIM + d;
            Kt[d * 68 + c] = K[g];
            Vs[c * 68 + d] = V[g];
        }
        if (tid < 64)
            smask[tid] = (mask[b * SEQ + kv0 + tid] == 0) ? -INFINITY : 0.0f;
        __syncthreads();

        float s[4][4] = {};
        #pragma unroll 8
        for (int d = 0; d < 64; d++) {
            float4 qa = *(const float4*)&Qt[d * 68 + ty * 4];
            float4 kb = *(const float4*)&Kt[d * 68 + tx * 4];
            float qv[4] = {qa.x, qa.y, qa.z, qa.w};
            float kv[4] = {kb.x, kb.y, kb.z, kb.w};
            #pragma unroll
            for (int i = 0; i < 4; i++)
                #pragma unroll
                for (int j = 0; j < 4; j++)
                    s[i][j] += qv[i] * kv[j];
        }
        #pragma unroll
        for (int j = 0; j < 4; j++) {
            float mj = smask[tx * 4 + j];
            #pragma unroll
            for (int i = 0; i < 4; i++) s[i][j] += mj;
        }

        #pragma unroll
        for (int i = 0; i < 4; i++) {
            float mt = fmaxf(fmaxf(s[i][0], s[i][1]), fmaxf(s[i][2], s[i][3]));
            #pragma unroll
            for (int off = 8; off >= 1; off >>= 1)
                mt = fmaxf(mt, __shfl_xor_sync(0xffffffffu, mt, off));
            float mnew = fmaxf(mrow[i], mt);
            float alpha = __expf(mrow[i] - mnew);
            float lsum = 0.0f;
            #pragma unroll
            for (int j = 0; j < 4; j++) {
                float p = __expf(s[i][j] - mnew);
                s[i][j] = p;
                lsum += p;
            }
            #pragma unroll
            for (int off = 8; off >= 1; off >>= 1)
                lsum += __shfl_xor_sync(0xffffffffu, lsum, off);
            lrow[i] = lrow[i] * alpha + lsum;
            mrow[i] = mnew;
            #pragma unroll
            for (int j = 0; j < 4; j++) acc[i][j] *= alpha;
        }

        #pragma unroll
        for (int i = 0; i < 4; i++)
            #pragma unroll
            for (int j = 0; j < 4; j++)
                Pt[(tx * 4 + j) * 68 + ty * 4 + i] = s[i][j];
        __syncthreads();

        #pragma unroll 8
        for (int c = 0; c < 64; c++) {
            float4 pa = *(const float4*)&Pt[c * 68 + ty * 4];
            float4 vb = *(const float4*)&Vs[c * 68 + tx * 4];
            float pv[4] = {pa.x, pa.y, pa.z, pa.w};
            float vv[4] = {vb.x, vb.y, vb.z, vb.w};
            #pragma unroll
            for (int i = 0; i < 4; i++)
                #pragma unroll
                for (int j = 0; j < 4; j++)
                    acc[i][j] += pv[i] * vv[j];
        }
        __syncthreads();
    }

    #pragma unroll
    for (int i = 0; i < 4; i++) {
        float inv = 1.0f / lrow[i];
        int row = q0 + ty * 4 + i;
        float4 o;
        o.x = acc[i][0] * inv; o.y = acc[i][1] * inv;
        o.z = acc[i][2] * inv; o.w = acc[i][3] * inv;
        *(float4*)&ctx[base + (size_t)row * DIM + tx * 4] = o;
    }
}

// ---------------- residual + LayerNorm ----------------
__global__ void ln_residual_kernel(const float* __restrict__ a,
                                   const float* __restrict__ r,
                                   const float* __restrict__ gamma,
                                   const float* __restrict__ beta,
                                   float* __restrict__ out) {
    const int row = blockIdx.x;
    const int tid = threadIdx.x;
    const float* pa = a + (size_t)row * DIM;
    const float* pr = r + (size_t)row * DIM;

    float v[4];
    float sum = 0.0f, sq = 0.0f;
    #pragma unroll
    for (int i = 0; i < 4; i++) {
        int c = tid + i * 256;
        float t = pa[c] + pr[c];
        v[i] = t;
        sum += t;
        sq  += t * t;
    }
    #pragma unroll
    for (int off = 16; off >= 1; off >>= 1) {
        sum += __shfl_xor_sync(0xffffffffu, sum, off);
        sq  += __shfl_xor_sync(0xffffffffu, sq,  off);
    }
    __shared__ float ssum[8], ssq[8];
    int warp = tid >> 5, lane = tid & 31;
    if (lane == 0) { ssum[warp] = sum; ssq[warp] = sq; }
    __syncthreads();
    sum = 0.0f; sq = 0.0f;
    #pragma unroll
    for (int i = 0; i < 8; i++) { sum += ssum[i]; sq += ssq[i]; }

    const float invN = 1.0f / (float)DIM;
    float mu  = sum * invN;
    float var = fmaxf(sq * invN - mu * mu, 0.0f);
    float rstd = rsqrtf(var + 1e-12f);

    #pragma unroll
    for (int i = 0; i < 4; i++) {
        int c = tid + i * 256;
        out[(size_t)row * DIM + c] = (v[i] - mu) * rstd * gamma[c] + beta[c];
    }
}

// ---------------- launch ----------------
extern "C" void kernel_launch(void* const* d_in, const int* in_sizes, int n_in,
                              void* d_out, int out_size) {
    const float* x    = (const float*)d_in[0];
    const int*   mask = (const int*)  d_in[1];
    const float* Wq   = (const float*)d_in[2];
    const float* bq   = (const float*)d_in[3];
    const float* Wk   = (const float*)d_in[4];
    const float* bk   = (const float*)d_in[5];
    const float* Wv   = (const float*)d_in[6];
    const float* bv   = (const float*)d_in[7];
    const float* Wo   = (const float*)d_in[8];
    const float* bo   = (const float*)d_in[9];
    const float* ln1g = (const float*)d_in[10];
    const float* ln1b = (const float*)d_in[11];
    const float* W1   = (const float*)d_in[12];
    const float* b1   = (const float*)d_in[13];
    const float* W2   = (const float*)d_in[14];
    const float* b2   = (const float*)d_in[15];
    const float* ln2g = (const float*)d_in[16];
    const float* ln2b = (const float*)d_in[17];
    float* out = (float*)d_out;

    float *q, *k, *v, *ctx, *h1, *ffn;
    cudaGetSymbolAddress((void**)&q,   g_q);
    cudaGetSymbolAddress((void**)&k,   g_k);
    cudaGetSymbolAddress((void**)&v,   g_v);
    cudaGetSymbolAddress((void**)&ctx, g_ctx);
    cudaGetSymbolAddress((void**)&h1,  g_h1);
    cudaGetSymbolAddress((void**)&ffn, g_ffn);

    const dim3 gD(DIM / 128, MROWS / 128);   // (8, 32)
    const dim3 gH(HID / 128, MROWS / 128);   // (32, 32)

    // QKV projections (tf32 mma.sync tensor cores)
    gemm_mma<0><<<gD, 256>>>(x, Wq, bq, q, MROWS, DIM, DIM);
    gemm_mma<0><<<gD, 256>>>(x, Wk, bk, k, MROWS, DIM, DIM);
    gemm_mma<0><<<gD, 256>>>(x, Wv, bv, v, MROWS, DIM, DIM);

    // attention (fp32)
    int smem = (4 * 64 * 68 + 64) * (int)sizeof(float);
    cudaFuncSetAttribute(attn_kernel, cudaFuncAttributeMaxDynamicSharedMemorySize, smem);
    attn_kernel<<<dim3(SEQ / 64, NH, BS), 256, smem>>>(q, k, v, mask, ctx);

    // output projection (reuse q as sa_out)
    gemm_mma<0><<<gD, 256>>>(ctx, Wo, bo, q, MROWS, DIM, DIM);

    // LN1(sa_out + x) -> h1
    ln_residual_kernel<<<MROWS, 256>>>(q, x, ln1g, ln1b, h1);

    // FFN
    gemm_mma<1><<<gH, 256>>>(h1, W1, b1, ffn, MROWS, DIM, HID);
    gemm_mma<0><<<gD, 256>>>(ffn, W2, b2, k, MROWS, HID, DIM);

    // LN2(ffn_out + h1) -> out
    ln_residual_kernel<<<MROWS, 256>>>(k, h1, ln2g, ln2b, out);
}

// round 5
// speedup vs baseline: 2.5809x; 1.3788x over previous
#include <cuda_runtime.h>
#include <math.h>
#include <stdint.h>

#define BS   2
#define SEQ  2048
#define DIM  1024
#define HID  4096
#define NH   16
#define DPH  64
#define MROWS (BS*SEQ)   // 4096

// ---------------- scratch (no allocation allowed) ----------------
__device__ float g_q  [MROWS*DIM];
__device__ float g_k  [MROWS*DIM];
__device__ float g_v  [MROWS*DIM];
__device__ float g_ctx[MROWS*DIM];
__device__ float g_h1 [MROWS*DIM];
__device__ float g_ffn[MROWS*HID];

__device__ __forceinline__ uint32_t f2tf32(float f) {
    uint32_t r;
    asm("cvt.rna.tf32.f32 %0, %1;" : "=r"(r) : "f"(f));
    return r;
}

__device__ __forceinline__ void mma_tf32(float* d,
                                         uint32_t a0, uint32_t a1, uint32_t a2, uint32_t a3,
                                         uint32_t b0, uint32_t b1) {
    asm volatile(
        "mma.sync.aligned.m16n8k8.row.col.f32.tf32.tf32.f32 "
        "{%0,%1,%2,%3}, {%4,%5,%6,%7}, {%8,%9}, {%0,%1,%2,%3};"
        : "+f"(d[0]), "+f"(d[1]), "+f"(d[2]), "+f"(d[3])
        : "r"(a0), "r"(a1), "r"(a2), "r"(a3), "r"(b0), "r"(b1));
}

__device__ __forceinline__ float gelu_f(float x) {
    return 0.5f * x * (1.0f + erff(x * 0.70710678118654752f));
}

// ---------------- tf32 mma.sync GEMM (unchanged from R4) ----------------
#define AS_STRIDE 36
#define BS_STRIDE 136

template<int ACT>
__global__ void __launch_bounds__(256)
gemm_mma(const float* __restrict__ A, const float* __restrict__ W,
         const float* __restrict__ bias, float* __restrict__ C,
         int M, int K, int N) {
    __shared__ uint32_t As[128 * AS_STRIDE];
    __shared__ uint32_t Bsm[32 * BS_STRIDE];

    const int tid  = threadIdx.x;
    const int wid  = tid >> 5;
    const int lane = tid & 31;
    const int grp  = lane >> 2;
    const int t4   = lane & 3;
    const int m0 = blockIdx.y * 128, n0 = blockIdx.x * 128;
    const int wm = (wid & 3) * 32;
    const int wn = (wid >> 2) * 64;

    float acc[2][8][4];
    #pragma unroll
    for (int i = 0; i < 2; i++)
        #pragma unroll
        for (int j = 0; j < 8; j++)
            #pragma unroll
            for (int c = 0; c < 4; c++) acc[i][j][c] = 0.0f;

    const int nit = K / 32;
    for (int it = 0; it < nit; it++) {
        const float* Ab = A + (size_t)m0 * K + (size_t)it * 32;
        #pragma unroll
        for (int i = 0; i < 4; i++) {
            int idx = tid + i * 256;
            int row = idx >> 3, c4 = idx & 7;
            float4 v = *(const float4*)(Ab + (size_t)row * K + c4 * 4);
            uint4 u;
            u.x = f2tf32(v.x); u.y = f2tf32(v.y); u.z = f2tf32(v.z); u.w = f2tf32(v.w);
            *(uint4*)&As[row * AS_STRIDE + c4 * 4] = u;
        }
        const float* Wb = W + (size_t)(it * 32) * N + n0;
        #pragma unroll
        for (int i = 0; i < 4; i++) {
            int idx = tid + i * 256;
            int k = idx >> 5, nq = idx & 31;
            float4 v = *(const float4*)(Wb + (size_t)k * N + nq * 4);
            uint4 u;
            u.x = f2tf32(v.x); u.y = f2tf32(v.y); u.z = f2tf32(v.z); u.w = f2tf32(v.w);
            *(uint4*)&Bsm[k * BS_STRIDE + nq * 4] = u;
        }
        __syncthreads();

        #pragma unroll
        for (int kk = 0; kk < 4; kk++) {
            const int kb = kk * 8;
            uint32_t afr[2][4];
            #pragma unroll
            for (int mt = 0; mt < 2; mt++) {
                const int rb = wm + mt * 16;
                afr[mt][0] = As[(rb + grp)     * AS_STRIDE + kb + t4];
                afr[mt][1] = As[(rb + grp + 8) * AS_STRIDE + kb + t4];
                afr[mt][2] = As[(rb + grp)     * AS_STRIDE + kb + t4 + 4];
                afr[mt][3] = As[(rb + grp + 8) * AS_STRIDE + kb + t4 + 4];
            }
            uint32_t bfr[8][2];
            #pragma unroll
            for (int nt = 0; nt < 8; nt++) {
                const int col = wn + nt * 8 + grp;
                bfr[nt][0] = Bsm[(kb + t4)     * BS_STRIDE + col];
                bfr[nt][1] = Bsm[(kb + t4 + 4) * BS_STRIDE + col];
            }
            #pragma unroll
            for (int mt = 0; mt < 2; mt++)
                #pragma unroll
                for (int nt = 0; nt < 8; nt++)
                    mma_tf32(acc[mt][nt], afr[mt][0], afr[mt][1], afr[mt][2], afr[mt][3],
                             bfr[nt][0], bfr[nt][1]);
        }
        __syncthreads();
    }

    #pragma unroll
    for (int mt = 0; mt < 2; mt++) {
        #pragma unroll
        for (int nt = 0; nt < 8; nt++) {
            const int col = n0 + wn + nt * 8 + t4 * 2;
            const float b0v = bias[col], b1v = bias[col + 1];
            const int r0 = m0 + wm + mt * 16 + grp;
            float v0 = acc[mt][nt][0] + b0v;
            float v1 = acc[mt][nt][1] + b1v;
            float v2 = acc[mt][nt][2] + b0v;
            float v3 = acc[mt][nt][3] + b1v;
            if (ACT == 1) { v0 = gelu_f(v0); v1 = gelu_f(v1); v2 = gelu_f(v2); v3 = gelu_f(v3); }
            *(float2*)&C[(size_t)r0 * N + col]       = make_float2(v0, v1);
            *(float2*)&C[(size_t)(r0 + 8) * N + col] = make_float2(v2, v3);
        }
    }
}

// ---------------- Flash attention on tensor cores (tf32 mma.sync) ----------------
// 128 queries/block, KV tile 64, 8 warps x 16 q-rows, 256 threads.
// smem (floats): Ksm[64][68], Vsm[64][68], Psm[128][72] (also Q staging), smask[64]
#define KS_STRIDE 68
#define PS_STRIDE 72
#define ATTN_SMEM_FLOATS (2*64*KS_STRIDE + 128*PS_STRIDE + 64)
#define ATTN_SMEM_BYTES (ATTN_SMEM_FLOATS * 4)

__global__ void __launch_bounds__(256)
attn_mma(const float* __restrict__ Q, const float* __restrict__ K,
         const float* __restrict__ V, const int* __restrict__ mask,
         float* __restrict__ ctx) {
    extern __shared__ float sm[];
    uint32_t* Ks   = (uint32_t*)sm;                       // [64][68] tf32 K[kv][d]
    uint32_t* Vs   = Ks + 64 * KS_STRIDE;                 // [64][68] tf32 V[kv][d]
    uint32_t* Ps   = Vs + 64 * KS_STRIDE;                 // [128][72] tf32 (Q staging, then P)
    float*    smask = (float*)(Ps + 128 * PS_STRIDE);     // [64]

    const int tid  = threadIdx.x;
    const int wid  = tid >> 5;
    const int lane = tid & 31;
    const int grp  = lane >> 2;
    const int t4   = lane & 3;
    const int w16  = wid * 16;
    const int q0 = blockIdx.x * 128;
    const int h  = blockIdx.y;
    const int b  = blockIdx.z;
    const size_t base = (size_t)b * SEQ * DIM + h * DPH;

    // ---- stage Q tile (128x64) into Ps (scaled, tf32) ----
    #pragma unroll
    for (int i = 0; i < 8; i++) {
        int idx = tid + i * 256;
        int row = idx >> 4, c4 = idx & 15;
        float4 v = *(const float4*)(Q + base + (size_t)(q0 + row) * DIM + c4 * 4);
        uint4 u;
        u.x = f2tf32(v.x * 0.125f); u.y = f2tf32(v.y * 0.125f);
        u.z = f2tf32(v.z * 0.125f); u.w = f2tf32(v.w * 0.125f);
        *(uint4*)&Ps[row * PS_STRIDE + c4 * 4] = u;
    }
    __syncthreads();

    // ---- Q fragments to registers (8 k-steps) ----
    uint32_t qf[8][4];
    #pragma unroll
    for (int k = 0; k < 8; k++) {
        qf[k][0] = Ps[(w16 + grp)     * PS_STRIDE + k * 8 + t4];
        qf[k][1] = Ps[(w16 + grp + 8) * PS_STRIDE + k * 8 + t4];
        qf[k][2] = Ps[(w16 + grp)     * PS_STRIDE + k * 8 + t4 + 4];
        qf[k][3] = Ps[(w16 + grp + 8) * PS_STRIDE + k * 8 + t4 + 4];
    }
    __syncthreads();

    float o[8][4];
    #pragma unroll
    for (int nf = 0; nf < 8; nf++)
        #pragma unroll
        for (int c = 0; c < 4; c++) o[nf][c] = 0.0f;
    float mrow0 = -INFINITY, mrow1 = -INFINITY;
    float l0 = 0.0f, l1 = 0.0f;

    for (int kv0 = 0; kv0 < SEQ; kv0 += 64) {
        // ---- load K/V tiles (64x64 each), tf32 ----
        #pragma unroll
        for (int i = 0; i < 4; i++) {
            int idx = tid + i * 256;
            int row = idx >> 4, c4 = idx & 15;
            size_t g = base + (size_t)(kv0 + row) * DIM + c4 * 4;
            float4 kv4 = *(const float4*)(K + g);
            float4 vv4 = *(const float4*)(V + g);
            uint4 uk, uv;
            uk.x = f2tf32(kv4.x); uk.y = f2tf32(kv4.y); uk.z = f2tf32(kv4.z); uk.w = f2tf32(kv4.w);
            uv.x = f2tf32(vv4.x); uv.y = f2tf32(vv4.y); uv.z = f2tf32(vv4.z); uv.w = f2tf32(vv4.w);
            *(uint4*)&Ks[row * KS_STRIDE + c4 * 4] = uk;
            *(uint4*)&Vs[row * KS_STRIDE + c4 * 4] = uv;
        }
        if (tid < 64)
            smask[tid] = (mask[b * SEQ + kv0 + tid] == 0) ? -INFINITY : 0.0f;
        __syncthreads();

        // ---- S = Q K^T : s[nf][c], rows (grp, grp+8), cols nf*8 + t4*2 + {0,1} ----
        float s[8][4];
        #pragma unroll
        for (int nf = 0; nf < 8; nf++)
            #pragma unroll
            for (int c = 0; c < 4; c++) s[nf][c] = 0.0f;
        #pragma unroll
        for (int k = 0; k < 8; k++) {
            const int kb = k * 8;
            #pragma unroll
            for (int nf = 0; nf < 8; nf++) {
                uint32_t b0 = Ks[(nf * 8 + grp) * KS_STRIDE + kb + t4];
                uint32_t b1 = Ks[(nf * 8 + grp) * KS_STRIDE + kb + t4 + 4];
                mma_tf32(s[nf], qf[k][0], qf[k][1], qf[k][2], qf[k][3], b0, b1);
            }
        }

        // ---- mask ----
        #pragma unroll
        for (int nf = 0; nf < 8; nf++) {
            float mv0 = smask[nf * 8 + t4 * 2];
            float mv1 = smask[nf * 8 + t4 * 2 + 1];
            s[nf][0] += mv0; s[nf][1] += mv1;
            s[nf][2] += mv0; s[nf][3] += mv1;
        }

        // ---- online softmax (rows grp / grp+8, stats over t4 quad) ----
        float mt0 = -INFINITY, mt1 = -INFINITY;
        #pragma unroll
        for (int nf = 0; nf < 8; nf++) {
            mt0 = fmaxf(mt0, fmaxf(s[nf][0], s[nf][1]));
            mt1 = fmaxf(mt1, fmaxf(s[nf][2], s[nf][3]));
        }
        mt0 = fmaxf(mt0, __shfl_xor_sync(0xffffffffu, mt0, 1));
        mt0 = fmaxf(mt0, __shfl_xor_sync(0xffffffffu, mt0, 2));
        mt1 = fmaxf(mt1, __shfl_xor_sync(0xffffffffu, mt1, 1));
        mt1 = fmaxf(mt1, __shfl_xor_sync(0xffffffffu, mt1, 2));
        float mnew0 = fmaxf(mrow0, mt0);
        float mnew1 = fmaxf(mrow1, mt1);
        float alpha0 = __expf(mrow0 - mnew0);
        float alpha1 = __expf(mrow1 - mnew1);
        float lsum0 = 0.0f, lsum1 = 0.0f;
        #pragma unroll
        for (int nf = 0; nf < 8; nf++) {
            s[nf][0] = __expf(s[nf][0] - mnew0);
            s[nf][1] = __expf(s[nf][1] - mnew0);
            s[nf][2] = __expf(s[nf][2] - mnew1);
            s[nf][3] = __expf(s[nf][3] - mnew1);
            lsum0 += s[nf][0] + s[nf][1];
            lsum1 += s[nf][2] + s[nf][3];
        }
        lsum0 += __shfl_xor_sync(0xffffffffu, lsum0, 1);
        lsum0 += __shfl_xor_sync(0xffffffffu, lsum0, 2);
        lsum1 += __shfl_xor_sync(0xffffffffu, lsum1, 1);
        lsum1 += __shfl_xor_sync(0xffffffffu, lsum1, 2);
        l0 = l0 * alpha0 + lsum0;
        l1 = l1 * alpha1 + lsum1;
        mrow0 = mnew0; mrow1 = mnew1;
        #pragma unroll
        for (int nf = 0; nf < 8; nf++) {
            o[nf][0] *= alpha0; o[nf][1] *= alpha0;
            o[nf][2] *= alpha1; o[nf][3] *= alpha1;
        }

        // ---- write P (tf32) to smem ----
        #pragma unroll
        for (int nf = 0; nf < 8; nf++) {
            const int col = nf * 8 + t4 * 2;
            Ps[(w16 + grp)     * PS_STRIDE + col]     = f2tf32(s[nf][0]);
            Ps[(w16 + grp)     * PS_STRIDE + col + 1] = f2tf32(s[nf][1]);
            Ps[(w16 + grp + 8) * PS_STRIDE + col]     = f2tf32(s[nf][2]);
            Ps[(w16 + grp + 8) * PS_STRIDE + col + 1] = f2tf32(s[nf][3]);
        }
        __syncwarp();

        // ---- O += P @ V ----
        #pragma unroll
        for (int k = 0; k < 8; k++) {
            const int kb = k * 8;
            uint32_t a0 = Ps[(w16 + grp)     * PS_STRIDE + kb + t4];
            uint32_t a1 = Ps[(w16 + grp + 8) * PS_STRIDE + kb + t4];
            uint32_t a2 = Ps[(w16 + grp)     * PS_STRIDE + kb + t4 + 4];
            uint32_t a3 = Ps[(w16 + grp + 8) * PS_STRIDE + kb + t4 + 4];
            #pragma unroll
            for (int nf = 0; nf < 8; nf++) {
                uint32_t b0 = Vs[(kb + t4)     * KS_STRIDE + nf * 8 + grp];
                uint32_t b1 = Vs[(kb + t4 + 4) * KS_STRIDE + nf * 8 + grp];
                mma_tf32(o[nf], a0, a1, a2, a3, b0, b1);
            }
        }
        __syncthreads();
    }

    // ---- normalize + write ctx ----
    const float inv0 = 1.0f / l0;
    const float inv1 = 1.0f / l1;
    const int r0 = q0 + w16 + grp;
    #pragma unroll
    for (int nf = 0; nf < 8; nf++) {
        const int d0 = nf * 8 + t4 * 2;
        *(float2*)&ctx[base + (size_t)r0 * DIM + d0] =
            make_float2(o[nf][0] * inv0, o[nf][1] * inv0);
        *(float2*)&ctx[base + (size_t)(r0 + 8) * DIM + d0] =
            make_float2(o[nf][2] * inv1, o[nf][3] * inv1);
    }
}

// ---------------- residual + LayerNorm ----------------
__global__ void ln_residual_kernel(const float* __restrict__ a,
                                   const float* __restrict__ r,
                                   const float* __restrict__ gamma,
                                   const float* __restrict__ beta,
                                   float* __restrict__ out) {
    const int row = blockIdx.x;
    const int tid = threadIdx.x;
    const float* pa = a + (size_t)row * DIM;
    const float* pr = r + (size_t)row * DIM;

    float v[4];
    float sum = 0.0f, sq = 0.0f;
    #pragma unroll
    for (int i = 0; i < 4; i++) {
        int c = tid + i * 256;
        float t = pa[c] + pr[c];
        v[i] = t;
        sum += t;
        sq  += t * t;
    }
    #pragma unroll
    for (int off = 16; off >= 1; off >>= 1) {
        sum += __shfl_xor_sync(0xffffffffu, sum, off);
        sq  += __shfl_xor_sync(0xffffffffu, sq,  off);
    }
    __shared__ float ssum[8], ssq[8];
    int warp = tid >> 5, lane = tid & 31;
    if (lane == 0) { ssum[warp] = sum; ssq[warp] = sq; }
    __syncthreads();
    sum = 0.0f; sq = 0.0f;
    #pragma unroll
    for (int i = 0; i < 8; i++) { sum += ssum[i]; sq += ssq[i]; }

    const float invN = 1.0f / (float)DIM;
    float mu  = sum * invN;
    float var = fmaxf(sq * invN - mu * mu, 0.0f);
    float rstd = rsqrtf(var + 1e-12f);

    #pragma unroll
    for (int i = 0; i < 4; i++) {
        int c = tid + i * 256;
        out[(size_t)row * DIM + c] = (v[i] - mu) * rstd * gamma[c] + beta[c];
    }
}

// ---------------- launch ----------------
extern "C" void kernel_launch(void* const* d_in, const int* in_sizes, int n_in,
                              void* d_out, int out_size) {
    const float* x    = (const float*)d_in[0];
    const int*   mask = (const int*)  d_in[1];
    const float* Wq   = (const float*)d_in[2];
    const float* bq   = (const float*)d_in[3];
    const float* Wk   = (const float*)d_in[4];
    const float* bk   = (const float*)d_in[5];
    const float* Wv   = (const float*)d_in[6];
    const float* bv   = (const float*)d_in[7];
    const float* Wo   = (const float*)d_in[8];
    const float* bo   = (const float*)d_in[9];
    const float* ln1g = (const float*)d_in[10];
    const float* ln1b = (const float*)d_in[11];
    const float* W1   = (const float*)d_in[12];
    const float* b1   = (const float*)d_in[13];
    const float* W2   = (const float*)d_in[14];
    const float* b2   = (const float*)d_in[15];
    const float* ln2g = (const float*)d_in[16];
    const float* ln2b = (const float*)d_in[17];
    float* out = (float*)d_out;

    float *q, *k, *v, *ctx, *h1, *ffn;
    cudaGetSymbolAddress((void**)&q,   g_q);
    cudaGetSymbolAddress((void**)&k,   g_k);
    cudaGetSymbolAddress((void**)&v,   g_v);
    cudaGetSymbolAddress((void**)&ctx, g_ctx);
    cudaGetSymbolAddress((void**)&h1,  g_h1);
    cudaGetSymbolAddress((void**)&ffn, g_ffn);

    const dim3 gD(DIM / 128, MROWS / 128);   // (8, 32)
    const dim3 gH(HID / 128, MROWS / 128);   // (32, 32)

    // QKV projections (tf32 mma.sync)
    gemm_mma<0><<<gD, 256>>>(x, Wq, bq, q, MROWS, DIM, DIM);
    gemm_mma<0><<<gD, 256>>>(x, Wk, bk, k, MROWS, DIM, DIM);
    gemm_mma<0><<<gD, 256>>>(x, Wv, bv, v, MROWS, DIM, DIM);

    // attention (tf32 mma.sync flash)
    cudaFuncSetAttribute(attn_mma, cudaFuncAttributeMaxDynamicSharedMemorySize, ATTN_SMEM_BYTES);
    attn_mma<<<dim3(SEQ / 128, NH, BS), 256, ATTN_SMEM_BYTES>>>(q, k, v, mask, ctx);

    // output projection (reuse q as sa_out)
    gemm_mma<0><<<gD, 256>>>(ctx, Wo, bo, q, MROWS, DIM, DIM);

    // LN1(sa_out + x) -> h1
    ln_residual_kernel<<<MROWS, 256>>>(q, x, ln1g, ln1b, h1);

    // FFN
    gemm_mma<1><<<gH, 256>>>(h1, W1, b1, ffn, MROWS, DIM, HID);
    gemm_mma<0><<<gD, 256>>>(ffn, W2, b2, k, MROWS, HID, DIM);

    // LN2(ffn_out + h1) -> out
    ln_residual_kernel<<<MROWS, 256>>>(k, h1, ln2g, ln2b, out);
}

// round 6
// speedup vs baseline: 2.7845x; 1.0789x over previous
#include <cuda_runtime.h>
#include <math.h>
#include <stdint.h>

#define BS   2
#define SEQ  2048
#define DIM  1024
#define HID  4096
#define NH   16
#define DPH  64
#define MROWS (BS*SEQ)   // 4096

// ---------------- scratch (no allocation allowed) ----------------
__device__ float g_q  [MROWS*DIM];
__device__ float g_k  [MROWS*DIM];
__device__ float g_v  [MROWS*DIM];
__device__ float g_ctx[MROWS*DIM];
__device__ float g_h1 [MROWS*DIM];
__device__ float g_ffn[MROWS*HID];

__device__ __forceinline__ uint32_t f2tf32(float f) {
    uint32_t r;
    asm("cvt.rna.tf32.f32 %0, %1;" : "=r"(r) : "f"(f));
    return r;
}

__device__ __forceinline__ void mma_tf32(float* d,
                                         uint32_t a0, uint32_t a1, uint32_t a2, uint32_t a3,
                                         uint32_t b0, uint32_t b1) {
    asm volatile(
        "mma.sync.aligned.m16n8k8.row.col.f32.tf32.tf32.f32 "
        "{%0,%1,%2,%3}, {%4,%5,%6,%7}, {%8,%9}, {%0,%1,%2,%3};"
        : "+f"(d[0]), "+f"(d[1]), "+f"(d[2]), "+f"(d[3])
        : "r"(a0), "r"(a1), "r"(a2), "r"(a3), "r"(b0), "r"(b1));
}

__device__ __forceinline__ float gelu_f(float x) {
    return 0.5f * x * (1.0f + erff(x * 0.70710678118654752f));
}

// ---------------- tf32 mma.sync GEMM, double-buffered + reg prefetch ----------------
// CTA 128x128, BK=32, 256 threads, warp tile 32x64.
#define AS_STRIDE 36
#define BS_STRIDE 136
#define AS_BUF (128 * AS_STRIDE)           // 4608 uints per buffer
#define BS_BUF (32 * BS_STRIDE)            // 4352 uints per buffer
#define GEMM_SMEM_BYTES ((2 * AS_BUF + 2 * BS_BUF) * 4)   // 71680 B

template<int ACT>
__global__ void __launch_bounds__(256)
gemm_mma(const float* __restrict__ A, const float* __restrict__ W,
         const float* __restrict__ bias, float* __restrict__ C,
         int M, int K, int N) {
    extern __shared__ uint32_t dsm[];
    uint32_t* Asb[2] = { dsm, dsm + AS_BUF };
    uint32_t* Bsb[2] = { dsm + 2 * AS_BUF, dsm + 2 * AS_BUF + BS_BUF };

    const int tid  = threadIdx.x;
    const int wid  = tid >> 5;
    const int lane = tid & 31;
    const int grp  = lane >> 2;
    const int t4   = lane & 3;
    const int m0 = blockIdx.y * 128, n0 = blockIdx.x * 128;
    const int wm = (wid & 3) * 32;
    const int wn = (wid >> 2) * 64;

    // per-thread load coords (fixed across iterations)
    const int ar[4] = { (tid) >> 3, (tid + 256) >> 3, (tid + 512) >> 3, (tid + 768) >> 3 };
    const int ac = (tid & 7) * 4;
    const int bk4[4] = { (tid) >> 5, (tid + 256) >> 5, (tid + 512) >> 5, (tid + 768) >> 5 };
    const int bn = (tid & 31) * 4;

    float acc[2][8][4];
    #pragma unroll
    for (int i = 0; i < 2; i++)
        #pragma unroll
        for (int j = 0; j < 8; j++)
            #pragma unroll
            for (int c = 0; c < 4; c++) acc[i][j][c] = 0.0f;

    const int nit = K / 32;

    // ---- preload tile 0 ----
    {
        const float* Ab = A + (size_t)m0 * K;
        const float* Wb = W + n0;
        #pragma unroll
        for (int i = 0; i < 4; i++) {
            float4 v = *(const float4*)(Ab + (size_t)ar[i] * K + ac);
            uint4 u;
            u.x = f2tf32(v.x); u.y = f2tf32(v.y); u.z = f2tf32(v.z); u.w = f2tf32(v.w);
            *(uint4*)&Asb[0][ar[i] * AS_STRIDE + ac] = u;
        }
        #pragma unroll
        for (int i = 0; i < 4; i++) {
            float4 v = *(const float4*)(Wb + (size_t)bk4[i] * N + bn);
            uint4 u;
            u.x = f2tf32(v.x); u.y = f2tf32(v.y); u.z = f2tf32(v.z); u.w = f2tf32(v.w);
            *(uint4*)&Bsb[0][bk4[i] * BS_STRIDE + bn] = u;
        }
    }
    __syncthreads();

    for (int it = 0; it < nit; it++) {
        const int buf = it & 1;
        const uint32_t* As = Asb[buf];
        const uint32_t* Bsm = Bsb[buf];

        // ---- prefetch next tile into registers (hidden under compute) ----
        float4 pa[4], pb[4];
        if (it + 1 < nit) {
            const float* Ab = A + (size_t)m0 * K + (size_t)(it + 1) * 32;
            const float* Wb = W + (size_t)(it + 1) * 32 * N + n0;
            #pragma unroll
            for (int i = 0; i < 4; i++)
                pa[i] = *(const float4*)(Ab + (size_t)ar[i] * K + ac);
            #pragma unroll
            for (int i = 0; i < 4; i++)
                pb[i] = *(const float4*)(Wb + (size_t)bk4[i] * N + bn);
        }

        // ---- compute 4 k-steps of m16n8k8 ----
        #pragma unroll
        for (int kk = 0; kk < 4; kk++) {
            const int kb = kk * 8;
            uint32_t afr[2][4];
            #pragma unroll
            for (int mt = 0; mt < 2; mt++) {
                const int rb = wm + mt * 16;
                afr[mt][0] = As[(rb + grp)     * AS_STRIDE + kb + t4];
                afr[mt][1] = As[(rb + grp + 8) * AS_STRIDE + kb + t4];
                afr[mt][2] = As[(rb + grp)     * AS_STRIDE + kb + t4 + 4];
                afr[mt][3] = As[(rb + grp + 8) * AS_STRIDE + kb + t4 + 4];
            }
            uint32_t bfr[8][2];
            #pragma unroll
            for (int nt = 0; nt < 8; nt++) {
                const int col = wn + nt * 8 + grp;
                bfr[nt][0] = Bsm[(kb + t4)     * BS_STRIDE + col];
                bfr[nt][1] = Bsm[(kb + t4 + 4) * BS_STRIDE + col];
            }
            #pragma unroll
            for (int mt = 0; mt < 2; mt++)
                #pragma unroll
                for (int nt = 0; nt < 8; nt++)
                    mma_tf32(acc[mt][nt], afr[mt][0], afr[mt][1], afr[mt][2], afr[mt][3],
                             bfr[nt][0], bfr[nt][1]);
        }

        // ---- store prefetched tile into the other buffer ----
        if (it + 1 < nit) {
            uint32_t* Asn = Asb[buf ^ 1];
            uint32_t* Bsn = Bsb[buf ^ 1];
            #pragma unroll
            for (int i = 0; i < 4; i++) {
                uint4 u;
                u.x = f2tf32(pa[i].x); u.y = f2tf32(pa[i].y);
                u.z = f2tf32(pa[i].z); u.w = f2tf32(pa[i].w);
                *(uint4*)&Asn[ar[i] * AS_STRIDE + ac] = u;
            }
            #pragma unroll
            for (int i = 0; i < 4; i++) {
                uint4 u;
                u.x = f2tf32(pb[i].x); u.y = f2tf32(pb[i].y);
                u.z = f2tf32(pb[i].z); u.w = f2tf32(pb[i].w);
                *(uint4*)&Bsn[bk4[i] * BS_STRIDE + bn] = u;
            }
        }
        __syncthreads();
    }

    // ---- epilogue ----
    #pragma unroll
    for (int mt = 0; mt < 2; mt++) {
        #pragma unroll
        for (int nt = 0; nt < 8; nt++) {
            const int col = n0 + wn + nt * 8 + t4 * 2;
            const float b0v = bias[col], b1v = bias[col + 1];
            const int r0 = m0 + wm + mt * 16 + grp;
            float v0 = acc[mt][nt][0] + b0v;
            float v1 = acc[mt][nt][1] + b1v;
            float v2 = acc[mt][nt][2] + b0v;
            float v3 = acc[mt][nt][3] + b1v;
            if (ACT == 1) { v0 = gelu_f(v0); v1 = gelu_f(v1); v2 = gelu_f(v2); v3 = gelu_f(v3); }
            *(float2*)&C[(size_t)r0 * N + col]       = make_float2(v0, v1);
            *(float2*)&C[(size_t)(r0 + 8) * N + col] = make_float2(v2, v3);
        }
    }
}

// ---------------- Flash attention on tensor cores (unchanged from R5) ----------------
#define KS_STRIDE 68
#define PS_STRIDE 72
#define ATTN_SMEM_FLOATS (2*64*KS_STRIDE + 128*PS_STRIDE + 64)
#define ATTN_SMEM_BYTES (ATTN_SMEM_FLOATS * 4)

__global__ void __launch_bounds__(256)
attn_mma(const float* __restrict__ Q, const float* __restrict__ K,
         const float* __restrict__ V, const int* __restrict__ mask,
         float* __restrict__ ctx) {
    extern __shared__ float sm[];
    uint32_t* Ks   = (uint32_t*)sm;
    uint32_t* Vs   = Ks + 64 * KS_STRIDE;
    uint32_t* Ps   = Vs + 64 * KS_STRIDE;
    float*    smask = (float*)(Ps + 128 * PS_STRIDE);

    const int tid  = threadIdx.x;
    const int wid  = tid >> 5;
    const int lane = tid & 31;
    const int grp  = lane >> 2;
    const int t4   = lane & 3;
    const int w16  = wid * 16;
    const int q0 = blockIdx.x * 128;
    const int h  = blockIdx.y;
    const int b  = blockIdx.z;
    const size_t base = (size_t)b * SEQ * DIM + h * DPH;

    #pragma unroll
    for (int i = 0; i < 8; i++) {
        int idx = tid + i * 256;
        int row = idx >> 4, c4 = idx & 15;
        float4 v = *(const float4*)(Q + base + (size_t)(q0 + row) * DIM + c4 * 4);
        uint4 u;
        u.x = f2tf32(v.x * 0.125f); u.y = f2tf32(v.y * 0.125f);
        u.z = f2tf32(v.z * 0.125f); u.w = f2tf32(v.w * 0.125f);
        *(uint4*)&Ps[row * PS_STRIDE + c4 * 4] = u;
    }
    __syncthreads();

    uint32_t qf[8][4];
    #pragma unroll
    for (int k = 0; k < 8; k++) {
        qf[k][0] = Ps[(w16 + grp)     * PS_STRIDE + k * 8 + t4];
        qf[k][1] = Ps[(w16 + grp + 8) * PS_STRIDE + k * 8 + t4];
        qf[k][2] = Ps[(w16 + grp)     * PS_STRIDE + k * 8 + t4 + 4];
        qf[k][3] = Ps[(w16 + grp + 8) * PS_STRIDE + k * 8 + t4 + 4];
    }
    __syncthreads();

    float o[8][4];
    #pragma unroll
    for (int nf = 0; nf < 8; nf++)
        #pragma unroll
        for (int c = 0; c < 4; c++) o[nf][c] = 0.0f;
    float mrow0 = -INFINITY, mrow1 = -INFINITY;
    float l0 = 0.0f, l1 = 0.0f;

    for (int kv0 = 0; kv0 < SEQ; kv0 += 64) {
        #pragma unroll
        for (int i = 0; i < 4; i++) {
            int idx = tid + i * 256;
            int row = idx >> 4, c4 = idx & 15;
            size_t g = base + (size_t)(kv0 + row) * DIM + c4 * 4;
            float4 kv4 = *(const float4*)(K + g);
            float4 vv4 = *(const float4*)(V + g);
            uint4 uk, uv;
            uk.x = f2tf32(kv4.x); uk.y = f2tf32(kv4.y); uk.z = f2tf32(kv4.z); uk.w = f2tf32(kv4.w);
            uv.x = f2tf32(vv4.x); uv.y = f2tf32(vv4.y); uv.z = f2tf32(vv4.z); uv.w = f2tf32(vv4.w);
            *(uint4*)&Ks[row * KS_STRIDE + c4 * 4] = uk;
            *(uint4*)&Vs[row * KS_STRIDE + c4 * 4] = uv;
        }
        if (tid < 64)
            smask[tid] = (mask[b * SEQ + kv0 + tid] == 0) ? -INFINITY : 0.0f;
        __syncthreads();

        float s[8][4];
        #pragma unroll
        for (int nf = 0; nf < 8; nf++)
            #pragma unroll
            for (int c = 0; c < 4; c++) s[nf][c] = 0.0f;
        #pragma unroll
        for (int k = 0; k < 8; k++) {
            const int kb = k * 8;
            #pragma unroll
            for (int nf = 0; nf < 8; nf++) {
                uint32_t b0 = Ks[(nf * 8 + grp) * KS_STRIDE + kb + t4];
                uint32_t b1 = Ks[(nf * 8 + grp) * KS_STRIDE + kb + t4 + 4];
                mma_tf32(s[nf], qf[k][0], qf[k][1], qf[k][2], qf[k][3], b0, b1);
            }
        }

        #pragma unroll
        for (int nf = 0; nf < 8; nf++) {
            float mv0 = smask[nf * 8 + t4 * 2];
            float mv1 = smask[nf * 8 + t4 * 2 + 1];
            s[nf][0] += mv0; s[nf][1] += mv1;
            s[nf][2] += mv0; s[nf][3] += mv1;
        }

        float mt0 = -INFINITY, mt1 = -INFINITY;
        #pragma unroll
        for (int nf = 0; nf < 8; nf++) {
            mt0 = fmaxf(mt0, fmaxf(s[nf][0], s[nf][1]));
            mt1 = fmaxf(mt1, fmaxf(s[nf][2], s[nf][3]));
        }
        mt0 = fmaxf(mt0, __shfl_xor_sync(0xffffffffu, mt0, 1));
        mt0 = fmaxf(mt0, __shfl_xor_sync(0xffffffffu, mt0, 2));
        mt1 = fmaxf(mt1, __shfl_xor_sync(0xffffffffu, mt1, 1));
        mt1 = fmaxf(mt1, __shfl_xor_sync(0xffffffffu, mt1, 2));
        float mnew0 = fmaxf(mrow0, mt0);
        float mnew1 = fmaxf(mrow1, mt1);
        float alpha0 = __expf(mrow0 - mnew0);
        float alpha1 = __expf(mrow1 - mnew1);
        float lsum0 = 0.0f, lsum1 = 0.0f;
        #pragma unroll
        for (int nf = 0; nf < 8; nf++) {
            s[nf][0] = __expf(s[nf][0] - mnew0);
            s[nf][1] = __expf(s[nf][1] - mnew0);
            s[nf][2] = __expf(s[nf][2] - mnew1);
            s[nf][3] = __expf(s[nf][3] - mnew1);
            lsum0 += s[nf][0] + s[nf][1];
            lsum1 += s[nf][2] + s[nf][3];
        }
        lsum0 += __shfl_xor_sync(0xffffffffu, lsum0, 1);
        lsum0 += __shfl_xor_sync(0xffffffffu, lsum0, 2);
        lsum1 += __shfl_xor_sync(0xffffffffu, lsum1, 1);
        lsum1 += __shfl_xor_sync(0xffffffffu, lsum1, 2);
        l0 = l0 * alpha0 + lsum0;
        l1 = l1 * alpha1 + lsum1;
        mrow0 = mnew0; mrow1 = mnew1;
        #pragma unroll
        for (int nf = 0; nf < 8; nf++) {
            o[nf][0] *= alpha0; o[nf][1] *= alpha0;
            o[nf][2] *= alpha1; o[nf][3] *= alpha1;
        }

        #pragma unroll
        for (int nf = 0; nf < 8; nf++) {
            const int col = nf * 8 + t4 * 2;
            Ps[(w16 + grp)     * PS_STRIDE + col]     = f2tf32(s[nf][0]);
            Ps[(w16 + grp)     * PS_STRIDE + col + 1] = f2tf32(s[nf][1]);
            Ps[(w16 + grp + 8) * PS_STRIDE + col]     = f2tf32(s[nf][2]);
            Ps[(w16 + grp + 8) * PS_STRIDE + col + 1] = f2tf32(s[nf][3]);
        }
        __syncwarp();

        #pragma unroll
        for (int k = 0; k < 8; k++) {
            const int kb = k * 8;
            uint32_t a0 = Ps[(w16 + grp)     * PS_STRIDE + kb + t4];
            uint32_t a1 = Ps[(w16 + grp + 8) * PS_STRIDE + kb + t4];
            uint32_t a2 = Ps[(w16 + grp)     * PS_STRIDE + kb + t4 + 4];
            uint32_t a3 = Ps[(w16 + grp + 8) * PS_STRIDE + kb + t4 + 4];
            #pragma unroll
            for (int nf = 0; nf < 8; nf++) {
                uint32_t b0 = Vs[(kb + t4)     * KS_STRIDE + nf * 8 + grp];
                uint32_t b1 = Vs[(kb + t4 + 4) * KS_STRIDE + nf * 8 + grp];
                mma_tf32(o[nf], a0, a1, a2, a3, b0, b1);
            }
        }
        __syncthreads();
    }

    const float inv0 = 1.0f / l0;
    const float inv1 = 1.0f / l1;
    const int r0 = q0 + w16 + grp;
    #pragma unroll
    for (int nf = 0; nf < 8; nf++) {
        const int d0 = nf * 8 + t4 * 2;
        *(float2*)&ctx[base + (size_t)r0 * DIM + d0] =
            make_float2(o[nf][0] * inv0, o[nf][1] * inv0);
        *(float2*)&ctx[base + (size_t)(r0 + 8) * DIM + d0] =
            make_float2(o[nf][2] * inv1, o[nf][3] * inv1);
    }
}

// ---------------- residual + LayerNorm ----------------
__global__ void ln_residual_kernel(const float* __restrict__ a,
                                   const float* __restrict__ r,
                                   const float* __restrict__ gamma,
                                   const float* __restrict__ beta,
                                   float* __restrict__ out) {
    const int row = blockIdx.x;
    const int tid = threadIdx.x;
    const float* pa = a + (size_t)row * DIM;
    const float* pr = r + (size_t)row * DIM;

    float v[4];
    float sum = 0.0f, sq = 0.0f;
    #pragma unroll
    for (int i = 0; i < 4; i++) {
        int c = tid + i * 256;
        float t = pa[c] + pr[c];
        v[i] = t;
        sum += t;
        sq  += t * t;
    }
    #pragma unroll
    for (int off = 16; off >= 1; off >>= 1) {
        sum += __shfl_xor_sync(0xffffffffu, sum, off);
        sq  += __shfl_xor_sync(0xffffffffu, sq,  off);
    }
    __shared__ float ssum[8], ssq[8];
    int warp = tid >> 5, lane = tid & 31;
    if (lane == 0) { ssum[warp] = sum; ssq[warp] = sq; }
    __syncthreads();
    sum = 0.0f; sq = 0.0f;
    #pragma unroll
    for (int i = 0; i < 8; i++) { sum += ssum[i]; sq += ssq[i]; }

    const float invN = 1.0f / (float)DIM;
    float mu  = sum * invN;
    float var = fmaxf(sq * invN - mu * mu, 0.0f);
    float rstd = rsqrtf(var + 1e-12f);

    #pragma unroll
    for (int i = 0; i < 4; i++) {
        int c = tid + i * 256;
        out[(size_t)row * DIM + c] = (v[i] - mu) * rstd * gamma[c] + beta[c];
    }
}

// ---------------- launch ----------------
extern "C" void kernel_launch(void* const* d_in, const int* in_sizes, int n_in,
                              void* d_out, int out_size) {
    const float* x    = (const float*)d_in[0];
    const int*   mask = (const int*)  d_in[1];
    const float* Wq   = (const float*)d_in[2];
    const float* bq   = (const float*)d_in[3];
    const float* Wk   = (const float*)d_in[4];
    const float* bk   = (const float*)d_in[5];
    const float* Wv   = (const float*)d_in[6];
    const float* bv   = (const float*)d_in[7];
    const float* Wo   = (const float*)d_in[8];
    const float* bo   = (const float*)d_in[9];
    const float* ln1g = (const float*)d_in[10];
    const float* ln1b = (const float*)d_in[11];
    const float* W1   = (const float*)d_in[12];
    const float* b1   = (const float*)d_in[13];
    const float* W2   = (const float*)d_in[14];
    const float* b2   = (const float*)d_in[15];
    const float* ln2g = (const float*)d_in[16];
    const float* ln2b = (const float*)d_in[17];
    float* out = (float*)d_out;

    float *q, *k, *v, *ctx, *h1, *ffn;
    cudaGetSymbolAddress((void**)&q,   g_q);
    cudaGetSymbolAddress((void**)&k,   g_k);
    cudaGetSymbolAddress((void**)&v,   g_v);
    cudaGetSymbolAddress((void**)&ctx, g_ctx);
    cudaGetSymbolAddress((void**)&h1,  g_h1);
    cudaGetSymbolAddress((void**)&ffn, g_ffn);

    cudaFuncSetAttribute(gemm_mma<0>, cudaFuncAttributeMaxDynamicSharedMemorySize, GEMM_SMEM_BYTES);
    cudaFuncSetAttribute(gemm_mma<1>, cudaFuncAttributeMaxDynamicSharedMemorySize, GEMM_SMEM_BYTES);
    cudaFuncSetAttribute(attn_mma, cudaFuncAttributeMaxDynamicSharedMemorySize, ATTN_SMEM_BYTES);

    const dim3 gD(DIM / 128, MROWS / 128);   // (8, 32)
    const dim3 gH(HID / 128, MROWS / 128);   // (32, 32)

    // QKV projections (tf32 mma.sync, pipelined)
    gemm_mma<0><<<gD, 256, GEMM_SMEM_BYTES>>>(x, Wq, bq, q, MROWS, DIM, DIM);
    gemm_mma<0><<<gD, 256, GEMM_SMEM_BYTES>>>(x, Wk, bk, k, MROWS, DIM, DIM);
    gemm_mma<0><<<gD, 256, GEMM_SMEM_BYTES>>>(x, Wv, bv, v, MROWS, DIM, DIM);

    // attention (tf32 mma.sync flash)
    attn_mma<<<dim3(SEQ / 128, NH, BS), 256, ATTN_SMEM_BYTES>>>(q, k, v, mask, ctx);

    // output projection (reuse q as sa_out)
    gemm_mma<0><<<gD, 256, GEMM_SMEM_BYTES>>>(ctx, Wo, bo, q, MROWS, DIM, DIM);

    // LN1(sa_out + x) -> h1
    ln_residual_kernel<<<MROWS, 256>>>(q, x, ln1g, ln1b, h1);

    // FFN
    gemm_mma<1><<<gH, 256, GEMM_SMEM_BYTES>>>(h1, W1, b1, ffn, MROWS, DIM, HID);
    gemm_mma<0><<<gD, 256, GEMM_SMEM_BYTES>>>(ffn, W2, b2, k, MROWS, HID, DIM);

    // LN2(ffn_out + h1) -> out
    ln_residual_kernel<<<MROWS, 256>>>(k, h1, ln2g, ln2b, out);
}

// round 7
// speedup vs baseline: 3.3431x; 1.2006x over previous
#include <cuda_runtime.h>
#include <math.h>
#include <stdint.h>

#define BS   2
#define SEQ  2048
#define DIM  1024
#define HID  4096
#define NH   16
#define DPH  64
#define MROWS (BS*SEQ)   // 4096

// ---------------- scratch (no allocation allowed) ----------------
__device__ float g_q  [MROWS*DIM];
__device__ float g_k  [MROWS*DIM];
__device__ float g_v  [MROWS*DIM];
__device__ float g_ctx[MROWS*DIM];
__device__ float g_h1 [MROWS*DIM];
__device__ float g_h1t[MROWS*DIM];
__device__ float g_ffn[MROWS*HID];
__device__ float g_xt [MROWS*DIM];
__device__ float g_wqt[DIM*DIM];
__device__ float g_wkt[DIM*DIM];
__device__ float g_wvt[DIM*DIM];
__device__ float g_wot[DIM*DIM];
__device__ float g_w1t[DIM*HID];
__device__ float g_w2t[HID*DIM];

__device__ __forceinline__ uint32_t f2tf32(float f) {
    uint32_t r;
    asm("cvt.rna.tf32.f32 %0, %1;" : "=r"(r) : "f"(f));
    return r;
}
__device__ __forceinline__ uint32_t smem_u32(const void* p) {
    uint32_t a;
    asm("{ .reg .u64 t; cvta.to.shared.u64 t, %1; cvt.u32.u64 %0, t; }" : "=r"(a) : "l"(p));
    return a;
}
__device__ __forceinline__ void cp_async16(uint32_t dst, const void* src) {
    asm volatile("cp.async.cg.shared.global [%0], [%1], 16;" :: "r"(dst), "l"(src));
}
#define CP_COMMIT() asm volatile("cp.async.commit_group;" ::: "memory")
#define CP_WAIT(n)  asm volatile("cp.async.wait_group %0;" :: "n"(n) : "memory")

__device__ __forceinline__ void mma_tf32(float* d,
                                         uint32_t a0, uint32_t a1, uint32_t a2, uint32_t a3,
                                         uint32_t b0, uint32_t b1) {
    asm volatile(
        "mma.sync.aligned.m16n8k8.row.col.f32.tf32.tf32.f32 "
        "{%0,%1,%2,%3}, {%4,%5,%6,%7}, {%8,%9}, {%0,%1,%2,%3};"
        : "+f"(d[0]), "+f"(d[1]), "+f"(d[2]), "+f"(d[3])
        : "r"(a0), "r"(a1), "r"(a2), "r"(a3), "r"(b0), "r"(b1));
}

__device__ __forceinline__ float gelu_f(float x) {
    return 0.5f * x * (1.0f + erff(x * 0.70710678118654752f));
}

// ---------------- elementwise tf32 rounding pass ----------------
__global__ void cvt_tf32_kernel(const float* __restrict__ in, float* __restrict__ out, int n4) {
    int i = blockIdx.x * blockDim.x + threadIdx.x;
    if (i < n4) {
        float4 v = ((const float4*)in)[i];
        uint4 u;
        u.x = f2tf32(v.x); u.y = f2tf32(v.y); u.z = f2tf32(v.z); u.w = f2tf32(v.w);
        ((uint4*)out)[i] = u;
    }
}

// ---------------- tf32 GEMM body: cp.async double-buffered, no cvt ----------------
// Inputs A (tf32-rounded), W (tf32-rounded). CTA 128x128, BK=32, 256 threads.
#define AS_STRIDE 36
#define BS_STRIDE 136
#define AS_BUF (128 * AS_STRIDE)
#define BS_BUF (32 * BS_STRIDE)
#define GEMM_SMEM_BYTES ((2 * AS_BUF + 2 * BS_BUF) * 4)   // 71680 B

template<int ACT, int TFOUT>
__device__ __forceinline__ void gemm_body(const float* __restrict__ A,
                                          const float* __restrict__ W,
                                          const float* __restrict__ bias,
                                          float* __restrict__ C,
                                          int K, int N, int m0, int n0) {
    extern __shared__ uint32_t dsm[];
    const uint32_t sb = smem_u32(dsm);
    const uint32_t aoff[2] = { 0u, (uint32_t)AS_BUF * 4u };
    const uint32_t boff[2] = { (uint32_t)(2 * AS_BUF) * 4u, (uint32_t)(2 * AS_BUF + BS_BUF) * 4u };

    const int tid  = threadIdx.x;
    const int wid  = tid >> 5;
    const int lane = tid & 31;
    const int grp  = lane >> 2;
    const int t4   = lane & 3;
    const int wm = (wid & 3) * 32;
    const int wn = (wid >> 2) * 64;

    const int ar[4] = { (tid) >> 3, (tid + 256) >> 3, (tid + 512) >> 3, (tid + 768) >> 3 };
    const int ac = (tid & 7) * 4;
    const int bk4[4] = { (tid) >> 5, (tid + 256) >> 5, (tid + 512) >> 5, (tid + 768) >> 5 };
    const int bn = (tid & 31) * 4;

    float acc[2][8][4];
    #pragma unroll
    for (int i = 0; i < 2; i++)
        #pragma unroll
        for (int j = 0; j < 8; j++)
            #pragma unroll
            for (int c = 0; c < 4; c++) acc[i][j][c] = 0.0f;

    const int nit = K / 32;

    // prologue: tile 0
    {
        const float* Ab = A + (size_t)m0 * K;
        const float* Wb = W + n0;
        #pragma unroll
        for (int i = 0; i < 4; i++)
            cp_async16(sb + aoff[0] + (ar[i] * AS_STRIDE + ac) * 4, Ab + (size_t)ar[i] * K + ac);
        #pragma unroll
        for (int i = 0; i < 4; i++)
            cp_async16(sb + boff[0] + (bk4[i] * BS_STRIDE + bn) * 4, Wb + (size_t)bk4[i] * N + bn);
        CP_COMMIT();
    }

    for (int it = 0; it < nit; it++) {
        const int buf = it & 1;
        if (it + 1 < nit) {
            const float* Ab = A + (size_t)m0 * K + (size_t)(it + 1) * 32;
            const float* Wb = W + (size_t)(it + 1) * 32 * N + n0;
            #pragma unroll
            for (int i = 0; i < 4; i++)
                cp_async16(sb + aoff[buf ^ 1] + (ar[i] * AS_STRIDE + ac) * 4, Ab + (size_t)ar[i] * K + ac);
            #pragma unroll
            for (int i = 0; i < 4; i++)
                cp_async16(sb + boff[buf ^ 1] + (bk4[i] * BS_STRIDE + bn) * 4, Wb + (size_t)bk4[i] * N + bn);
            CP_COMMIT();
            CP_WAIT(1);
        } else {
            CP_WAIT(0);
        }
        __syncthreads();

        const uint32_t* As  = dsm + (buf ? AS_BUF : 0);
        const uint32_t* Bsm = dsm + 2 * AS_BUF + (buf ? BS_BUF : 0);
        #pragma unroll
        for (int kk = 0; kk < 4; kk++) {
            const int kb = kk * 8;
            uint32_t afr[2][4];
            #pragma unroll
            for (int mt = 0; mt < 2; mt++) {
                const int rb = wm + mt * 16;
                afr[mt][0] = As[(rb + grp)     * AS_STRIDE + kb + t4];
                afr[mt][1] = As[(rb + grp + 8) * AS_STRIDE + kb + t4];
                afr[mt][2] = As[(rb + grp)     * AS_STRIDE + kb + t4 + 4];
                afr[mt][3] = As[(rb + grp + 8) * AS_STRIDE + kb + t4 + 4];
            }
            uint32_t bfr[8][2];
            #pragma unroll
            for (int nt = 0; nt < 8; nt++) {
                const int col = wn + nt * 8 + grp;
                bfr[nt][0] = Bsm[(kb + t4)     * BS_STRIDE + col];
                bfr[nt][1] = Bsm[(kb + t4 + 4) * BS_STRIDE + col];
            }
            #pragma unroll
            for (int mt = 0; mt < 2; mt++)
                #pragma unroll
                for (int nt = 0; nt < 8; nt++)
                    mma_tf32(acc[mt][nt], afr[mt][0], afr[mt][1], afr[mt][2], afr[mt][3],
                             bfr[nt][0], bfr[nt][1]);
        }
        __syncthreads();
    }

    #pragma unroll
    for (int mt = 0; mt < 2; mt++) {
        #pragma unroll
        for (int nt = 0; nt < 8; nt++) {
            const int col = n0 + wn + nt * 8 + t4 * 2;
            const float b0v = bias[col], b1v = bias[col + 1];
            const int r0 = m0 + wm + mt * 16 + grp;
            float v0 = acc[mt][nt][0] + b0v;
            float v1 = acc[mt][nt][1] + b1v;
            float v2 = acc[mt][nt][2] + b0v;
            float v3 = acc[mt][nt][3] + b1v;
            if (ACT == 1) { v0 = gelu_f(v0); v1 = gelu_f(v1); v2 = gelu_f(v2); v3 = gelu_f(v3); }
            if (TFOUT) {
                v0 = __uint_as_float(f2tf32(v0));
                v1 = __uint_as_float(f2tf32(v1));
                v2 = __uint_as_float(f2tf32(v2));
                v3 = __uint_as_float(f2tf32(v3));
            }
            *(float2*)&C[(size_t)r0 * N + col]       = make_float2(v0, v1);
            *(float2*)&C[(size_t)(r0 + 8) * N + col] = make_float2(v2, v3);
        }
    }
}

template<int ACT, int TFOUT>
__global__ void __launch_bounds__(256, 2)
gemm_cp(const float* __restrict__ A, const float* __restrict__ W,
        const float* __restrict__ bias, float* __restrict__ C, int K, int N) {
    gemm_body<ACT, TFOUT>(A, W, bias, C, K, N, blockIdx.y * 128, blockIdx.x * 128);
}

// fused QKV: grid.x = 24; blockIdx.x>>3 selects q/k/v
__global__ void __launch_bounds__(256, 2)
qkv_gemm(const float* __restrict__ xt,
         const float* __restrict__ wq, const float* __restrict__ wk, const float* __restrict__ wv,
         const float* __restrict__ bq, const float* __restrict__ bk, const float* __restrict__ bv,
         float* __restrict__ q, float* __restrict__ k, float* __restrict__ v) {
    const int sel = blockIdx.x >> 3;
    const float* W    = (sel == 0) ? wq : (sel == 1) ? wk : wv;
    const float* bias = (sel == 0) ? bq : (sel == 1) ? bk : bv;
    float*       C    = (sel == 0) ? q  : (sel == 1) ? k  : v;
    gemm_body<0, 1>(xt, W, bias, C, DIM, DIM, blockIdx.y * 128, (blockIdx.x & 7) * 128);
}

// ---------------- Flash attention: tf32 mma + cp.async K/V pipeline ----------------
// Inputs q,k,v are tf32-rounded. 128 queries/block, KV tile 64, 8 warps.
#define KS_STRIDE 68
#define PS_STRIDE 72
#define AT_KBUF (64 * KS_STRIDE)
// words: K0,K1,V0,V1 (4*4352), Ps (9216), smask[2][64]
#define ATTN_SMEM_WORDS (4 * AT_KBUF + 128 * PS_STRIDE + 128)
#define ATTN_SMEM_BYTES (ATTN_SMEM_WORDS * 4)

__global__ void __launch_bounds__(256)
attn_mma(const float* __restrict__ Q, const float* __restrict__ K,
         const float* __restrict__ V, const int* __restrict__ mask,
         float* __restrict__ ctx) {
    extern __shared__ uint32_t asm_[];
    uint32_t* Ksb[2] = { asm_, asm_ + AT_KBUF };
    uint32_t* Vsb[2] = { asm_ + 2 * AT_KBUF, asm_ + 3 * AT_KBUF };
    uint32_t* Ps = asm_ + 4 * AT_KBUF;
    float* smaskb = (float*)(Ps + 128 * PS_STRIDE);   // [2][64]
    const uint32_t sb = smem_u32(asm_);
    const uint32_t koff[2] = { 0u, (uint32_t)AT_KBUF * 4u };
    const uint32_t voff[2] = { (uint32_t)(2 * AT_KBUF) * 4u, (uint32_t)(3 * AT_KBUF) * 4u };

    const int tid  = threadIdx.x;
    const int wid  = tid >> 5;
    const int lane = tid & 31;
    const int grp  = lane >> 2;
    const int t4   = lane & 3;
    const int w16  = wid * 16;
    const int q0 = blockIdx.x * 128;
    const int h  = blockIdx.y;
    const int b  = blockIdx.z;
    const size_t base = (size_t)b * SEQ * DIM + h * DPH;

    // stage Q (already tf32-rounded; *0.125 is exact)
    #pragma unroll
    for (int i = 0; i < 8; i++) {
        int idx = tid + i * 256;
        int row = idx >> 4, c4 = idx & 15;
        float4 v = *(const float4*)(Q + base + (size_t)(q0 + row) * DIM + c4 * 4);
        uint4 u;
        u.x = __float_as_uint(v.x * 0.125f); u.y = __float_as_uint(v.y * 0.125f);
        u.z = __float_as_uint(v.z * 0.125f); u.w = __float_as_uint(v.w * 0.125f);
        *(uint4*)&Ps[row * PS_STRIDE + c4 * 4] = u;
    }
    __syncthreads();

    uint32_t qf[8][4];
    #pragma unroll
    for (int k = 0; k < 8; k++) {
        qf[k][0] = Ps[(w16 + grp)     * PS_STRIDE + k * 8 + t4];
        qf[k][1] = Ps[(w16 + grp + 8) * PS_STRIDE + k * 8 + t4];
        qf[k][2] = Ps[(w16 + grp)     * PS_STRIDE + k * 8 + t4 + 4];
        qf[k][3] = Ps[(w16 + grp + 8) * PS_STRIDE + k * 8 + t4 + 4];
    }
    __syncthreads();

    // per-thread K/V load coords
    const int lrow[4] = { tid >> 4, (tid + 256) >> 4, (tid + 512) >> 4, (tid + 768) >> 4 };
    const int lc = (tid & 15) * 4;

    float o[8][4];
    #pragma unroll
    for (int nf = 0; nf < 8; nf++)
        #pragma unroll
        for (int c = 0; c < 4; c++) o[nf][c] = 0.0f;
    float mrow0 = -INFINITY, mrow1 = -INFINITY;
    float l0 = 0.0f, l1 = 0.0f;

    // prologue: tile 0
    {
        #pragma unroll
        for (int i = 0; i < 4; i++) {
            size_t g = base + (size_t)lrow[i] * DIM + lc;
            cp_async16(sb + koff[0] + (lrow[i] * KS_STRIDE + lc) * 4, K + g);
            cp_async16(sb + voff[0] + (lrow[i] * KS_STRIDE + lc) * 4, V + g);
        }
        CP_COMMIT();
        if (tid < 64)
            smaskb[tid] = (mask[b * SEQ + tid] == 0) ? -INFINITY : 0.0f;
    }

    const int nt_tiles = SEQ / 64;
    for (int it = 0; it < nt_tiles; it++) {
        const int buf = it & 1;
        const int kv_next = (it + 1) * 64;
        if (it + 1 < nt_tiles) {
            #pragma unroll
            for (int i = 0; i < 4; i++) {
                size_t g = base + (size_t)(kv_next + lrow[i]) * DIM + lc;
                cp_async16(sb + koff[buf ^ 1] + (lrow[i] * KS_STRIDE + lc) * 4, K + g);
                cp_async16(sb + voff[buf ^ 1] + (lrow[i] * KS_STRIDE + lc) * 4, V + g);
            }
            CP_COMMIT();
            if (tid < 64)
                smaskb[(buf ^ 1) * 64 + tid] = (mask[b * SEQ + kv_next + tid] == 0) ? -INFINITY : 0.0f;
            CP_WAIT(1);
        } else {
            CP_WAIT(0);
        }
        __syncthreads();

        const uint32_t* Ks = Ksb[buf];
        const uint32_t* Vs = Vsb[buf];
        const float* smask = smaskb + buf * 64;

        float s[8][4];
        #pragma unroll
        for (int nf = 0; nf < 8; nf++)
            #pragma unroll
            for (int c = 0; c < 4; c++) s[nf][c] = 0.0f;
        #pragma unroll
        for (int k = 0; k < 8; k++) {
            const int kb = k * 8;
            #pragma unroll
            for (int nf = 0; nf < 8; nf++) {
                uint32_t b0 = Ks[(nf * 8 + grp) * KS_STRIDE + kb + t4];
                uint32_t b1 = Ks[(nf * 8 + grp) * KS_STRIDE + kb + t4 + 4];
                mma_tf32(s[nf], qf[k][0], qf[k][1], qf[k][2], qf[k][3], b0, b1);
            }
        }

        #pragma unroll
        for (int nf = 0; nf < 8; nf++) {
            float mv0 = smask[nf * 8 + t4 * 2];
            float mv1 = smask[nf * 8 + t4 * 2 + 1];
            s[nf][0] += mv0; s[nf][1] += mv1;
            s[nf][2] += mv0; s[nf][3] += mv1;
        }

        float mt0 = -INFINITY, mt1 = -INFINITY;
        #pragma unroll
        for (int nf = 0; nf < 8; nf++) {
            mt0 = fmaxf(mt0, fmaxf(s[nf][0], s[nf][1]));
            mt1 = fmaxf(mt1, fmaxf(s[nf][2], s[nf][3]));
        }
        mt0 = fmaxf(mt0, __shfl_xor_sync(0xffffffffu, mt0, 1));
        mt0 = fmaxf(mt0, __shfl_xor_sync(0xffffffffu, mt0, 2));
        mt1 = fmaxf(mt1, __shfl_xor_sync(0xffffffffu, mt1, 1));
        mt1 = fmaxf(mt1, __shfl_xor_sync(0xffffffffu, mt1, 2));
        float mnew0 = fmaxf(mrow0, mt0);
        float mnew1 = fmaxf(mrow1, mt1);
        float alpha0 = __expf(mrow0 - mnew0);
        float alpha1 = __expf(mrow1 - mnew1);
        float lsum0 = 0.0f, lsum1 = 0.0f;
        #pragma unroll
        for (int nf = 0; nf < 8; nf++) {
            s[nf][0] = __expf(s[nf][0] - mnew0);
            s[nf][1] = __expf(s[nf][1] - mnew0);
            s[nf][2] = __expf(s[nf][2] - mnew1);
            s[nf][3] = __expf(s[nf][3] - mnew1);
            lsum0 += s[nf][0] + s[nf][1];
            lsum1 += s[nf][2] + s[nf][3];
        }
        lsum0 += __shfl_xor_sync(0xffffffffu, lsum0, 1);
        lsum0 += __shfl_xor_sync(0xffffffffu, lsum0, 2);
        lsum1 += __shfl_xor_sync(0xffffffffu, lsum1, 1);
        lsum1 += __shfl_xor_sync(0xffffffffu, lsum1, 2);
        l0 = l0 * alpha0 + lsum0;
        l1 = l1 * alpha1 + lsum1;
        mrow0 = mnew0; mrow1 = mnew1;
        #pragma unroll
        for (int nf = 0; nf < 8; nf++) {
            o[nf][0] *= alpha0; o[nf][1] *= alpha0;
            o[nf][2] *= alpha1; o[nf][3] *= alpha1;
        }

        #pragma unroll
        for (int nf = 0; nf < 8; nf++) {
            const int col = nf * 8 + t4 * 2;
            Ps[(w16 + grp)     * PS_STRIDE + col]     = f2tf32(s[nf][0]);
            Ps[(w16 + grp)     * PS_STRIDE + col + 1] = f2tf32(s[nf][1]);
            Ps[(w16 + grp + 8) * PS_STRIDE + col]     = f2tf32(s[nf][2]);
            Ps[(w16 + grp + 8) * PS_STRIDE + col + 1] = f2tf32(s[nf][3]);
        }
        __syncwarp();

        #pragma unroll
        for (int k = 0; k < 8; k++) {
            const int kb = k * 8;
            uint32_t a0 = Ps[(w16 + grp)     * PS_STRIDE + kb + t4];
            uint32_t a1 = Ps[(w16 + grp + 8) * PS_STRIDE + kb + t4];
            uint32_t a2 = Ps[(w16 + grp)     * PS_STRIDE + kb + t4 + 4];
            uint32_t a3 = Ps[(w16 + grp + 8) * PS_STRIDE + kb + t4 + 4];
            #pragma unroll
            for (int nf = 0; nf < 8; nf++) {
                uint32_t b0 = Vs[(kb + t4)     * KS_STRIDE + nf * 8 + grp];
                uint32_t b1 = Vs[(kb + t4 + 4) * KS_STRIDE + nf * 8 + grp];
                mma_tf32(o[nf], a0, a1, a2, a3, b0, b1);
            }
        }
        __syncthreads();
    }

    // normalize + write ctx tf32-rounded (ctx only feeds the Wo GEMM)
    const float inv0 = 1.0f / l0;
    const float inv1 = 1.0f / l1;
    const int r0 = q0 + w16 + grp;
    #pragma unroll
    for (int nf = 0; nf < 8; nf++) {
        const int d0 = nf * 8 + t4 * 2;
        *(float2*)&ctx[base + (size_t)r0 * DIM + d0] =
            make_float2(__uint_as_float(f2tf32(o[nf][0] * inv0)),
                        __uint_as_float(f2tf32(o[nf][1] * inv0)));
        *(float2*)&ctx[base + (size_t)(r0 + 8) * DIM + d0] =
            make_float2(__uint_as_float(f2tf32(o[nf][2] * inv1)),
                        __uint_as_float(f2tf32(o[nf][3] * inv1)));
    }
}

// ---------------- residual + LayerNorm (optional tf32 second output) ----------------
template<int TF>
__global__ void ln_residual_kernel(const float* __restrict__ a,
                                   const float* __restrict__ r,
                                   const float* __restrict__ gamma,
                                   const float* __restrict__ beta,
                                   float* __restrict__ out,
                                   float* __restrict__ out_t) {
    const int row = blockIdx.x;
    const int tid = threadIdx.x;
    const float* pa = a + (size_t)row * DIM;
    const float* pr = r + (size_t)row * DIM;

    float v[4];
    float sum = 0.0f, sq = 0.0f;
    #pragma unroll
    for (int i = 0; i < 4; i++) {
        int c = tid + i * 256;
        float t = pa[c] + pr[c];
        v[i] = t;
        sum += t;
        sq  += t * t;
    }
    #pragma unroll
    for (int off = 16; off >= 1; off >>= 1) {
        sum += __shfl_xor_sync(0xffffffffu, sum, off);
        sq  += __shfl_xor_sync(0xffffffffu, sq,  off);
    }
    __shared__ float ssum[8], ssq[8];
    int warp = tid >> 5, lane = tid & 31;
    if (lane == 0) { ssum[warp] = sum; ssq[warp] = sq; }
    __syncthreads();
    sum = 0.0f; sq = 0.0f;
    #pragma unroll
    for (int i = 0; i < 8; i++) { sum += ssum[i]; sq += ssq[i]; }

    const float invN = 1.0f / (float)DIM;
    float mu  = sum * invN;
    float var = fmaxf(sq * invN - mu * mu, 0.0f);
    float rstd = rsqrtf(var + 1e-12f);

    #pragma unroll
    for (int i = 0; i < 4; i++) {
        int c = tid + i * 256;
        float res = (v[i] - mu) * rstd * gamma[c] + beta[c];
        out[(size_t)row * DIM + c] = res;
        if (TF) out_t[(size_t)row * DIM + c] = __uint_as_float(f2tf32(res));
    }
}

// ---------------- launch ----------------
extern "C" void kernel_launch(void* const* d_in, const int* in_sizes, int n_in,
                              void* d_out, int out_size) {
    const float* x    = (const float*)d_in[0];
    const int*   mask = (const int*)  d_in[1];
    const float* Wq   = (const float*)d_in[2];
    const float* bq   = (const float*)d_in[3];
    const float* Wk   = (const float*)d_in[4];
    const float* bk   = (const float*)d_in[5];
    const float* Wv   = (const float*)d_in[6];
    const float* bv   = (const float*)d_in[7];
    const float* Wo   = (const float*)d_in[8];
    const float* bo   = (const float*)d_in[9];
    const float* ln1g = (const float*)d_in[10];
    const float* ln1b = (const float*)d_in[11];
    const float* W1   = (const float*)d_in[12];
    const float* b1   = (const float*)d_in[13];
    const float* W2   = (const float*)d_in[14];
    const float* b2   = (const float*)d_in[15];
    const float* ln2g = (const float*)d_in[16];
    const float* ln2b = (const float*)d_in[17];
    float* out = (float*)d_out;

    float *q, *k, *v, *ctx, *h1, *h1t, *ffn, *xt, *wqt, *wkt, *wvt, *wot, *w1t, *w2t;
    cudaGetSymbolAddress((void**)&q,   g_q);
    cudaGetSymbolAddress((void**)&k,   g_k);
    cudaGetSymbolAddress((void**)&v,   g_v);
    cudaGetSymbolAddress((void**)&ctx, g_ctx);
    cudaGetSymbolAddress((void**)&h1,  g_h1);
    cudaGetSymbolAddress((void**)&h1t, g_h1t);
    cudaGetSymbolAddress((void**)&ffn, g_ffn);
    cudaGetSymbolAddress((void**)&xt,  g_xt);
    cudaGetSymbolAddress((void**)&wqt, g_wqt);
    cudaGetSymbolAddress((void**)&wkt, g_wkt);
    cudaGetSymbolAddress((void**)&wvt, g_wvt);
    cudaGetSymbolAddress((void**)&wot, g_wot);
    cudaGetSymbolAddress((void**)&w1t, g_w1t);
    cudaGetSymbolAddress((void**)&w2t, g_w2t);

    cudaFuncSetAttribute(qkv_gemm,      cudaFuncAttributeMaxDynamicSharedMemorySize, GEMM_SMEM_BYTES);
    cudaFuncSetAttribute(gemm_cp<0,0>,  cudaFuncAttributeMaxDynamicSharedMemorySize, GEMM_SMEM_BYTES);
    cudaFuncSetAttribute(gemm_cp<1,1>,  cudaFuncAttributeMaxDynamicSharedMemorySize, GEMM_SMEM_BYTES);
    cudaFuncSetAttribute(attn_mma,      cudaFuncAttributeMaxDynamicSharedMemorySize, ATTN_SMEM_BYTES);

    // tf32 rounding passes (weights + x)
    {
        const int thr = 256;
        cvt_tf32_kernel<<<(MROWS*DIM/4 + thr-1)/thr, thr>>>(x,  xt,  MROWS*DIM/4);
        cvt_tf32_kernel<<<(DIM*DIM/4   + thr-1)/thr, thr>>>(Wq, wqt, DIM*DIM/4);
        cvt_tf32_kernel<<<(DIM*DIM/4   + thr-1)/thr, thr>>>(Wk, wkt, DIM*DIM/4);
        cvt_tf32_kernel<<<(DIM*DIM/4   + thr-1)/thr, thr>>>(Wv, wvt, DIM*DIM/4);
        cvt_tf32_kernel<<<(DIM*DIM/4   + thr-1)/thr, thr>>>(Wo, wot, DIM*DIM/4);
        cvt_tf32_kernel<<<(DIM*HID/4   + thr-1)/thr, thr>>>(W1, w1t, DIM*HID/4);
        cvt_tf32_kernel<<<(HID*DIM/4   + thr-1)/thr, thr>>>(W2, w2t, HID*DIM/4);
    }

    // fused QKV (tf32 outputs)
    qkv_gemm<<<dim3(24, MROWS/128), 256, GEMM_SMEM_BYTES>>>(xt, wqt, wkt, wvt, bq, bk, bv, q, k, v);

    // attention (pipelined, tf32 ctx out)
    attn_mma<<<dim3(SEQ/128, NH, BS), 256, ATTN_SMEM_BYTES>>>(q, k, v, mask, ctx);

    // output projection -> sa_out (fp32) in q
    gemm_cp<0,0><<<dim3(DIM/128, MROWS/128), 256, GEMM_SMEM_BYTES>>>(ctx, wot, bo, q, DIM, DIM);

    // LN1(sa_out + x) -> h1 (fp32) + h1t (tf32)
    ln_residual_kernel<1><<<MROWS, 256>>>(q, x, ln1g, ln1b, h1, h1t);

    // FFN1: gelu, tf32 out
    gemm_cp<1,1><<<dim3(HID/128, MROWS/128), 256, GEMM_SMEM_BYTES>>>(h1t, w1t, b1, ffn, DIM, HID);
    // FFN2: fp32 out into k (reused)
    gemm_cp<0,0><<<dim3(DIM/128, MROWS/128), 256, GEMM_SMEM_BYTES>>>(ffn, w2t, b2, k, HID, DIM);

    // LN2(ffn_out + h1) -> out
    ln_residual_kernel<0><<<MROWS, 256>>>(k, h1, ln2g, ln2b, out, nullptr);
}

// round 8
// speedup vs baseline: 3.5309x; 1.0562x over previous
#include <cuda_runtime.h>
#include <math.h>
#include <stdint.h>

#define BS   2
#define SEQ  2048
#define DIM  1024
#define HID  4096
#define NH   16
#define DPH  64
#define MROWS (BS*SEQ)   // 4096

// ---------------- scratch (no allocation allowed) ----------------
__device__ float g_q  [MROWS*DIM];
__device__ float g_k  [MROWS*DIM];
__device__ float g_v  [MROWS*DIM];
__device__ float g_ctx[MROWS*DIM];
__device__ float g_h1 [MROWS*DIM];
__device__ float g_h1t[MROWS*DIM];
__device__ float g_ffn[MROWS*HID];
__device__ float g_xt [MROWS*DIM];
__device__ float g_wqt[DIM*DIM];
__device__ float g_wkt[DIM*DIM];
__device__ float g_wvt[DIM*DIM];
__device__ float g_wot[DIM*DIM];
__device__ float g_w1t[DIM*HID];
__device__ float g_w2t[HID*DIM];

__device__ __forceinline__ uint32_t f2tf32(float f) {
    uint32_t r;
    asm("cvt.rna.tf32.f32 %0, %1;" : "=r"(r) : "f"(f));
    return r;
}
__device__ __forceinline__ uint32_t smem_u32(const void* p) {
    uint32_t a;
    asm("{ .reg .u64 t; cvta.to.shared.u64 t, %1; cvt.u32.u64 %0, t; }" : "=r"(a) : "l"(p));
    return a;
}
__device__ __forceinline__ void cp_async16(uint32_t dst, const void* src) {
    asm volatile("cp.async.cg.shared.global [%0], [%1], 16;" :: "r"(dst), "l"(src));
}
#define CP_COMMIT() asm volatile("cp.async.commit_group;" ::: "memory")
#define CP_WAIT(n)  asm volatile("cp.async.wait_group %0;" :: "n"(n) : "memory")

__device__ __forceinline__ void ldmatrix_x4(uint32_t& r0, uint32_t& r1, uint32_t& r2, uint32_t& r3,
                                            uint32_t addr) {
    asm volatile("ldmatrix.sync.aligned.m8n8.x4.shared.b16 {%0,%1,%2,%3}, [%4];"
        : "=r"(r0), "=r"(r1), "=r"(r2), "=r"(r3) : "r"(addr));
}

__device__ __forceinline__ void mma_tf32(float* d,
                                         uint32_t a0, uint32_t a1, uint32_t a2, uint32_t a3,
                                         uint32_t b0, uint32_t b1) {
    asm volatile(
        "mma.sync.aligned.m16n8k8.row.col.f32.tf32.tf32.f32 "
        "{%0,%1,%2,%3}, {%4,%5,%6,%7}, {%8,%9}, {%0,%1,%2,%3};"
        : "+f"(d[0]), "+f"(d[1]), "+f"(d[2]), "+f"(d[3])
        : "r"(a0), "r"(a1), "r"(a2), "r"(a3), "r"(b0), "r"(b1));
}

__device__ __forceinline__ float gelu_f(float x) {
    return 0.5f * x * (1.0f + erff(x * 0.70710678118654752f));
}

// ---------------- prep passes ----------------
__global__ void cvt_tf32_kernel(const float* __restrict__ in, float* __restrict__ out, int n4) {
    int i = blockIdx.x * blockDim.x + threadIdx.x;
    if (i < n4) {
        float4 v = ((const float4*)in)[i];
        uint4 u;
        u.x = f2tf32(v.x); u.y = f2tf32(v.y); u.z = f2tf32(v.z); u.w = f2tf32(v.w);
        ((uint4*)out)[i] = u;
    }
}

// out[c][r] = tf32(in[r][c]); R, C multiples of 32. block (32,8), grid (C/32, R/32)
__global__ void transpose_tf32_kernel(const float* __restrict__ in, float* __restrict__ out,
                                      int R, int C) {
    __shared__ float tile[32][33];
    const int c0 = blockIdx.x * 32, r0 = blockIdx.y * 32;
    const int tx = threadIdx.x, ty = threadIdx.y;
    #pragma unroll
    for (int i = 0; i < 32; i += 8)
        tile[ty + i][tx] = in[(size_t)(r0 + ty + i) * C + c0 + tx];
    __syncthreads();
    #pragma unroll
    for (int i = 0; i < 32; i += 8)
        out[(size_t)(c0 + ty + i) * R + r0 + tx] = __uint_as_float(f2tf32(tile[tx][ty + i]));
}

// ---------------- tf32 GEMM: both operands K-major, ldmatrix fragments ----------------
// C[M,N] = A[M,K] @ Wt[N,K]^T + bias. CTA 128x128, BK=32, 3-stage cp.async.
#define GS 36                                  // smem row stride (words) for 32-k tiles
#define G_TILE_BYTES (128 * GS * 4)            // 18432
#define G_STAGE_BYTES (2 * G_TILE_BYTES)       // 36864
#define GEMM_SMEM_BYTES (3 * G_STAGE_BYTES)    // 110592

template<int ACT, int TFOUT>
__device__ __forceinline__ void gemm_body(const float* __restrict__ A,
                                          const float* __restrict__ Wt,
                                          const float* __restrict__ bias,
                                          float* __restrict__ C,
                                          int K, int N, int m0, int n0) {
    extern __shared__ uint32_t dsm[];
    const uint32_t sb = smem_u32(dsm);

    const int tid  = threadIdx.x;
    const int wid  = tid >> 5;
    const int lane = tid & 31;
    const int grp  = lane >> 2;
    const int t4   = lane & 3;
    const int ts   = lane >> 3;
    const int r8   = lane & 7;
    const int wm = (wid & 3) * 32;
    const int wn = (wid >> 2) * 64;

    const int lrow = tid >> 3;
    const int lcol = (tid & 7) * 4;

    // ldmatrix per-lane offsets (bytes)
    const uint32_t a_loff = (uint32_t)((((ts & 1) * 8 + r8) * GS + (ts >> 1) * 4) * 4);
    const uint32_t b_loff = (uint32_t)((((ts >> 1) * 8 + r8) * GS + (ts & 1) * 4) * 4);

    float acc[2][8][4];
    #pragma unroll
    for (int i = 0; i < 2; i++)
        #pragma unroll
        for (int j = 0; j < 8; j++)
            #pragma unroll
            for (int c = 0; c < 4; c++) acc[i][j][c] = 0.0f;

    const int nit = K / 32;

    auto load_stage = [&](int s, int it) {
        const uint32_t base = sb + (uint32_t)s * G_STAGE_BYTES;
        const float* Ab = A  + (size_t)(m0 + lrow) * K + it * 32 + lcol;
        const float* Bb = Wt + (size_t)(n0 + lrow) * K + it * 32 + lcol;
        #pragma unroll
        for (int i = 0; i < 4; i++)
            cp_async16(base + (uint32_t)(((lrow + 32 * i) * GS + lcol) * 4), Ab + (size_t)(32 * i) * K);
        #pragma unroll
        for (int i = 0; i < 4; i++)
            cp_async16(base + G_TILE_BYTES + (uint32_t)(((lrow + 32 * i) * GS + lcol) * 4), Bb + (size_t)(32 * i) * K);
    };

    load_stage(0, 0);
    CP_COMMIT();
    load_stage(1, 1);
    CP_COMMIT();

    for (int it = 0; it < nit; it++) {
        const int s = it % 3;
        CP_WAIT(1);
        __syncthreads();
        if (it + 2 < nit) load_stage((it + 2) % 3, it + 2);
        CP_COMMIT();

        const uint32_t sA = sb + (uint32_t)s * G_STAGE_BYTES + (uint32_t)(wm * GS * 4) + a_loff;
        const uint32_t sB = sb + (uint32_t)s * G_STAGE_BYTES + G_TILE_BYTES + (uint32_t)(wn * GS * 4) + b_loff;
        #pragma unroll
        for (int kk = 0; kk < 4; kk++) {
            const uint32_t kb4 = kk * 32;    // kb * 4 bytes
            uint32_t afr[2][4];
            #pragma unroll
            for (int mt = 0; mt < 2; mt++)
                ldmatrix_x4(afr[mt][0], afr[mt][1], afr[mt][2], afr[mt][3],
                            sA + (uint32_t)(mt * 16 * GS * 4) + kb4);
            uint32_t bfr[8][2];
            #pragma unroll
            for (int np = 0; np < 4; np++)
                ldmatrix_x4(bfr[2*np][0], bfr[2*np][1], bfr[2*np+1][0], bfr[2*np+1][1],
                            sB + (uint32_t)(np * 16 * GS * 4) + kb4);
            #pragma unroll
            for (int mt = 0; mt < 2; mt++)
                #pragma unroll
                for (int nt = 0; nt < 8; nt++)
                    mma_tf32(acc[mt][nt], afr[mt][0], afr[mt][1], afr[mt][2], afr[mt][3],
                             bfr[nt][0], bfr[nt][1]);
        }
    }

    #pragma unroll
    for (int mt = 0; mt < 2; mt++) {
        #pragma unroll
        for (int nt = 0; nt < 8; nt++) {
            const int col = n0 + wn + nt * 8 + t4 * 2;
            const float b0v = bias[col], b1v = bias[col + 1];
            const int r0 = m0 + wm + mt * 16 + grp;
            float v0 = acc[mt][nt][0] + b0v;
            float v1 = acc[mt][nt][1] + b1v;
            float v2 = acc[mt][nt][2] + b0v;
            float v3 = acc[mt][nt][3] + b1v;
            if (ACT == 1) { v0 = gelu_f(v0); v1 = gelu_f(v1); v2 = gelu_f(v2); v3 = gelu_f(v3); }
            if (TFOUT) {
                v0 = __uint_as_float(f2tf32(v0));
                v1 = __uint_as_float(f2tf32(v1));
                v2 = __uint_as_float(f2tf32(v2));
                v3 = __uint_as_float(f2tf32(v3));
            }
            *(float2*)&C[(size_t)r0 * N + col]       = make_float2(v0, v1);
            *(float2*)&C[(size_t)(r0 + 8) * N + col] = make_float2(v2, v3);
        }
    }
}

template<int ACT, int TFOUT>
__global__ void __launch_bounds__(256, 2)
gemm_cp(const float* __restrict__ A, const float* __restrict__ Wt,
        const float* __restrict__ bias, float* __restrict__ C, int K, int N) {
    gemm_body<ACT, TFOUT>(A, Wt, bias, C, K, N, blockIdx.y * 128, blockIdx.x * 128);
}

__global__ void __launch_bounds__(256, 2)
qkv_gemm(const float* __restrict__ xt,
         const float* __restrict__ wq, const float* __restrict__ wk, const float* __restrict__ wv,
         const float* __restrict__ bq, const float* __restrict__ bk, const float* __restrict__ bv,
         float* __restrict__ q, float* __restrict__ k, float* __restrict__ v) {
    const int sel = blockIdx.x >> 3;
    const float* W    = (sel == 0) ? wq : (sel == 1) ? wk : wv;
    const float* bias = (sel == 0) ? bq : (sel == 1) ? bk : bv;
    float*       C    = (sel == 0) ? q  : (sel == 1) ? k  : v;
    gemm_body<0, 1>(xt, W, bias, C, DIM, DIM, blockIdx.y * 128, (blockIdx.x & 7) * 128);
}

// ---------------- Flash attention: ldmatrix K/P frags, cp.async K/V pipeline ----------------
#define KS_STRIDE 68
#define VS_STRIDE 72
#define PS_STRIDE 76
#define AT_KBUF (64 * KS_STRIDE)     // 4352 words
#define AT_VBUF (64 * VS_STRIDE)     // 4608 words
#define AT_P    (128 * PS_STRIDE)    // 9728 words
#define ATTN_SMEM_WORDS (2 * AT_KBUF + 2 * AT_VBUF + AT_P + 128)
#define ATTN_SMEM_BYTES (ATTN_SMEM_WORDS * 4)

__global__ void __launch_bounds__(256)
attn_mma(const float* __restrict__ Q, const float* __restrict__ K,
         const float* __restrict__ V, const int* __restrict__ mask,
         float* __restrict__ ctx) {
    extern __shared__ uint32_t asm_[];
    uint32_t* Vsb[2] = { asm_ + 2 * AT_KBUF, asm_ + 2 * AT_KBUF + AT_VBUF };
    uint32_t* Ps = asm_ + 2 * AT_KBUF + 2 * AT_VBUF;
    float* smaskb = (float*)(Ps + AT_P);
    const uint32_t sb = smem_u32(asm_);
    const uint32_t koff[2] = { 0u, (uint32_t)AT_KBUF * 4u };
    const uint32_t voff[2] = { (uint32_t)(2 * AT_KBUF) * 4u, (uint32_t)(2 * AT_KBUF + AT_VBUF) * 4u };
    const uint32_t sbP = sb + (uint32_t)(2 * AT_KBUF + 2 * AT_VBUF) * 4u;

    const int tid  = threadIdx.x;
    const int wid  = tid >> 5;
    const int lane = tid & 31;
    const int grp  = lane >> 2;
    const int t4   = lane & 3;
    const int ts   = lane >> 3;
    const int r8   = lane & 7;
    const int w16  = wid * 16;
    const int q0 = blockIdx.x * 128;
    const int h  = blockIdx.y;
    const int b  = blockIdx.z;
    const size_t base = (size_t)b * SEQ * DIM + h * DPH;

    const uint32_t k_loff = (uint32_t)((((ts >> 1) * 8 + r8) * KS_STRIDE + (ts & 1) * 4) * 4);
    const uint32_t p_loff = (uint32_t)(((w16 + (ts & 1) * 8 + r8) * PS_STRIDE + (ts >> 1) * 4) * 4);

    // stage Q (tf32-rounded already; *0.125 exact)
    #pragma unroll
    for (int i = 0; i < 8; i++) {
        int idx = tid + i * 256;
        int row = idx >> 4, c4 = idx & 15;
        float4 v = *(const float4*)(Q + base + (size_t)(q0 + row) * DIM + c4 * 4);
        uint4 u;
        u.x = __float_as_uint(v.x * 0.125f); u.y = __float_as_uint(v.y * 0.125f);
        u.z = __float_as_uint(v.z * 0.125f); u.w = __float_as_uint(v.w * 0.125f);
        *(uint4*)&Ps[row * PS_STRIDE + c4 * 4] = u;
    }
    __syncthreads();

    uint32_t qf[8][4];
    #pragma unroll
    for (int k = 0; k < 8; k++) {
        ldmatrix_x4(qf[k][0], qf[k][1], qf[k][2], qf[k][3], sbP + p_loff + (uint32_t)(k * 32));
    }
    __syncthreads();

    const int lrow = tid >> 4;
    const int lc = (tid & 15) * 4;

    float o[8][4];
    #pragma unroll
    for (int nf = 0; nf < 8; nf++)
        #pragma unroll
        for (int c = 0; c < 4; c++) o[nf][c] = 0.0f;
    float mrow0 = -INFINITY, mrow1 = -INFINITY;
    float l0 = 0.0f, l1 = 0.0f;

    {
        #pragma unroll
        for (int i = 0; i < 4; i++) {
            size_t g = base + (size_t)(lrow + 16 * i) * DIM + lc;
            cp_async16(sb + koff[0] + (uint32_t)(((lrow + 16 * i) * KS_STRIDE + lc) * 4), K + g);
            cp_async16(sb + voff[0] + (uint32_t)(((lrow + 16 * i) * VS_STRIDE + lc) * 4), V + g);
        }
        CP_COMMIT();
        if (tid < 64)
            smaskb[tid] = (mask[b * SEQ + tid] == 0) ? -INFINITY : 0.0f;
    }

    const int nt_tiles = SEQ / 64;
    for (int it = 0; it < nt_tiles; it++) {
        const int buf = it & 1;
        const int kv_next = (it + 1) * 64;
        if (it + 1 < nt_tiles) {
            #pragma unroll
            for (int i = 0; i < 4; i++) {
                size_t g = base + (size_t)(kv_next + lrow + 16 * i) * DIM + lc;
                cp_async16(sb + koff[buf ^ 1] + (uint32_t)(((lrow + 16 * i) * KS_STRIDE + lc) * 4), K + g);
                cp_async16(sb + voff[buf ^ 1] + (uint32_t)(((lrow + 16 * i) * VS_STRIDE + lc) * 4), V + g);
            }
            CP_COMMIT();
            if (tid < 64)
                smaskb[(buf ^ 1) * 64 + tid] = (mask[b * SEQ + kv_next + tid] == 0) ? -INFINITY : 0.0f;
            CP_WAIT(1);
        } else {
            CP_WAIT(0);
        }
        __syncthreads();

        const uint32_t sbK = sb + koff[buf] + k_loff;
        const uint32_t* Vs = Vsb[buf];
        const float* smask = smaskb + buf * 64;

        float s[8][4];
        #pragma unroll
        for (int nf = 0; nf < 8; nf++)
            #pragma unroll
            for (int c = 0; c < 4; c++) s[nf][c] = 0.0f;
        #pragma unroll
        for (int k = 0; k < 8; k++) {
            const uint32_t kb4 = k * 32;
            #pragma unroll
            for (int np = 0; np < 4; np++) {
                uint32_t b00, b01, b10, b11;
                ldmatrix_x4(b00, b01, b10, b11,
                            sbK + (uint32_t)(np * 16 * KS_STRIDE * 4) + kb4);
                mma_tf32(s[2*np],   qf[k][0], qf[k][1], qf[k][2], qf[k][3], b00, b01);
                mma_tf32(s[2*np+1], qf[k][0], qf[k][1], qf[k][2], qf[k][3], b10, b11);
            }
        }

        #pragma unroll
        for (int nf = 0; nf < 8; nf++) {
            float mv0 = smask[nf * 8 + t4 * 2];
            float mv1 = smask[nf * 8 + t4 * 2 + 1];
            s[nf][0] += mv0; s[nf][1] += mv1;
            s[nf][2] += mv0; s[nf][3] += mv1;
        }

        float mt0 = -INFINITY, mt1 = -INFINITY;
        #pragma unroll
        for (int nf = 0; nf < 8; nf++) {
            mt0 = fmaxf(mt0, fmaxf(s[nf][0], s[nf][1]));
            mt1 = fmaxf(mt1, fmaxf(s[nf][2], s[nf][3]));
        }
        mt0 = fmaxf(mt0, __shfl_xor_sync(0xffffffffu, mt0, 1));
        mt0 = fmaxf(mt0, __shfl_xor_sync(0xffffffffu, mt0, 2));
        mt1 = fmaxf(mt1, __shfl_xor_sync(0xffffffffu, mt1, 1));
        mt1 = fmaxf(mt1, __shfl_xor_sync(0xffffffffu, mt1, 2));
        float mnew0 = fmaxf(mrow0, mt0);
        float mnew1 = fmaxf(mrow1, mt1);
        float alpha0 = __expf(mrow0 - mnew0);
        float alpha1 = __expf(mrow1 - mnew1);
        float lsum0 = 0.0f, lsum1 = 0.0f;
        #pragma unroll
        for (int nf = 0; nf < 8; nf++) {
            s[nf][0] = __expf(s[nf][0] - mnew0);
            s[nf][1] = __expf(s[nf][1] - mnew0);
            s[nf][2] = __expf(s[nf][2] - mnew1);
            s[nf][3] = __expf(s[nf][3] - mnew1);
            lsum0 += s[nf][0] + s[nf][1];
            lsum1 += s[nf][2] + s[nf][3];
        }
        lsum0 += __shfl_xor_sync(0xffffffffu, lsum0, 1);
        lsum0 += __shfl_xor_sync(0xffffffffu, lsum0, 2);
        lsum1 += __shfl_xor_sync(0xffffffffu, lsum1, 1);
        lsum1 += __shfl_xor_sync(0xffffffffu, lsum1, 2);
        l0 = l0 * alpha0 + lsum0;
        l1 = l1 * alpha1 + lsum1;
        mrow0 = mnew0; mrow1 = mnew1;
        #pragma unroll
        for (int nf = 0; nf < 8; nf++) {
            o[nf][0] *= alpha0; o[nf][1] *= alpha0;
            o[nf][2] *= alpha1; o[nf][3] *= alpha1;
        }

        #pragma unroll
        for (int nf = 0; nf < 8; nf++) {
            const int col = nf * 8 + t4 * 2;
            Ps[(w16 + grp)     * PS_STRIDE + col]     = f2tf32(s[nf][0]);
            Ps[(w16 + grp)     * PS_STRIDE + col + 1] = f2tf32(s[nf][1]);
            Ps[(w16 + grp + 8) * PS_STRIDE + col]     = f2tf32(s[nf][2]);
            Ps[(w16 + grp + 8) * PS_STRIDE + col + 1] = f2tf32(s[nf][3]);
        }
        __syncwarp();

        #pragma unroll
        for (int k = 0; k < 8; k++) {
            const int kb = k * 8;
            uint32_t a0, a1, a2, a3;
            ldmatrix_x4(a0, a1, a2, a3, sbP + p_loff + (uint32_t)(k * 32));
            #pragma unroll
            for (int nf = 0; nf < 8; nf++) {
                uint32_t b0 = Vs[(kb + t4)     * VS_STRIDE + nf * 8 + grp];
                uint32_t b1 = Vs[(kb + t4 + 4) * VS_STRIDE + nf * 8 + grp];
                mma_tf32(o[nf], a0, a1, a2, a3, b0, b1);
            }
        }
        __syncthreads();
    }

    const float inv0 = 1.0f / l0;
    const float inv1 = 1.0f / l1;
    const int r0 = q0 + w16 + grp;
    #pragma unroll
    for (int nf = 0; nf < 8; nf++) {
        const int d0 = nf * 8 + t4 * 2;
        *(float2*)&ctx[base + (size_t)r0 * DIM + d0] =
            make_float2(__uint_as_float(f2tf32(o[nf][0] * inv0)),
                        __uint_as_float(f2tf32(o[nf][1] * inv0)));
        *(float2*)&ctx[base + (size_t)(r0 + 8) * DIM + d0] =
            make_float2(__uint_as_float(f2tf32(o[nf][2] * inv1)),
                        __uint_as_float(f2tf32(o[nf][3] * inv1)));
    }
}

// ---------------- residual + LayerNorm ----------------
template<int TF>
__global__ void ln_residual_kernel(const float* __restrict__ a,
                                   const float* __restrict__ r,
                                   const float* __restrict__ gamma,
                                   const float* __restrict__ beta,
                                   float* __restrict__ out,
                                   float* __restrict__ out_t) {
    const int row = blockIdx.x;
    const int tid = threadIdx.x;
    const float* pa = a + (size_t)row * DIM;
    const float* pr = r + (size_t)row * DIM;

    float v[4];
    float sum = 0.0f, sq = 0.0f;
    #pragma unroll
    for (int i = 0; i < 4; i++) {
        int c = tid + i * 256;
        float t = pa[c] + pr[c];
        v[i] = t;
        sum += t;
        sq  += t * t;
    }
    #pragma unroll
    for (int off = 16; off >= 1; off >>= 1) {
        sum += __shfl_xor_sync(0xffffffffu, sum, off);
        sq  += __shfl_xor_sync(0xffffffffu, sq,  off);
    }
    __shared__ float ssum[8], ssq[8];
    int warp = tid >> 5, lane = tid & 31;
    if (lane == 0) { ssum[warp] = sum; ssq[warp] = sq; }
    __syncthreads();
    sum = 0.0f; sq = 0.0f;
    #pragma unroll
    for (int i = 0; i < 8; i++) { sum += ssum[i]; sq += ssq[i]; }

    const float invN = 1.0f / (float)DIM;
    float mu  = sum * invN;
    float var = fmaxf(sq * invN - mu * mu, 0.0f);
    float rstd = rsqrtf(var + 1e-12f);

    #pragma unroll
    for (int i = 0; i < 4; i++) {
        int c = tid + i * 256;
        float res = (v[i] - mu) * rstd * gamma[c] + beta[c];
        out[(size_t)row * DIM + c] = res;
        if (TF) out_t[(size_t)row * DIM + c] = __uint_as_float(f2tf32(res));
    }
}

// ---------------- launch ----------------
extern "C" void kernel_launch(void* const* d_in, const int* in_sizes, int n_in,
                              void* d_out, int out_size) {
    const float* x    = (const float*)d_in[0];
    const int*   mask = (const int*)  d_in[1];
    const float* Wq   = (const float*)d_in[2];
    const float* bq   = (const float*)d_in[3];
    const float* Wk   = (const float*)d_in[4];
    const float* bk   = (const float*)d_in[5];
    const float* Wv   = (const float*)d_in[6];
    const float* bv   = (const float*)d_in[7];
    const float* Wo   = (const float*)d_in[8];
    const float* bo   = (const float*)d_in[9];
    const float* ln1g = (const float*)d_in[10];
    const float* ln1b = (const float*)d_in[11];
    const float* W1   = (const float*)d_in[12];
    const float* b1   = (const float*)d_in[13];
    const float* W2   = (const float*)d_in[14];
    const float* b2   = (const float*)d_in[15];
    const float* ln2g = (const float*)d_in[16];
    const float* ln2b = (const float*)d_in[17];
    float* out = (float*)d_out;

    float *q, *k, *v, *ctx, *h1, *h1t, *ffn, *xt, *wqt, *wkt, *wvt, *wot, *w1t, *w2t;
    cudaGetSymbolAddress((void**)&q,   g_q);
    cudaGetSymbolAddress((void**)&k,   g_k);
    cudaGetSymbolAddress((void**)&v,   g_v);
    cudaGetSymbolAddress((void**)&ctx, g_ctx);
    cudaGetSymbolAddress((void**)&h1,  g_h1);
    cudaGetSymbolAddress((void**)&h1t, g_h1t);
    cudaGetSymbolAddress((void**)&ffn, g_ffn);
    cudaGetSymbolAddress((void**)&xt,  g_xt);
    cudaGetSymbolAddress((void**)&wqt, g_wqt);
    cudaGetSymbolAddress((void**)&wkt, g_wkt);
    cudaGetSymbolAddress((void**)&wvt, g_wvt);
    cudaGetSymbolAddress((void**)&wot, g_wot);
    cudaGetSymbolAddress((void**)&w1t, g_w1t);
    cudaGetSymbolAddress((void**)&w2t, g_w2t);

    cudaFuncSetAttribute(qkv_gemm,      cudaFuncAttributeMaxDynamicSharedMemorySize, GEMM_SMEM_BYTES);
    cudaFuncSetAttribute(gemm_cp<0,0>,  cudaFuncAttributeMaxDynamicSharedMemorySize, GEMM_SMEM_BYTES);
    cudaFuncSetAttribute(gemm_cp<1,1>,  cudaFuncAttributeMaxDynamicSharedMemorySize, GEMM_SMEM_BYTES);
    cudaFuncSetAttribute(attn_mma,      cudaFuncAttributeMaxDynamicSharedMemorySize, ATTN_SMEM_BYTES);

    // prep: x row-major cvt; weights transposed+cvt
    {
        const int thr = 256;
        cvt_tf32_kernel<<<(MROWS*DIM/4 + thr-1)/thr, thr>>>(x, xt, MROWS*DIM/4);
        dim3 tb(32, 8);
        transpose_tf32_kernel<<<dim3(DIM/32, DIM/32), tb>>>(Wq, wqt, DIM, DIM);
        transpose_tf32_kernel<<<dim3(DIM/32, DIM/32), tb>>>(Wk, wkt, DIM, DIM);
        transpose_tf32_kernel<<<dim3(DIM/32, DIM/32), tb>>>(Wv, wvt, DIM, DIM);
        transpose_tf32_kernel<<<dim3(DIM/32, DIM/32), tb>>>(Wo, wot, DIM, DIM);
        transpose_tf32_kernel<<<dim3(HID/32, DIM/32), tb>>>(W1, w1t, DIM, HID);
        transpose_tf32_kernel<<<dim3(DIM/32, HID/32), tb>>>(W2, w2t, HID, DIM);
    }

    // fused QKV (tf32 outputs)
    qkv_gemm<<<dim3(24, MROWS/128), 256, GEMM_SMEM_BYTES>>>(xt, wqt, wkt, wvt, bq, bk, bv, q, k, v);

    // attention
    attn_mma<<<dim3(SEQ/128, NH, BS), 256, ATTN_SMEM_BYTES>>>(q, k, v, mask, ctx);

    // output projection -> sa_out (fp32) in q
    gemm_cp<0,0><<<dim3(DIM/128, MROWS/128), 256, GEMM_SMEM_BYTES>>>(ctx, wot, bo, q, DIM, DIM);

    // LN1(sa_out + x) -> h1 (fp32) + h1t (tf32)
    ln_residual_kernel<1><<<MROWS, 256>>>(q, x, ln1g, ln1b, h1, h1t);

    // FFN
    gemm_cp<1,1><<<dim3(HID/128, MROWS/128), 256, GEMM_SMEM_BYTES>>>(h1t, w1t, b1, ffn, DIM, HID);
    gemm_cp<0,0><<<dim3(DIM/128, MROWS/128), 256, GEMM_SMEM_BYTES>>>(ffn, w2t, b2, k, HID, DIM);

    // LN2(ffn_out + h1) -> out
    ln_residual_kernel<0><<<MROWS, 256>>>(k, h1, ln2g, ln2b, out, nullptr);
}

// round 9
// speedup vs baseline: 3.7281x; 1.0559x over previous
#include <cuda_runtime.h>
#include <math.h>
#include <stdint.h>

#define BS   2
#define SEQ  2048
#define DIM  1024
#define HID  4096
#define NH   16
#define DPH  64
#define MROWS (BS*SEQ)   // 4096

// ---------------- scratch (no allocation allowed) ----------------
__device__ float g_q  [MROWS*DIM];
__device__ float g_k  [MROWS*DIM];
__device__ float g_v  [MROWS*DIM];
__device__ float g_ctx[MROWS*DIM];
__device__ float g_h1 [MROWS*DIM];
__device__ float g_h1t[MROWS*DIM];
__device__ float g_ffn[MROWS*HID];
__device__ float g_xt [MROWS*DIM];
__device__ float g_wqt[DIM*DIM];
__device__ float g_wkt[DIM*DIM];
__device__ float g_wvt[DIM*DIM];
__device__ float g_wot[DIM*DIM];
__device__ float g_w1t[DIM*HID];
__device__ float g_w2t[HID*DIM];

__device__ __forceinline__ uint32_t f2tf32(float f) {
    uint32_t r;
    asm("cvt.rna.tf32.f32 %0, %1;" : "=r"(r) : "f"(f));
    return r;
}
__device__ __forceinline__ uint32_t smem_u32(const void* p) {
    uint32_t a;
    asm("{ .reg .u64 t; cvta.to.shared.u64 t, %1; cvt.u32.u64 %0, t; }" : "=r"(a) : "l"(p));
    return a;
}
__device__ __forceinline__ void cp_async16(uint32_t dst, const void* src) {
    asm volatile("cp.async.cg.shared.global [%0], [%1], 16;" :: "r"(dst), "l"(src));
}
#define CP_COMMIT() asm volatile("cp.async.commit_group;" ::: "memory")
#define CP_WAIT(n)  asm volatile("cp.async.wait_group %0;" :: "n"(n) : "memory")

__device__ __forceinline__ void ldmatrix_x4(uint32_t& r0, uint32_t& r1, uint32_t& r2, uint32_t& r3,
                                            uint32_t addr) {
    asm volatile("ldmatrix.sync.aligned.m8n8.x4.shared.b16 {%0,%1,%2,%3}, [%4];"
        : "=r"(r0), "=r"(r1), "=r"(r2), "=r"(r3) : "r"(addr));
}

__device__ __forceinline__ void mma_tf32(float* d,
                                         uint32_t a0, uint32_t a1, uint32_t a2, uint32_t a3,
                                         uint32_t b0, uint32_t b1) {
    asm volatile(
        "mma.sync.aligned.m16n8k8.row.col.f32.tf32.tf32.f32 "
        "{%0,%1,%2,%3}, {%4,%5,%6,%7}, {%8,%9}, {%0,%1,%2,%3};"
        : "+f"(d[0]), "+f"(d[1]), "+f"(d[2]), "+f"(d[3])
        : "r"(a0), "r"(a1), "r"(a2), "r"(a3), "r"(b0), "r"(b1));
}

__device__ __forceinline__ float gelu_f(float x) {
    return 0.5f * x * (1.0f + erff(x * 0.70710678118654752f));
}

// ---------------- prep passes ----------------
__global__ void cvt_tf32_kernel(const float* __restrict__ in, float* __restrict__ out, int n4) {
    int i = blockIdx.x * blockDim.x + threadIdx.x;
    if (i < n4) {
        float4 v = ((const float4*)in)[i];
        uint4 u;
        u.x = f2tf32(v.x); u.y = f2tf32(v.y); u.z = f2tf32(v.z); u.w = f2tf32(v.w);
        ((uint4*)out)[i] = u;
    }
}

__global__ void transpose_tf32_kernel(const float* __restrict__ in, float* __restrict__ out,
                                      int R, int C) {
    __shared__ float tile[32][33];
    const int c0 = blockIdx.x * 32, r0 = blockIdx.y * 32;
    const int tx = threadIdx.x, ty = threadIdx.y;
    #pragma unroll
    for (int i = 0; i < 32; i += 8)
        tile[ty + i][tx] = in[(size_t)(r0 + ty + i) * C + c0 + tx];
    __syncthreads();
    #pragma unroll
    for (int i = 0; i < 32; i += 8)
        out[(size_t)(c0 + ty + i) * R + r0 + tx] = __uint_as_float(f2tf32(tile[tx][ty + i]));
}

// ---------------- tf32 GEMM (unchanged from R8, plus output scale) ----------------
#define GS 36
#define G_TILE_BYTES (128 * GS * 4)
#define G_STAGE_BYTES (2 * G_TILE_BYTES)
#define GEMM_SMEM_BYTES (3 * G_STAGE_BYTES)

template<int ACT, int TFOUT>
__device__ __forceinline__ void gemm_body(const float* __restrict__ A,
                                          const float* __restrict__ Wt,
                                          const float* __restrict__ bias,
                                          float* __restrict__ C,
                                          int K, int N, int m0, int n0, float oscale) {
    extern __shared__ uint32_t dsm[];
    const uint32_t sb = smem_u32(dsm);

    const int tid  = threadIdx.x;
    const int wid  = tid >> 5;
    const int lane = tid & 31;
    const int grp  = lane >> 2;
    const int t4   = lane & 3;
    const int ts   = lane >> 3;
    const int r8   = lane & 7;
    const int wm = (wid & 3) * 32;
    const int wn = (wid >> 2) * 64;

    const int lrow = tid >> 3;
    const int lcol = (tid & 7) * 4;

    const uint32_t a_loff = (uint32_t)((((ts & 1) * 8 + r8) * GS + (ts >> 1) * 4) * 4);
    const uint32_t b_loff = (uint32_t)((((ts >> 1) * 8 + r8) * GS + (ts & 1) * 4) * 4);

    float acc[2][8][4];
    #pragma unroll
    for (int i = 0; i < 2; i++)
        #pragma unroll
        for (int j = 0; j < 8; j++)
            #pragma unroll
            for (int c = 0; c < 4; c++) acc[i][j][c] = 0.0f;

    const int nit = K / 32;

    auto load_stage = [&](int s, int it) {
        const uint32_t base = sb + (uint32_t)s * G_STAGE_BYTES;
        const float* Ab = A  + (size_t)(m0 + lrow) * K + it * 32 + lcol;
        const float* Bb = Wt + (size_t)(n0 + lrow) * K + it * 32 + lcol;
        #pragma unroll
        for (int i = 0; i < 4; i++)
            cp_async16(base + (uint32_t)(((lrow + 32 * i) * GS + lcol) * 4), Ab + (size_t)(32 * i) * K);
        #pragma unroll
        for (int i = 0; i < 4; i++)
            cp_async16(base + G_TILE_BYTES + (uint32_t)(((lrow + 32 * i) * GS + lcol) * 4), Bb + (size_t)(32 * i) * K);
    };

    load_stage(0, 0);
    CP_COMMIT();
    load_stage(1, 1);
    CP_COMMIT();

    for (int it = 0; it < nit; it++) {
        const int s = it % 3;
        CP_WAIT(1);
        __syncthreads();
        if (it + 2 < nit) load_stage((it + 2) % 3, it + 2);
        CP_COMMIT();

        const uint32_t sA = sb + (uint32_t)s * G_STAGE_BYTES + (uint32_t)(wm * GS * 4) + a_loff;
        const uint32_t sB = sb + (uint32_t)s * G_STAGE_BYTES + G_TILE_BYTES + (uint32_t)(wn * GS * 4) + b_loff;
        #pragma unroll
        for (int kk = 0; kk < 4; kk++) {
            const uint32_t kb4 = kk * 32;
            uint32_t afr[2][4];
            #pragma unroll
            for (int mt = 0; mt < 2; mt++)
                ldmatrix_x4(afr[mt][0], afr[mt][1], afr[mt][2], afr[mt][3],
                            sA + (uint32_t)(mt * 16 * GS * 4) + kb4);
            uint32_t bfr[8][2];
            #pragma unroll
            for (int np = 0; np < 4; np++)
                ldmatrix_x4(bfr[2*np][0], bfr[2*np][1], bfr[2*np+1][0], bfr[2*np+1][1],
                            sB + (uint32_t)(np * 16 * GS * 4) + kb4);
            #pragma unroll
            for (int mt = 0; mt < 2; mt++)
                #pragma unroll
                for (int nt = 0; nt < 8; nt++)
                    mma_tf32(acc[mt][nt], afr[mt][0], afr[mt][1], afr[mt][2], afr[mt][3],
                             bfr[nt][0], bfr[nt][1]);
        }
    }

    #pragma unroll
    for (int mt = 0; mt < 2; mt++) {
        #pragma unroll
        for (int nt = 0; nt < 8; nt++) {
            const int col = n0 + wn + nt * 8 + t4 * 2;
            const float b0v = bias[col], b1v = bias[col + 1];
            const int r0 = m0 + wm + mt * 16 + grp;
            float v0 = (acc[mt][nt][0] + b0v) * oscale;
            float v1 = (acc[mt][nt][1] + b1v) * oscale;
            float v2 = (acc[mt][nt][2] + b0v) * oscale;
            float v3 = (acc[mt][nt][3] + b1v) * oscale;
            if (ACT == 1) { v0 = gelu_f(v0); v1 = gelu_f(v1); v2 = gelu_f(v2); v3 = gelu_f(v3); }
            if (TFOUT) {
                v0 = __uint_as_float(f2tf32(v0));
                v1 = __uint_as_float(f2tf32(v1));
                v2 = __uint_as_float(f2tf32(v2));
                v3 = __uint_as_float(f2tf32(v3));
            }
            *(float2*)&C[(size_t)r0 * N + col]       = make_float2(v0, v1);
            *(float2*)&C[(size_t)(r0 + 8) * N + col] = make_float2(v2, v3);
        }
    }
}

template<int ACT, int TFOUT>
__global__ void __launch_bounds__(256, 2)
gemm_cp(const float* __restrict__ A, const float* __restrict__ Wt,
        const float* __restrict__ bias, float* __restrict__ C, int K, int N) {
    gemm_body<ACT, TFOUT>(A, Wt, bias, C, K, N, blockIdx.y * 128, blockIdx.x * 128, 1.0f);
}

// fused QKV; q output pre-scaled by 0.125 (exact, commutes with tf32 rounding)
__global__ void __launch_bounds__(256, 2)
qkv_gemm(const float* __restrict__ xt,
         const float* __restrict__ wq, const float* __restrict__ wk, const float* __restrict__ wv,
         const float* __restrict__ bq, const float* __restrict__ bk, const float* __restrict__ bv,
         float* __restrict__ q, float* __restrict__ k, float* __restrict__ v) {
    const int sel = blockIdx.x >> 3;
    const float* W    = (sel == 0) ? wq : (sel == 1) ? wk : wv;
    const float* bias = (sel == 0) ? bq : (sel == 1) ? bk : bv;
    float*       C    = (sel == 0) ? q  : (sel == 1) ? k  : v;
    const float scale = (sel == 0) ? 0.125f : 1.0f;
    gemm_body<0, 1>(xt, W, bias, C, DIM, DIM, blockIdx.y * 128, (blockIdx.x & 7) * 128, scale);
}

// ---------------- Flash attention: Q in smem, P via shuffles, 2 CTAs/SM ----------------
#define KS_STRIDE 68
#define VS_STRIDE 72
#define AT_Q    (128 * KS_STRIDE)    // 8704 words
#define AT_KBUF (64 * KS_STRIDE)     // 4352 words
#define AT_VBUF (64 * VS_STRIDE)     // 4608 words
#define ATTN_SMEM_WORDS (AT_Q + 2 * AT_KBUF + 2 * AT_VBUF + 128)
#define ATTN_SMEM_BYTES (ATTN_SMEM_WORDS * 4)   // 107,520 B

__global__ void __launch_bounds__(256, 2)
attn_mma(const float* __restrict__ Q, const float* __restrict__ K,
         const float* __restrict__ V, const int* __restrict__ mask,
         float* __restrict__ ctx) {
    extern __shared__ uint32_t asm_[];
    uint32_t* Vsb[2] = { asm_ + AT_Q + 2 * AT_KBUF, asm_ + AT_Q + 2 * AT_KBUF + AT_VBUF };
    float* smaskb = (float*)(asm_ + AT_Q + 2 * AT_KBUF + 2 * AT_VBUF);
    const uint32_t sb = smem_u32(asm_);
    const uint32_t qoff = 0u;
    const uint32_t koff[2] = { (uint32_t)AT_Q * 4u, (uint32_t)(AT_Q + AT_KBUF) * 4u };
    const uint32_t voff[2] = { (uint32_t)(AT_Q + 2 * AT_KBUF) * 4u,
                               (uint32_t)(AT_Q + 2 * AT_KBUF + AT_VBUF) * 4u };

    const int tid  = threadIdx.x;
    const int wid  = tid >> 5;
    const int lane = tid & 31;
    const int grp  = lane >> 2;
    const int t4   = lane & 3;
    const int ts   = lane >> 3;
    const int r8   = lane & 7;
    const int w16  = wid * 16;
    const int q0 = blockIdx.x * 128;
    const int h  = blockIdx.y;
    const int b  = blockIdx.z;
    const size_t base = (size_t)b * SEQ * DIM + h * DPH;

    // A-fragment ldmatrix offset into Q (rows w16.., stride 68)
    const uint32_t q_loff = (uint32_t)(((w16 + (ts & 1) * 8 + r8) * KS_STRIDE + (ts >> 1) * 4) * 4);
    // B-fragment ldmatrix offset into K (stride 68)
    const uint32_t k_loff = (uint32_t)((((ts >> 1) * 8 + r8) * KS_STRIDE + (ts & 1) * 4) * 4);

    const int lrow = tid >> 4;          // 0..15
    const int lc = (tid & 15) * 4;

    float o[8][4];
    #pragma unroll
    for (int nf = 0; nf < 8; nf++)
        #pragma unroll
        for (int c = 0; c < 4; c++) o[nf][c] = 0.0f;
    float mrow0 = -INFINITY, mrow1 = -INFINITY;
    float l0 = 0.0f, l1 = 0.0f;

    // prologue: Q tile (128x64) + K/V tile 0, one commit group
    {
        #pragma unroll
        for (int i = 0; i < 8; i++) {
            int row = lrow + 16 * i;
            cp_async16(sb + qoff + (uint32_t)((row * KS_STRIDE + lc) * 4),
                       Q + base + (size_t)(q0 + row) * DIM + lc);
        }
        #pragma unroll
        for (int i = 0; i < 4; i++) {
            size_t g = base + (size_t)(lrow + 16 * i) * DIM + lc;
            cp_async16(sb + koff[0] + (uint32_t)(((lrow + 16 * i) * KS_STRIDE + lc) * 4), K + g);
            cp_async16(sb + voff[0] + (uint32_t)(((lrow + 16 * i) * VS_STRIDE + lc) * 4), V + g);
        }
        CP_COMMIT();
        if (tid < 64)
            smaskb[tid] = (mask[b * SEQ + tid] == 0) ? -INFINITY : 0.0f;
    }

    const int nt_tiles = SEQ / 64;
    for (int it = 0; it < nt_tiles; it++) {
        const int buf = it & 1;
        const int kv_next = (it + 1) * 64;
        if (it + 1 < nt_tiles) {
            #pragma unroll
            for (int i = 0; i < 4; i++) {
                size_t g = base + (size_t)(kv_next + lrow + 16 * i) * DIM + lc;
                cp_async16(sb + koff[buf ^ 1] + (uint32_t)(((lrow + 16 * i) * KS_STRIDE + lc) * 4), K + g);
                cp_async16(sb + voff[buf ^ 1] + (uint32_t)(((lrow + 16 * i) * VS_STRIDE + lc) * 4), V + g);
            }
            CP_COMMIT();
            if (tid < 64)
                smaskb[(buf ^ 1) * 64 + tid] = (mask[b * SEQ + kv_next + tid] == 0) ? -INFINITY : 0.0f;
            CP_WAIT(1);
        } else {
            CP_WAIT(0);
        }
        __syncthreads();

        const uint32_t sbK = sb + koff[buf] + k_loff;
        const uint32_t* Vs = Vsb[buf];
        const float* smask = smaskb + buf * 64;

        // S = Q K^T ; Q fragments re-loaded from smem per k-step
        float s[8][4];
        #pragma unroll
        for (int nf = 0; nf < 8; nf++)
            #pragma unroll
            for (int c = 0; c < 4; c++) s[nf][c] = 0.0f;
        #pragma unroll
        for (int k = 0; k < 8; k++) {
            const uint32_t kb4 = k * 32;
            uint32_t qa0, qa1, qa2, qa3;
            ldmatrix_x4(qa0, qa1, qa2, qa3, sb + qoff + q_loff + kb4);
            #pragma unroll
            for (int np = 0; np < 4; np++) {
                uint32_t b00, b01, b10, b11;
                ldmatrix_x4(b00, b01, b10, b11,
                            sbK + (uint32_t)(np * 16 * KS_STRIDE * 4) + kb4);
                mma_tf32(s[2*np],   qa0, qa1, qa2, qa3, b00, b01);
                mma_tf32(s[2*np+1], qa0, qa1, qa2, qa3, b10, b11);
            }
        }

        #pragma unroll
        for (int nf = 0; nf < 8; nf++) {
            float mv0 = smask[nf * 8 + t4 * 2];
            float mv1 = smask[nf * 8 + t4 * 2 + 1];
            s[nf][0] += mv0; s[nf][1] += mv1;
            s[nf][2] += mv0; s[nf][3] += mv1;
        }

        float mt0 = -INFINITY, mt1 = -INFINITY;
        #pragma unroll
        for (int nf = 0; nf < 8; nf++) {
            mt0 = fmaxf(mt0, fmaxf(s[nf][0], s[nf][1]));
            mt1 = fmaxf(mt1, fmaxf(s[nf][2], s[nf][3]));
        }
        mt0 = fmaxf(mt0, __shfl_xor_sync(0xffffffffu, mt0, 1));
        mt0 = fmaxf(mt0, __shfl_xor_sync(0xffffffffu, mt0, 2));
        mt1 = fmaxf(mt1, __shfl_xor_sync(0xffffffffu, mt1, 1));
        mt1 = fmaxf(mt1, __shfl_xor_sync(0xffffffffu, mt1, 2));
        float mnew0 = fmaxf(mrow0, mt0);
        float mnew1 = fmaxf(mrow1, mt1);
        float alpha0 = __expf(mrow0 - mnew0);
        float alpha1 = __expf(mrow1 - mnew1);
        float lsum0 = 0.0f, lsum1 = 0.0f;
        #pragma unroll
        for (int nf = 0; nf < 8; nf++) {
            s[nf][0] = __expf(s[nf][0] - mnew0);
            s[nf][1] = __expf(s[nf][1] - mnew0);
            s[nf][2] = __expf(s[nf][2] - mnew1);
            s[nf][3] = __expf(s[nf][3] - mnew1);
            lsum0 += s[nf][0] + s[nf][1];
            lsum1 += s[nf][2] + s[nf][3];
        }
        lsum0 += __shfl_xor_sync(0xffffffffu, lsum0, 1);
        lsum0 += __shfl_xor_sync(0xffffffffu, lsum0, 2);
        lsum1 += __shfl_xor_sync(0xffffffffu, lsum1, 1);
        lsum1 += __shfl_xor_sync(0xffffffffu, lsum1, 2);
        l0 = l0 * alpha0 + lsum0;
        l1 = l1 * alpha1 + lsum1;
        mrow0 = mnew0; mrow1 = mnew1;
        #pragma unroll
        for (int nf = 0; nf < 8; nf++) {
            o[nf][0] *= alpha0; o[nf][1] *= alpha0;
            o[nf][2] *= alpha1; o[nf][3] *= alpha1;
        }

        // round P to tf32 in-place (same rounding point as smem path)
        uint32_t su[8][4];
        #pragma unroll
        for (int nf = 0; nf < 8; nf++) {
            su[nf][0] = f2tf32(s[nf][0]);
            su[nf][1] = f2tf32(s[nf][1]);
            su[nf][2] = f2tf32(s[nf][2]);
            su[nf][3] = f2tf32(s[nf][3]);
        }

        // O += P @ V : A-fragments of P built via quad shuffles
        const int sl0 = 4 * grp + (t4 >> 1);
        const int sl2 = sl0 + 2;
        const bool hi = (t4 & 1);
        #pragma unroll
        for (int k = 0; k < 8; k++) {
            uint32_t v00 = __shfl_sync(0xffffffffu, su[k][0], sl0);
            uint32_t v01 = __shfl_sync(0xffffffffu, su[k][1], sl0);
            uint32_t a0 = hi ? v01 : v00;
            uint32_t v20 = __shfl_sync(0xffffffffu, su[k][0], sl2);
            uint32_t v21 = __shfl_sync(0xffffffffu, su[k][1], sl2);
            uint32_t a2 = hi ? v21 : v20;
            uint32_t v10 = __shfl_sync(0xffffffffu, su[k][2], sl0);
            uint32_t v11 = __shfl_sync(0xffffffffu, su[k][3], sl0);
            uint32_t a1 = hi ? v11 : v10;
            uint32_t v30 = __shfl_sync(0xffffffffu, su[k][2], sl2);
            uint32_t v31 = __shfl_sync(0xffffffffu, su[k][3], sl2);
            uint32_t a3 = hi ? v31 : v30;
            const int kb = k * 8;
            #pragma unroll
            for (int nf = 0; nf < 8; nf++) {
                uint32_t b0 = Vs[(kb + t4)     * VS_STRIDE + nf * 8 + grp];
                uint32_t b1 = Vs[(kb + t4 + 4) * VS_STRIDE + nf * 8 + grp];
                mma_tf32(o[nf], a0, a1, a2, a3, b0, b1);
            }
        }
        __syncthreads();
    }

    const float inv0 = 1.0f / l0;
    const float inv1 = 1.0f / l1;
    const int r0 = q0 + w16 + grp;
    #pragma unroll
    for (int nf = 0; nf < 8; nf++) {
        const int d0 = nf * 8 + t4 * 2;
        *(float2*)&ctx[base + (size_t)r0 * DIM + d0] =
            make_float2(__uint_as_float(f2tf32(o[nf][0] * inv0)),
                        __uint_as_float(f2tf32(o[nf][1] * inv0)));
        *(float2*)&ctx[base + (size_t)(r0 + 8) * DIM + d0] =
            make_float2(__uint_as_float(f2tf32(o[nf][2] * inv1)),
                        __uint_as_float(f2tf32(o[nf][3] * inv1)));
    }
}

// ---------------- residual + LayerNorm ----------------
template<int TF>
__global__ void ln_residual_kernel(const float* __restrict__ a,
                                   const float* __restrict__ r,
                                   const float* __restrict__ gamma,
                                   const float* __restrict__ beta,
                                   float* __restrict__ out,
                                   float* __restrict__ out_t) {
    const int row = blockIdx.x;
    const int tid = threadIdx.x;
    const float* pa = a + (size_t)row * DIM;
    const float* pr = r + (size_t)row * DIM;

    float v[4];
    float sum = 0.0f, sq = 0.0f;
    #pragma unroll
    for (int i = 0; i < 4; i++) {
        int c = tid + i * 256;
        float t = pa[c] + pr[c];
        v[i] = t;
        sum += t;
        sq  += t * t;
    }
    #pragma unroll
    for (int off = 16; off >= 1; off >>= 1) {
        sum += __shfl_xor_sync(0xffffffffu, sum, off);
        sq  += __shfl_xor_sync(0xffffffffu, sq,  off);
    }
    __shared__ float ssum[8], ssq[8];
    int warp = tid >> 5, lane = tid & 31;
    if (lane == 0) { ssum[warp] = sum; ssq[warp] = sq; }
    __syncthreads();
    sum = 0.0f; sq = 0.0f;
    #pragma unroll
    for (int i = 0; i < 8; i++) { sum += ssum[i]; sq += ssq[i]; }

    const float invN = 1.0f / (float)DIM;
    float mu  = sum * invN;
    float var = fmaxf(sq * invN - mu * mu, 0.0f);
    float rstd = rsqrtf(var + 1e-12f);

    #pragma unroll
    for (int i = 0; i < 4; i++) {
        int c = tid + i * 256;
        float res = (v[i] - mu) * rstd * gamma[c] + beta[c];
        out[(size_t)row * DIM + c] = res;
        if (TF) out_t[(size_t)row * DIM + c] = __uint_as_float(f2tf32(res));
    }
}

// ---------------- launch ----------------
extern "C" void kernel_launch(void* const* d_in, const int* in_sizes, int n_in,
                              void* d_out, int out_size) {
    const float* x    = (const float*)d_in[0];
    const int*   mask = (const int*)  d_in[1];
    const float* Wq   = (const float*)d_in[2];
    const float* bq   = (const float*)d_in[3];
    const float* Wk   = (const float*)d_in[4];
    const float* bk   = (const float*)d_in[5];
    const float* Wv   = (const float*)d_in[6];
    const float* bv   = (const float*)d_in[7];
    const float* Wo   = (const float*)d_in[8];
    const float* bo   = (const float*)d_in[9];
    const float* ln1g = (const float*)d_in[10];
    const float* ln1b = (const float*)d_in[11];
    const float* W1   = (const float*)d_in[12];
    const float* b1   = (const float*)d_in[13];
    const float* W2   = (const float*)d_in[14];
    const float* b2   = (const float*)d_in[15];
    const float* ln2g = (const float*)d_in[16];
    const float* ln2b = (const float*)d_in[17];
    float* out = (float*)d_out;

    float *q, *k, *v, *ctx, *h1, *h1t, *ffn, *xt, *wqt, *wkt, *wvt, *wot, *w1t, *w2t;
    cudaGetSymbolAddress((void**)&q,   g_q);
    cudaGetSymbolAddress((void**)&k,   g_k);
    cudaGetSymbolAddress((void**)&v,   g_v);
    cudaGetSymbolAddress((void**)&ctx, g_ctx);
    cudaGetSymbolAddress((void**)&h1,  g_h1);
    cudaGetSymbolAddress((void**)&h1t, g_h1t);
    cudaGetSymbolAddress((void**)&ffn, g_ffn);
    cudaGetSymbolAddress((void**)&xt,  g_xt);
    cudaGetSymbolAddress((void**)&wqt, g_wqt);
    cudaGetSymbolAddress((void**)&wkt, g_wkt);
    cudaGetSymbolAddress((void**)&wvt, g_wvt);
    cudaGetSymbolAddress((void**)&wot, g_wot);
    cudaGetSymbolAddress((void**)&w1t, g_w1t);
    cudaGetSymbolAddress((void**)&w2t, g_w2t);

    cudaFuncSetAttribute(qkv_gemm,      cudaFuncAttributeMaxDynamicSharedMemorySize, GEMM_SMEM_BYTES);
    cudaFuncSetAttribute(gemm_cp<0,0>,  cudaFuncAttributeMaxDynamicSharedMemorySize, GEMM_SMEM_BYTES);
    cudaFuncSetAttribute(gemm_cp<1,1>,  cudaFuncAttributeMaxDynamicSharedMemorySize, GEMM_SMEM_BYTES);
    cudaFuncSetAttribute(attn_mma,      cudaFuncAttributeMaxDynamicSharedMemorySize, ATTN_SMEM_BYTES);

    {
        const int thr = 256;
        cvt_tf32_kernel<<<(MROWS*DIM/4 + thr-1)/thr, thr>>>(x, xt, MROWS*DIM/4);
        dim3 tb(32, 8);
        transpose_tf32_kernel<<<dim3(DIM/32, DIM/32), tb>>>(Wq, wqt, DIM, DIM);
        transpose_tf32_kernel<<<dim3(DIM/32, DIM/32), tb>>>(Wk, wkt, DIM, DIM);
        transpose_tf32_kernel<<<dim3(DIM/32, DIM/32), tb>>>(Wv, wvt, DIM, DIM);
        transpose_tf32_kernel<<<dim3(DIM/32, DIM/32), tb>>>(Wo, wot, DIM, DIM);
        transpose_tf32_kernel<<<dim3(HID/32, DIM/32), tb>>>(W1, w1t, DIM, HID);
        transpose_tf32_kernel<<<dim3(DIM/32, HID/32), tb>>>(W2, w2t, HID, DIM);
    }

    qkv_gemm<<<dim3(24, MROWS/128), 256, GEMM_SMEM_BYTES>>>(xt, wqt, wkt, wvt, bq, bk, bv, q, k, v);

    attn_mma<<<dim3(SEQ/128, NH, BS), 256, ATTN_SMEM_BYTES>>>(q, k, v, mask, ctx);

    gemm_cp<0,0><<<dim3(DIM/128, MROWS/128), 256, GEMM_SMEM_BYTES>>>(ctx, wot, bo, q, DIM, DIM);

    ln_residual_kernel<1><<<MROWS, 256>>>(q, x, ln1g, ln1b, h1, h1t);

    gemm_cp<1,1><<<dim3(HID/128, MROWS/128), 256, GEMM_SMEM_BYTES>>>(h1t, w1t, b1, ffn, DIM, HID);
    gemm_cp<0,0><<<dim3(DIM/128, MROWS/128), 256, GEMM_SMEM_BYTES>>>(ffn, w2t, b2, k, HID, DIM);

    ln_residual_kernel<0><<<MROWS, 256>>>(k, h1, ln2g, ln2b, out, nullptr);
}

// round 10
// speedup vs baseline: 7.1500x; 1.9179x over previous
#include <cuda_runtime.h>
#include <cuda_fp16.h>
#include <math.h>
#include <stdint.h>

#define BS   2
#define SEQ  2048
#define DIM  1024
#define HID  4096
#define NH   16
#define DPH  64
#define MROWS (BS*SEQ)   // 4096

// ---------------- scratch (no allocation allowed) ----------------
__device__ __half g_q  [MROWS*DIM];
__device__ __half g_k  [MROWS*DIM];
__device__ __half g_v  [MROWS*DIM];
__device__ __half g_ctx[MROWS*DIM];
__device__ __half g_h1t[MROWS*DIM];
__device__ __half g_ffn[MROWS*HID];
__device__ __half g_xt [MROWS*DIM];
__device__ __half g_wqt[DIM*DIM];
__device__ __half g_wkt[DIM*DIM];
__device__ __half g_wvt[DIM*DIM];
__device__ __half g_wot[DIM*DIM];
__device__ __half g_w1t[DIM*HID];
__device__ __half g_w2t[HID*DIM];
__device__ float  g_sa [MROWS*DIM];
__device__ float  g_h1 [MROWS*DIM];
__device__ float  g_f2 [MROWS*DIM];

__device__ __forceinline__ uint32_t smem_u32(const void* p) {
    uint32_t a;
    asm("{ .reg .u64 t; cvta.to.shared.u64 t, %1; cvt.u32.u64 %0, t; }" : "=r"(a) : "l"(p));
    return a;
}
__device__ __forceinline__ void cp_async16(uint32_t dst, const void* src) {
    asm volatile("cp.async.cg.shared.global [%0], [%1], 16;" :: "r"(dst), "l"(src));
}
#define CP_COMMIT() asm volatile("cp.async.commit_group;" ::: "memory")
#define CP_WAIT(n)  asm volatile("cp.async.wait_group %0;" :: "n"(n) : "memory")

__device__ __forceinline__ void ldmatrix_x4(uint32_t& r0, uint32_t& r1, uint32_t& r2, uint32_t& r3,
                                            uint32_t addr) {
    asm volatile("ldmatrix.sync.aligned.m8n8.x4.shared.b16 {%0,%1,%2,%3}, [%4];"
        : "=r"(r0), "=r"(r1), "=r"(r2), "=r"(r3) : "r"(addr));
}
__device__ __forceinline__ void ldmatrix_x4_trans(uint32_t& r0, uint32_t& r1, uint32_t& r2, uint32_t& r3,
                                                  uint32_t addr) {
    asm volatile("ldmatrix.sync.aligned.m8n8.x4.trans.shared.b16 {%0,%1,%2,%3}, [%4];"
        : "=r"(r0), "=r"(r1), "=r"(r2), "=r"(r3) : "r"(addr));
}

__device__ __forceinline__ void mma_f16(float* d,
                                        uint32_t a0, uint32_t a1, uint32_t a2, uint32_t a3,
                                        uint32_t b0, uint32_t b1) {
    asm volatile(
        "mma.sync.aligned.m16n8k16.row.col.f32.f16.f16.f32 "
        "{%0,%1,%2,%3}, {%4,%5,%6,%7}, {%8,%9}, {%0,%1,%2,%3};"
        : "+f"(d[0]), "+f"(d[1]), "+f"(d[2]), "+f"(d[3])
        : "r"(a0), "r"(a1), "r"(a2), "r"(a3), "r"(b0), "r"(b1));
}

__device__ __forceinline__ uint32_t pack_h2(float a, float b) {
    __half2 h = __floats2half2_rn(a, b);
    return *(uint32_t*)&h;
}

__device__ __forceinline__ float gelu_f(float x) {
    return 0.5f * x * (1.0f + erff(x * 0.70710678118654752f));
}

// ---------------- prep passes ----------------
__global__ void cvt_h_kernel(const float* __restrict__ in, __half* __restrict__ out, int n4) {
    int i = blockIdx.x * blockDim.x + threadIdx.x;
    if (i < n4) {
        float4 v = ((const float4*)in)[i];
        uint2 u;
        u.x = pack_h2(v.x, v.y);
        u.y = pack_h2(v.z, v.w);
        ((uint2*)out)[i] = u;
    }
}

__global__ void transpose_h_kernel(const float* __restrict__ in, __half* __restrict__ out,
                                   int R, int C) {
    __shared__ float tile[32][33];
    const int c0 = blockIdx.x * 32, r0 = blockIdx.y * 32;
    const int tx = threadIdx.x, ty = threadIdx.y;
    #pragma unroll
    for (int i = 0; i < 32; i += 8)
        tile[ty + i][tx] = in[(size_t)(r0 + ty + i) * C + c0 + tx];
    __syncthreads();
    #pragma unroll
    for (int i = 0; i < 32; i += 8)
        out[(size_t)(c0 + ty + i) * R + r0 + tx] = __float2half_rn(tile[tx][ty + i]);
}

// ---------------- fp16 GEMM: CTA 128x128, BK=64, 3-stage cp.async ----------------
#define AS 72                                   // halves per row
#define G_TILE_BYTES (128 * AS * 2)             // 18432
#define G_STAGE_BYTES (2 * G_TILE_BYTES)        // 36864
#define GEMM_SMEM_BYTES (3 * G_STAGE_BYTES)     // 110592

template<int ACT, int HOUT>
__device__ __forceinline__ void gemm_body(const __half* __restrict__ A,
                                          const __half* __restrict__ Wt,
                                          const float* __restrict__ bias,
                                          void* __restrict__ Cv,
                                          int K, int N, int m0, int n0, float oscale) {
    extern __shared__ uint32_t dsm[];
    const uint32_t sb = smem_u32(dsm);

    const int tid  = threadIdx.x;
    const int lane = tid & 31;
    const int wid  = tid >> 5;
    const int grp  = lane >> 2;
    const int t4   = lane & 3;
    const int ts   = lane >> 3;
    const int r8   = lane & 7;
    const int wm = (wid & 3) * 32;
    const int wn = (wid >> 2) * 64;

    // A/B fragment ldmatrix lane offsets (bytes)
    const uint32_t a_loff = (uint32_t)((((ts & 1) * 8 + r8) * AS) * 2 + (ts >> 1) * 16);
    const uint32_t b_loff = (uint32_t)((((ts >> 1) * 8 + r8) * AS) * 2 + (ts & 1) * 16);

    float acc[2][8][4];
    #pragma unroll
    for (int i = 0; i < 2; i++)
        #pragma unroll
        for (int j = 0; j < 8; j++)
            #pragma unroll
            for (int c = 0; c < 4; c++) acc[i][j][c] = 0.0f;

    const int nit = K / 64;

    auto load_stage = [&](int s, int it) {
        const uint32_t base = sb + (uint32_t)s * G_STAGE_BYTES;
        #pragma unroll
        for (int j = 0; j < 4; j++) {
            int idx = tid + j * 256;
            int row = idx >> 3, c = idx & 7;
            cp_async16(base + (uint32_t)(row * AS * 2 + c * 16),
                       A + (size_t)(m0 + row) * K + it * 64 + c * 8);
        }
        #pragma unroll
        for (int j = 0; j < 4; j++) {
            int idx = tid + j * 256;
            int row = idx >> 3, c = idx & 7;
            cp_async16(base + G_TILE_BYTES + (uint32_t)(row * AS * 2 + c * 16),
                       Wt + (size_t)(n0 + row) * K + it * 64 + c * 8);
        }
    };

    load_stage(0, 0);
    CP_COMMIT();
    if (nit > 1) { load_stage(1, 1); }
    CP_COMMIT();

    for (int it = 0; it < nit; it++) {
        const int s = it % 3;
        CP_WAIT(1);
        __syncthreads();
        if (it + 2 < nit) load_stage((it + 2) % 3, it + 2);
        CP_COMMIT();

        const uint32_t sA = sb + (uint32_t)s * G_STAGE_BYTES + (uint32_t)(wm * AS * 2) + a_loff;
        const uint32_t sB = sb + (uint32_t)s * G_STAGE_BYTES + G_TILE_BYTES + (uint32_t)(wn * AS * 2) + b_loff;
        #pragma unroll
        for (int kk = 0; kk < 4; kk++) {
            const uint32_t kb = kk * 32;          // 16 halves
            uint32_t afr[2][4];
            #pragma unroll
            for (int mt = 0; mt < 2; mt++)
                ldmatrix_x4(afr[mt][0], afr[mt][1], afr[mt][2], afr[mt][3],
                            sA + (uint32_t)(mt * 16 * AS * 2) + kb);
            uint32_t bfr[8][2];
            #pragma unroll
            for (int np = 0; np < 4; np++)
                ldmatrix_x4(bfr[2*np][0], bfr[2*np][1], bfr[2*np+1][0], bfr[2*np+1][1],
                            sB + (uint32_t)(np * 16 * AS * 2) + kb);
            #pragma unroll
            for (int mt = 0; mt < 2; mt++)
                #pragma unroll
                for (int nt = 0; nt < 8; nt++)
                    mma_f16(acc[mt][nt], afr[mt][0], afr[mt][1], afr[mt][2], afr[mt][3],
                            bfr[nt][0], bfr[nt][1]);
        }
    }

    #pragma unroll
    for (int mt = 0; mt < 2; mt++) {
        #pragma unroll
        for (int nt = 0; nt < 8; nt++) {
            const int col = n0 + wn + nt * 8 + t4 * 2;
            const float b0v = bias[col], b1v = bias[col + 1];
            const int r0 = m0 + wm + mt * 16 + grp;
            float v0 = (acc[mt][nt][0] + b0v) * oscale;
            float v1 = (acc[mt][nt][1] + b1v) * oscale;
            float v2 = (acc[mt][nt][2] + b0v) * oscale;
            float v3 = (acc[mt][nt][3] + b1v) * oscale;
            if (ACT == 1) { v0 = gelu_f(v0); v1 = gelu_f(v1); v2 = gelu_f(v2); v3 = gelu_f(v3); }
            if (HOUT) {
                __half* Ch = (__half*)Cv;
                *(uint32_t*)&Ch[(size_t)r0 * N + col]       = pack_h2(v0, v1);
                *(uint32_t*)&Ch[(size_t)(r0 + 8) * N + col] = pack_h2(v2, v3);
            } else {
                float* Cf = (float*)Cv;
                *(float2*)&Cf[(size_t)r0 * N + col]       = make_float2(v0, v1);
                *(float2*)&Cf[(size_t)(r0 + 8) * N + col] = make_float2(v2, v3);
            }
        }
    }
}

template<int ACT, int HOUT>
__global__ void __launch_bounds__(256, 2)
gemm_cp(const __half* __restrict__ A, const __half* __restrict__ Wt,
        const float* __restrict__ bias, void* __restrict__ C, int K, int N) {
    gemm_body<ACT, HOUT>(A, Wt, bias, C, K, N, blockIdx.y * 128, blockIdx.x * 128, 1.0f);
}

__global__ void __launch_bounds__(256, 2)
qkv_gemm(const __half* __restrict__ xt,
         const __half* __restrict__ wq, const __half* __restrict__ wk, const __half* __restrict__ wv,
         const float* __restrict__ bq, const float* __restrict__ bk, const float* __restrict__ bv,
         __half* __restrict__ q, __half* __restrict__ k, __half* __restrict__ v) {
    const int sel = blockIdx.x >> 3;
    const __half* W   = (sel == 0) ? wq : (sel == 1) ? wk : wv;
    const float* bias = (sel == 0) ? bq : (sel == 1) ? bk : bv;
    __half*      C    = (sel == 0) ? q  : (sel == 1) ? k  : v;
    const float scale = (sel == 0) ? 0.125f : 1.0f;
    gemm_body<0, 1>(xt, W, bias, C, DIM, DIM, blockIdx.y * 128, (blockIdx.x & 7) * 128, scale);
}

// ---------------- fp16 flash attention ----------------
#define HS 72
#define AT_Q (128 * HS)    // halves
#define AT_T (64 * HS)
#define ATTN_SMEM_BYTES ((AT_Q + 4 * AT_T) * 2 + 512)   // 55808

__global__ void __launch_bounds__(256, 2)
attn_mma(const __half* __restrict__ Q, const __half* __restrict__ K,
         const __half* __restrict__ V, const int* __restrict__ mask,
         __half* __restrict__ ctx) {
    extern __shared__ uint32_t asm_[];
    const uint32_t sb = smem_u32(asm_);
    const uint32_t qoff = 0u;
    const uint32_t koff[2] = { (uint32_t)AT_Q * 2u, (uint32_t)(AT_Q + AT_T) * 2u };
    const uint32_t voff[2] = { (uint32_t)(AT_Q + 2 * AT_T) * 2u, (uint32_t)(AT_Q + 3 * AT_T) * 2u };
    float* smaskb = (float*)((char*)asm_ + (AT_Q + 4 * AT_T) * 2);

    const int tid  = threadIdx.x;
    const int lane = tid & 31;
    const int wid  = tid >> 5;
    const int grp  = lane >> 2;
    const int t4   = lane & 3;
    const int ts   = lane >> 3;
    const int r8   = lane & 7;
    const int w16  = wid * 16;
    const int q0 = blockIdx.x * 128;
    const int h  = blockIdx.y;
    const int b  = blockIdx.z;
    const size_t base = (size_t)b * SEQ * DIM + h * DPH;

    const uint32_t q_loff = (uint32_t)(((w16 + (ts & 1) * 8 + r8) * HS) * 2 + (ts >> 1) * 16);
    const uint32_t k_loff = (uint32_t)((((ts >> 1) * 8 + r8) * HS) * 2 + (ts & 1) * 16);
    const uint32_t v_loff = (uint32_t)((((ts & 1) * 8 + r8) * HS) * 2 + (ts >> 1) * 16);

    float o[8][4];
    #pragma unroll
    for (int nf = 0; nf < 8; nf++)
        #pragma unroll
        for (int c = 0; c < 4; c++) o[nf][c] = 0.0f;
    float mrow0 = -INFINITY, mrow1 = -INFINITY;
    float l0 = 0.0f, l1 = 0.0f;

    // prologue: Q (128x64) + K/V tile 0
    {
        #pragma unroll
        for (int j = 0; j < 4; j++) {
            int idx = tid + j * 256;
            int row = idx >> 3, c = idx & 7;
            cp_async16(sb + qoff + (uint32_t)(row * HS * 2 + c * 16),
                       Q + base + (size_t)(q0 + row) * DIM + c * 8);
        }
        #pragma unroll
        for (int j = 0; j < 2; j++) {
            int idx = tid + j * 256;
            int row = idx >> 3, c = idx & 7;
            size_t g = base + (size_t)row * DIM + c * 8;
            cp_async16(sb + koff[0] + (uint32_t)(row * HS * 2 + c * 16), K + g);
            cp_async16(sb + voff[0] + (uint32_t)(row * HS * 2 + c * 16), V + g);
        }
        CP_COMMIT();
        if (tid < 64)
            smaskb[tid] = (mask[b * SEQ + tid] == 0) ? -INFINITY : 0.0f;
    }

    const int nt_tiles = SEQ / 64;
    for (int it = 0; it < nt_tiles; it++) {
        const int buf = it & 1;
        const int kv_next = (it + 1) * 64;
        if (it + 1 < nt_tiles) {
            #pragma unroll
            for (int j = 0; j < 2; j++) {
                int idx = tid + j * 256;
                int row = idx >> 3, c = idx & 7;
                size_t g = base + (size_t)(kv_next + row) * DIM + c * 8;
                cp_async16(sb + koff[buf ^ 1] + (uint32_t)(row * HS * 2 + c * 16), K + g);
                cp_async16(sb + voff[buf ^ 1] + (uint32_t)(row * HS * 2 + c * 16), V + g);
            }
            CP_COMMIT();
            if (tid < 64)
                smaskb[(buf ^ 1) * 64 + tid] = (mask[b * SEQ + kv_next + tid] == 0) ? -INFINITY : 0.0f;
            CP_WAIT(1);
        } else {
            CP_WAIT(0);
        }
        __syncthreads();

        const uint32_t sbK = sb + koff[buf] + k_loff;
        const uint32_t sbV = sb + voff[buf] + v_loff;
        const float* smask = smaskb + buf * 64;

        // S = Q K^T (4 k-steps over d=64)
        float s[8][4];
        #pragma unroll
        for (int nf = 0; nf < 8; nf++)
            #pragma unroll
            for (int c = 0; c < 4; c++) s[nf][c] = 0.0f;
        #pragma unroll
        for (int kk = 0; kk < 4; kk++) {
            const uint32_t kb = kk * 32;
            uint32_t qa0, qa1, qa2, qa3;
            ldmatrix_x4(qa0, qa1, qa2, qa3, sb + qoff + q_loff + kb);
            #pragma unroll
            for (int np = 0; np < 4; np++) {
                uint32_t b00, b01, b10, b11;
                ldmatrix_x4(b00, b01, b10, b11,
                            sbK + (uint32_t)(np * 16 * HS * 2) + kb);
                mma_f16(s[2*np],   qa0, qa1, qa2, qa3, b00, b01);
                mma_f16(s[2*np+1], qa0, qa1, qa2, qa3, b10, b11);
            }
        }

        #pragma unroll
        for (int nf = 0; nf < 8; nf++) {
            float mv0 = smask[nf * 8 + t4 * 2];
            float mv1 = smask[nf * 8 + t4 * 2 + 1];
            s[nf][0] += mv0; s[nf][1] += mv1;
            s[nf][2] += mv0; s[nf][3] += mv1;
        }

        float mt0 = -INFINITY, mt1 = -INFINITY;
        #pragma unroll
        for (int nf = 0; nf < 8; nf++) {
            mt0 = fmaxf(mt0, fmaxf(s[nf][0], s[nf][1]));
            mt1 = fmaxf(mt1, fmaxf(s[nf][2], s[nf][3]));
        }
        mt0 = fmaxf(mt0, __shfl_xor_sync(0xffffffffu, mt0, 1));
        mt0 = fmaxf(mt0, __shfl_xor_sync(0xffffffffu, mt0, 2));
        mt1 = fmaxf(mt1, __shfl_xor_sync(0xffffffffu, mt1, 1));
        mt1 = fmaxf(mt1, __shfl_xor_sync(0xffffffffu, mt1, 2));
        float mnew0 = fmaxf(mrow0, mt0);
        float mnew1 = fmaxf(mrow1, mt1);
        float alpha0 = __expf(mrow0 - mnew0);
        float alpha1 = __expf(mrow1 - mnew1);
        float lsum0 = 0.0f, lsum1 = 0.0f;
        #pragma unroll
        for (int nf = 0; nf < 8; nf++) {
            s[nf][0] = __expf(s[nf][0] - mnew0);
            s[nf][1] = __expf(s[nf][1] - mnew0);
            s[nf][2] = __expf(s[nf][2] - mnew1);
            s[nf][3] = __expf(s[nf][3] - mnew1);
            lsum0 += s[nf][0] + s[nf][1];
            lsum1 += s[nf][2] + s[nf][3];
        }
        lsum0 += __shfl_xor_sync(0xffffffffu, lsum0, 1);
        lsum0 += __shfl_xor_sync(0xffffffffu, lsum0, 2);
        lsum1 += __shfl_xor_sync(0xffffffffu, lsum1, 1);
        lsum1 += __shfl_xor_sync(0xffffffffu, lsum1, 2);
        l0 = l0 * alpha0 + lsum0;
        l1 = l1 * alpha1 + lsum1;
        mrow0 = mnew0; mrow1 = mnew1;
        #pragma unroll
        for (int nf = 0; nf < 8; nf++) {
            o[nf][0] *= alpha0; o[nf][1] *= alpha0;
            o[nf][2] *= alpha1; o[nf][3] *= alpha1;
        }

        // O += P @ V : P D-fragments pack directly into fp16 A-fragments
        #pragma unroll
        for (int c = 0; c < 4; c++) {
            uint32_t a0 = pack_h2(s[2*c][0],   s[2*c][1]);
            uint32_t a1 = pack_h2(s[2*c][2],   s[2*c][3]);
            uint32_t a2 = pack_h2(s[2*c+1][0], s[2*c+1][1]);
            uint32_t a3 = pack_h2(s[2*c+1][2], s[2*c+1][3]);
            const uint32_t rowoff = (uint32_t)(c * 16 * HS * 2);
            #pragma unroll
            for (int np = 0; np < 4; np++) {
                uint32_t b00, b01, b10, b11;
                ldmatrix_x4_trans(b00, b01, b10, b11,
                                  sbV + rowoff + (uint32_t)(np * 32));
                mma_f16(o[2*np],   a0, a1, a2, a3, b00, b01);
                mma_f16(o[2*np+1], a0, a1, a2, a3, b10, b11);
            }
        }
        __syncthreads();
    }

    const float inv0 = 1.0f / l0;
    const float inv1 = 1.0f / l1;
    const int r0 = q0 + w16 + grp;
    #pragma unroll
    for (int nf = 0; nf < 8; nf++) {
        const int d0 = nf * 8 + t4 * 2;
        *(uint32_t*)&ctx[base + (size_t)r0 * DIM + d0] =
            pack_h2(o[nf][0] * inv0, o[nf][1] * inv0);
        *(uint32_t*)&ctx[base + (size_t)(r0 + 8) * DIM + d0] =
            pack_h2(o[nf][2] * inv1, o[nf][3] * inv1);
    }
}

// ---------------- residual + LayerNorm ----------------
template<int HOUT>
__global__ void ln_residual_kernel(const float* __restrict__ a,
                                   const float* __restrict__ r,
                                   const float* __restrict__ gamma,
                                   const float* __restrict__ beta,
                                   float* __restrict__ out,
                                   __half* __restrict__ out_t) {
    const int row = blockIdx.x;
    const int tid = threadIdx.x;
    const float* pa = a + (size_t)row * DIM;
    const float* pr = r + (size_t)row * DIM;

    float v[4];
    float sum = 0.0f, sq = 0.0f;
    #pragma unroll
    for (int i = 0; i < 4; i++) {
        int c = tid + i * 256;
        float t = pa[c] + pr[c];
        v[i] = t;
        sum += t;
        sq  += t * t;
    }
    #pragma unroll
    for (int off = 16; off >= 1; off >>= 1) {
        sum += __shfl_xor_sync(0xffffffffu, sum, off);
        sq  += __shfl_xor_sync(0xffffffffu, sq,  off);
    }
    __shared__ float ssum[8], ssq[8];
    int warp = tid >> 5, lane = tid & 31;
    if (lane == 0) { ssum[warp] = sum; ssq[warp] = sq; }
    __syncthreads();
    sum = 0.0f; sq = 0.0f;
    #pragma unroll
    for (int i = 0; i < 8; i++) { sum += ssum[i]; sq += ssq[i]; }

    const float invN = 1.0f / (float)DIM;
    float mu  = sum * invN;
    float var = fmaxf(sq * invN - mu * mu, 0.0f);
    float rstd = rsqrtf(var + 1e-12f);

    #pragma unroll
    for (int i = 0; i < 4; i++) {
        int c = tid + i * 256;
        float res = (v[i] - mu) * rstd * gamma[c] + beta[c];
        out[(size_t)row * DIM + c] = res;
        if (HOUT) out_t[(size_t)row * DIM + c] = __float2half_rn(res);
    }
}

// ---------------- launch ----------------
extern "C" void kernel_launch(void* const* d_in, const int* in_sizes, int n_in,
                              void* d_out, int out_size) {
    const float* x    = (const float*)d_in[0];
    const int*   mask = (const int*)  d_in[1];
    const float* Wq   = (const float*)d_in[2];
    const float* bq   = (const float*)d_in[3];
    const float* Wk   = (const float*)d_in[4];
    const float* bk   = (const float*)d_in[5];
    const float* Wv   = (const float*)d_in[6];
    const float* bv   = (const float*)d_in[7];
    const float* Wo   = (const float*)d_in[8];
    const float* bo   = (const float*)d_in[9];
    const float* ln1g = (const float*)d_in[10];
    const float* ln1b = (const float*)d_in[11];
    const float* W1   = (const float*)d_in[12];
    const float* b1   = (const float*)d_in[13];
    const float* W2   = (const float*)d_in[14];
    const float* b2   = (const float*)d_in[15];
    const float* ln2g = (const float*)d_in[16];
    const float* ln2b = (const float*)d_in[17];
    float* out = (float*)d_out;

    __half *q, *k, *v, *ctx, *h1t, *ffn, *xt, *wqt, *wkt, *wvt, *wot, *w1t, *w2t;
    float *sa, *h1, *f2;
    cudaGetSymbolAddress((void**)&q,   g_q);
    cudaGetSymbolAddress((void**)&k,   g_k);
    cudaGetSymbolAddress((void**)&v,   g_v);
    cudaGetSymbolAddress((void**)&ctx, g_ctx);
    cudaGetSymbolAddress((void**)&h1t, g_h1t);
    cudaGetSymbolAddress((void**)&ffn, g_ffn);
    cudaGetSymbolAddress((void**)&xt,  g_xt);
    cudaGetSymbolAddress((void**)&wqt, g_wqt);
    cudaGetSymbolAddress((void**)&wkt, g_wkt);
    cudaGetSymbolAddress((void**)&wvt, g_wvt);
    cudaGetSymbolAddress((void**)&wot, g_wot);
    cudaGetSymbolAddress((void**)&w1t, g_w1t);
    cudaGetSymbolAddress((void**)&w2t, g_w2t);
    cudaGetSymbolAddress((void**)&sa,  g_sa);
    cudaGetSymbolAddress((void**)&h1,  g_h1);
    cudaGetSymbolAddress((void**)&f2,  g_f2);

    cudaFuncSetAttribute(qkv_gemm,      cudaFuncAttributeMaxDynamicSharedMemorySize, GEMM_SMEM_BYTES);
    cudaFuncSetAttribute(gemm_cp<0,0>,  cudaFuncAttributeMaxDynamicSharedMemorySize, GEMM_SMEM_BYTES);
    cudaFuncSetAttribute(gemm_cp<1,1>,  cudaFuncAttributeMaxDynamicSharedMemorySize, GEMM_SMEM_BYTES);
    cudaFuncSetAttribute(attn_mma,      cudaFuncAttributeMaxDynamicSharedMemorySize, ATTN_SMEM_BYTES);

    {
        const int thr = 256;
        cvt_h_kernel<<<(MROWS*DIM/4 + thr-1)/thr, thr>>>(x, xt, MROWS*DIM/4);
        dim3 tb(32, 8);
        transpose_h_kernel<<<dim3(DIM/32, DIM/32), tb>>>(Wq, wqt, DIM, DIM);
        transpose_h_kernel<<<dim3(DIM/32, DIM/32), tb>>>(Wk, wkt, DIM, DIM);
        transpose_h_kernel<<<dim3(DIM/32, DIM/32), tb>>>(Wv, wvt, DIM, DIM);
        transpose_h_kernel<<<dim3(DIM/32, DIM/32), tb>>>(Wo, wot, DIM, DIM);
        transpose_h_kernel<<<dim3(HID/32, DIM/32), tb>>>(W1, w1t, DIM, HID);
        transpose_h_kernel<<<dim3(DIM/32, HID/32), tb>>>(W2, w2t, HID, DIM);
    }

    // fused QKV (fp16 out; q pre-scaled by 0.125)
    qkv_gemm<<<dim3(24, MROWS/128), 256, GEMM_SMEM_BYTES>>>(xt, wqt, wkt, wvt, bq, bk, bv, q, k, v);

    // attention (fp16 in/out)
    attn_mma<<<dim3(SEQ/128, NH, BS), 256, ATTN_SMEM_BYTES>>>(q, k, v, mask, ctx);

    // Wo projection -> sa_out fp32
    gemm_cp<0,0><<<dim3(DIM/128, MROWS/128), 256, GEMM_SMEM_BYTES>>>(ctx, wot, bo, sa, DIM, DIM);

    // LN1(sa + x) -> h1 fp32 + h1t fp16
    ln_residual_kernel<1><<<MROWS, 256>>>(sa, x, ln1g, ln1b, h1, h1t);

    // FFN1 (gelu, fp16 out), FFN2 (fp32 out)
    gemm_cp<1,1><<<dim3(HID/128, MROWS/128), 256, GEMM_SMEM_BYTES>>>(h1t, w1t, b1, ffn, DIM, HID);
    gemm_cp<0,0><<<dim3(DIM/128, MROWS/128), 256, GEMM_SMEM_BYTES>>>(ffn, w2t, b2, f2, HID, DIM);

    // LN2(f2 + h1) -> out
    ln_residual_kernel<0><<<MROWS, 256>>>(f2, h1, ln2g, ln2b, out, nullptr);
}

// round 11
// speedup vs baseline: 7.2031x; 1.0074x over previous
#include <cuda_runtime.h>
#include <cuda_fp16.h>
#include <math.h>
#include <stdint.h>

#define BS   2
#define SEQ  2048
#define DIM  1024
#define HID  4096
#define NH   16
#define DPH  64
#define MROWS (BS*SEQ)   // 4096

// ---------------- scratch (no allocation allowed) ----------------
__device__ __half g_q  [MROWS*DIM];
__device__ __half g_k  [MROWS*DIM];
__device__ __half g_v  [MROWS*DIM];
__device__ __half g_ctx[MROWS*DIM];
__device__ __half g_h1t[MROWS*DIM];
__device__ __half g_ffn[MROWS*HID];
__device__ __half g_xt [MROWS*DIM];
__device__ __half g_wqh[DIM*DIM];
__device__ __half g_wkh[DIM*DIM];
__device__ __half g_wvh[DIM*DIM];
__device__ __half g_woh[DIM*DIM];
__device__ __half g_w1h[DIM*HID];
__device__ __half g_w2h[HID*DIM];
__device__ float  g_sa [MROWS*DIM];
__device__ float  g_h1 [MROWS*DIM];
__device__ float  g_f2 [MROWS*DIM];

__device__ __forceinline__ uint32_t smem_u32(const void* p) {
    uint32_t a;
    asm("{ .reg .u64 t; cvta.to.shared.u64 t, %1; cvt.u32.u64 %0, t; }" : "=r"(a) : "l"(p));
    return a;
}
__device__ __forceinline__ void cp_async16(uint32_t dst, const void* src) {
    asm volatile("cp.async.cg.shared.global [%0], [%1], 16;" :: "r"(dst), "l"(src));
}
#define CP_COMMIT() asm volatile("cp.async.commit_group;" ::: "memory")
#define CP_WAIT(n)  asm volatile("cp.async.wait_group %0;" :: "n"(n) : "memory")

__device__ __forceinline__ void ldmatrix_x4(uint32_t& r0, uint32_t& r1, uint32_t& r2, uint32_t& r3,
                                            uint32_t addr) {
    asm volatile("ldmatrix.sync.aligned.m8n8.x4.shared.b16 {%0,%1,%2,%3}, [%4];"
        : "=r"(r0), "=r"(r1), "=r"(r2), "=r"(r3) : "r"(addr));
}
__device__ __forceinline__ void ldmatrix_x4_trans(uint32_t& r0, uint32_t& r1, uint32_t& r2, uint32_t& r3,
                                                  uint32_t addr) {
    asm volatile("ldmatrix.sync.aligned.m8n8.x4.trans.shared.b16 {%0,%1,%2,%3}, [%4];"
        : "=r"(r0), "=r"(r1), "=r"(r2), "=r"(r3) : "r"(addr));
}

__device__ __forceinline__ void mma_f16(float* d,
                                        uint32_t a0, uint32_t a1, uint32_t a2, uint32_t a3,
                                        uint32_t b0, uint32_t b1) {
    asm volatile(
        "mma.sync.aligned.m16n8k16.row.col.f32.f16.f16.f32 "
        "{%0,%1,%2,%3}, {%4,%5,%6,%7}, {%8,%9}, {%0,%1,%2,%3};"
        : "+f"(d[0]), "+f"(d[1]), "+f"(d[2]), "+f"(d[3])
        : "r"(a0), "r"(a1), "r"(a2), "r"(a3), "r"(b0), "r"(b1));
}

__device__ __forceinline__ uint32_t pack_h2(float a, float b) {
    __half2 h = __floats2half2_rn(a, b);
    return *(uint32_t*)&h;
}

__device__ __forceinline__ float gelu_f(float x) {
    return 0.5f * x * (1.0f + erff(x * 0.70710678118654752f));
}

// ---------------- prep: fp32 -> fp16 ----------------
__global__ void cvt_h_kernel(const float* __restrict__ in, __half* __restrict__ out, int n4) {
    int i = blockIdx.x * blockDim.x + threadIdx.x;
    if (i < n4) {
        float4 v = ((const float4*)in)[i];
        uint2 u;
        u.x = pack_h2(v.x, v.y);
        u.y = pack_h2(v.z, v.w);
        ((uint2*)out)[i] = u;
    }
}

// ---------------- fp16 GEMM: A [m][k], W row-major [k][n] (trans ldmatrix B) ----------------
// CTA 128x128, BK=64, 3-stage cp.async.
#define AS 72                                    // halves per A row
#define BT 136                                   // halves per B row (128 + 8 pad)
#define A_TILE_BYTES (128 * AS * 2)              // 18432
#define B_TILE_BYTES (64 * BT * 2)               // 17408
#define G_STAGE_BYTES (A_TILE_BYTES + B_TILE_BYTES)   // 35840
#define GEMM_SMEM_BYTES (3 * G_STAGE_BYTES)      // 107520

template<int ACT, int HOUT>
__device__ __forceinline__ void gemm_body(const __half* __restrict__ A,
                                          const __half* __restrict__ W,
                                          const float* __restrict__ bias,
                                          void* __restrict__ Cv,
                                          int K, int N, int m0, int n0, float oscale) {
    extern __shared__ uint32_t dsm[];
    const uint32_t sb = smem_u32(dsm);

    const int tid  = threadIdx.x;
    const int lane = tid & 31;
    const int wid  = tid >> 5;
    const int grp  = lane >> 2;
    const int t4   = lane & 3;
    const int ts   = lane >> 3;
    const int r8   = lane & 7;
    const int wm = (wid & 3) * 32;
    const int wn = (wid >> 2) * 64;

    // fragment lane offsets (bytes)
    const uint32_t a_loff = (uint32_t)((((ts & 1) * 8 + r8) * AS) * 2 + (ts >> 1) * 16);
    const uint32_t b_loff = (uint32_t)((((ts & 1) * 8 + r8) * BT) * 2 + (ts >> 1) * 16);

    float acc[2][8][4];
    #pragma unroll
    for (int i = 0; i < 2; i++)
        #pragma unroll
        for (int j = 0; j < 8; j++)
            #pragma unroll
            for (int c = 0; c < 4; c++) acc[i][j][c] = 0.0f;

    const int nit = K / 64;

    auto load_stage = [&](int s, int it) {
        const uint32_t base = sb + (uint32_t)s * G_STAGE_BYTES;
        #pragma unroll
        for (int j = 0; j < 4; j++) {
            int idx = tid + j * 256;
            int row = idx >> 3, c = idx & 7;
            cp_async16(base + (uint32_t)(row * AS * 2 + c * 16),
                       A + (size_t)(m0 + row) * K + it * 64 + c * 8);
        }
        #pragma unroll
        for (int j = 0; j < 4; j++) {
            int idx = tid + j * 256;
            int k = idx >> 4, nb = (idx & 15) * 8;
            cp_async16(base + (uint32_t)A_TILE_BYTES + (uint32_t)(k * BT * 2 + nb * 2),
                       W + (size_t)(it * 64 + k) * N + n0 + nb);
        }
    };

    load_stage(0, 0);
    CP_COMMIT();
    if (nit > 1) { load_stage(1, 1); }
    CP_COMMIT();

    for (int it = 0; it < nit; it++) {
        const int s = it % 3;
        CP_WAIT(1);
        __syncthreads();
        if (it + 2 < nit) load_stage((it + 2) % 3, it + 2);
        CP_COMMIT();

        const uint32_t sA = sb + (uint32_t)s * G_STAGE_BYTES + (uint32_t)(wm * AS * 2) + a_loff;
        const uint32_t sB = sb + (uint32_t)s * G_STAGE_BYTES + (uint32_t)A_TILE_BYTES
                          + (uint32_t)(wn * 2) + b_loff;
        #pragma unroll
        for (int kk = 0; kk < 4; kk++) {
            uint32_t afr[2][4];
            #pragma unroll
            for (int mt = 0; mt < 2; mt++)
                ldmatrix_x4(afr[mt][0], afr[mt][1], afr[mt][2], afr[mt][3],
                            sA + (uint32_t)(mt * 16 * AS * 2) + (uint32_t)(kk * 32));
            uint32_t bfr[8][2];
            #pragma unroll
            for (int np = 0; np < 4; np++)
                ldmatrix_x4_trans(bfr[2*np][0], bfr[2*np][1], bfr[2*np+1][0], bfr[2*np+1][1],
                                  sB + (uint32_t)(kk * 16 * BT * 2) + (uint32_t)(np * 32));
            #pragma unroll
            for (int mt = 0; mt < 2; mt++)
                #pragma unroll
                for (int nt = 0; nt < 8; nt++)
                    mma_f16(acc[mt][nt], afr[mt][0], afr[mt][1], afr[mt][2], afr[mt][3],
                            bfr[nt][0], bfr[nt][1]);
        }
    }

    #pragma unroll
    for (int mt = 0; mt < 2; mt++) {
        #pragma unroll
        for (int nt = 0; nt < 8; nt++) {
            const int col = n0 + wn + nt * 8 + t4 * 2;
            const float b0v = bias[col], b1v = bias[col + 1];
            const int r0 = m0 + wm + mt * 16 + grp;
            float v0 = (acc[mt][nt][0] + b0v) * oscale;
            float v1 = (acc[mt][nt][1] + b1v) * oscale;
            float v2 = (acc[mt][nt][2] + b0v) * oscale;
            float v3 = (acc[mt][nt][3] + b1v) * oscale;
            if (ACT == 1) { v0 = gelu_f(v0); v1 = gelu_f(v1); v2 = gelu_f(v2); v3 = gelu_f(v3); }
            if (HOUT) {
                __half* Ch = (__half*)Cv;
                *(uint32_t*)&Ch[(size_t)r0 * N + col]       = pack_h2(v0, v1);
                *(uint32_t*)&Ch[(size_t)(r0 + 8) * N + col] = pack_h2(v2, v3);
            } else {
                float* Cf = (float*)Cv;
                *(float2*)&Cf[(size_t)r0 * N + col]       = make_float2(v0, v1);
                *(float2*)&Cf[(size_t)(r0 + 8) * N + col] = make_float2(v2, v3);
            }
        }
    }
}

template<int ACT, int HOUT>
__global__ void __launch_bounds__(256, 2)
gemm_cp(const __half* __restrict__ A, const __half* __restrict__ W,
        const float* __restrict__ bias, void* __restrict__ C, int K, int N) {
    gemm_body<ACT, HOUT>(A, W, bias, C, K, N, blockIdx.y * 128, blockIdx.x * 128, 1.0f);
}

__global__ void __launch_bounds__(256, 2)
qkv_gemm(const __half* __restrict__ xt,
         const __half* __restrict__ wq, const __half* __restrict__ wk, const __half* __restrict__ wv,
         const float* __restrict__ bq, const float* __restrict__ bk, const float* __restrict__ bv,
         __half* __restrict__ q, __half* __restrict__ k, __half* __restrict__ v) {
    const int sel = blockIdx.x >> 3;
    const __half* W   = (sel == 0) ? wq : (sel == 1) ? wk : wv;
    const float* bias = (sel == 0) ? bq : (sel == 1) ? bk : bv;
    __half*      C    = (sel == 0) ? q  : (sel == 1) ? k  : v;
    const float scale = (sel == 0) ? 0.125f : 1.0f;
    gemm_body<0, 1>(xt, W, bias, C, DIM, DIM, blockIdx.y * 128, (blockIdx.x & 7) * 128, scale);
}

// ---------------- fp16 flash attention (unchanged from R10) ----------------
#define HS 72
#define AT_Q (128 * HS)
#define AT_T (64 * HS)
#define ATTN_SMEM_BYTES ((AT_Q + 4 * AT_T) * 2 + 512)   // 55808

__global__ void __launch_bounds__(256, 2)
attn_mma(const __half* __restrict__ Q, const __half* __restrict__ K,
         const __half* __restrict__ V, const int* __restrict__ mask,
         __half* __restrict__ ctx) {
    extern __shared__ uint32_t asm_[];
    const uint32_t sb = smem_u32(asm_);
    const uint32_t qoff = 0u;
    const uint32_t koff[2] = { (uint32_t)AT_Q * 2u, (uint32_t)(AT_Q + AT_T) * 2u };
    const uint32_t voff[2] = { (uint32_t)(AT_Q + 2 * AT_T) * 2u, (uint32_t)(AT_Q + 3 * AT_T) * 2u };
    float* smaskb = (float*)((char*)asm_ + (AT_Q + 4 * AT_T) * 2);

    const int tid  = threadIdx.x;
    const int lane = tid & 31;
    const int wid  = tid >> 5;
    const int grp  = lane >> 2;
    const int t4   = lane & 3;
    const int ts   = lane >> 3;
    const int r8   = lane & 7;
    const int w16  = wid * 16;
    const int q0 = blockIdx.x * 128;
    const int h  = blockIdx.y;
    const int b  = blockIdx.z;
    const size_t base = (size_t)b * SEQ * DIM + h * DPH;

    const uint32_t q_loff = (uint32_t)(((w16 + (ts & 1) * 8 + r8) * HS) * 2 + (ts >> 1) * 16);
    const uint32_t k_loff = (uint32_t)((((ts >> 1) * 8 + r8) * HS) * 2 + (ts & 1) * 16);
    const uint32_t v_loff = (uint32_t)((((ts & 1) * 8 + r8) * HS) * 2 + (ts >> 1) * 16);

    float o[8][4];
    #pragma unroll
    for (int nf = 0; nf < 8; nf++)
        #pragma unroll
        for (int c = 0; c < 4; c++) o[nf][c] = 0.0f;
    float mrow0 = -INFINITY, mrow1 = -INFINITY;
    float l0 = 0.0f, l1 = 0.0f;

    {
        #pragma unroll
        for (int j = 0; j < 4; j++) {
            int idx = tid + j * 256;
            int row = idx >> 3, c = idx & 7;
            cp_async16(sb + qoff + (uint32_t)(row * HS * 2 + c * 16),
                       Q + base + (size_t)(q0 + row) * DIM + c * 8);
        }
        #pragma unroll
        for (int j = 0; j < 2; j++) {
            int idx = tid + j * 256;
            int row = idx >> 3, c = idx & 7;
            size_t g = base + (size_t)row * DIM + c * 8;
            cp_async16(sb + koff[0] + (uint32_t)(row * HS * 2 + c * 16), K + g);
            cp_async16(sb + voff[0] + (uint32_t)(row * HS * 2 + c * 16), V + g);
        }
        CP_COMMIT();
        if (tid < 64)
            smaskb[tid] = (mask[b * SEQ + tid] == 0) ? -INFINITY : 0.0f;
    }

    const int nt_tiles = SEQ / 64;
    for (int it = 0; it < nt_tiles; it++) {
        const int buf = it & 1;
        const int kv_next = (it + 1) * 64;
        if (it + 1 < nt_tiles) {
            #pragma unroll
            for (int j = 0; j < 2; j++) {
                int idx = tid + j * 256;
                int row = idx >> 3, c = idx & 7;
                size_t g = base + (size_t)(kv_next + row) * DIM + c * 8;
                cp_async16(sb + koff[buf ^ 1] + (uint32_t)(row * HS * 2 + c * 16), K + g);
                cp_async16(sb + voff[buf ^ 1] + (uint32_t)(row * HS * 2 + c * 16), V + g);
            }
            CP_COMMIT();
            if (tid < 64)
                smaskb[(buf ^ 1) * 64 + tid] = (mask[b * SEQ + kv_next + tid] == 0) ? -INFINITY : 0.0f;
            CP_WAIT(1);
        } else {
            CP_WAIT(0);
        }
        __syncthreads();

        const uint32_t sbK = sb + koff[buf] + k_loff;
        const uint32_t sbV = sb + voff[buf] + v_loff;
        const float* smask = smaskb + buf * 64;

        float s[8][4];
        #pragma unroll
        for (int nf = 0; nf < 8; nf++)
            #pragma unroll
            for (int c = 0; c < 4; c++) s[nf][c] = 0.0f;
        #pragma unroll
        for (int kk = 0; kk < 4; kk++) {
            const uint32_t kb = kk * 32;
            uint32_t qa0, qa1, qa2, qa3;
            ldmatrix_x4(qa0, qa1, qa2, qa3, sb + qoff + q_loff + kb);
            #pragma unroll
            for (int np = 0; np < 4; np++) {
                uint32_t b00, b01, b10, b11;
                ldmatrix_x4(b00, b01, b10, b11,
                            sbK + (uint32_t)(np * 16 * HS * 2) + kb);
                mma_f16(s[2*np],   qa0, qa1, qa2, qa3, b00, b01);
                mma_f16(s[2*np+1], qa0, qa1, qa2, qa3, b10, b11);
            }
        }

        #pragma unroll
        for (int nf = 0; nf < 8; nf++) {
            float mv0 = smask[nf * 8 + t4 * 2];
            float mv1 = smask[nf * 8 + t4 * 2 + 1];
            s[nf][0] += mv0; s[nf][1] += mv1;
            s[nf][2] += mv0; s[nf][3] += mv1;
        }

        float mt0 = -INFINITY, mt1 = -INFINITY;
        #pragma unroll
        for (int nf = 0; nf < 8; nf++) {
            mt0 = fmaxf(mt0, fmaxf(s[nf][0], s[nf][1]));
            mt1 = fmaxf(mt1, fmaxf(s[nf][2], s[nf][3]));
        }
        mt0 = fmaxf(mt0, __shfl_xor_sync(0xffffffffu, mt0, 1));
        mt0 = fmaxf(mt0, __shfl_xor_sync(0xffffffffu, mt0, 2));
        mt1 = fmaxf(mt1, __shfl_xor_sync(0xffffffffu, mt1, 1));
        mt1 = fmaxf(mt1, __shfl_xor_sync(0xffffffffu, mt1, 2));
        float mnew0 = fmaxf(mrow0, mt0);
        float mnew1 = fmaxf(mrow1, mt1);
        float alpha0 = __expf(mrow0 - mnew0);
        float alpha1 = __expf(mrow1 - mnew1);
        float lsum0 = 0.0f, lsum1 = 0.0f;
        #pragma unroll
        for (int nf = 0; nf < 8; nf++) {
            s[nf][0] = __expf(s[nf][0] - mnew0);
            s[nf][1] = __expf(s[nf][1] - mnew0);
            s[nf][2] = __expf(s[nf][2] - mnew1);
            s[nf][3] = __expf(s[nf][3] - mnew1);
            lsum0 += s[nf][0] + s[nf][1];
            lsum1 += s[nf][2] + s[nf][3];
        }
        lsum0 += __shfl_xor_sync(0xffffffffu, lsum0, 1);
        lsum0 += __shfl_xor_sync(0xffffffffu, lsum0, 2);
        lsum1 += __shfl_xor_sync(0xffffffffu, lsum1, 1);
        lsum1 += __shfl_xor_sync(0xffffffffu, lsum1, 2);
        l0 = l0 * alpha0 + lsum0;
        l1 = l1 * alpha1 + lsum1;
        mrow0 = mnew0; mrow1 = mnew1;
        #pragma unroll
        for (int nf = 0; nf < 8; nf++) {
            o[nf][0] *= alpha0; o[nf][1] *= alpha0;
            o[nf][2] *= alpha1; o[nf][3] *= alpha1;
        }

        #pragma unroll
        for (int c = 0; c < 4; c++) {
            uint32_t a0 = pack_h2(s[2*c][0],   s[2*c][1]);
            uint32_t a1 = pack_h2(s[2*c][2],   s[2*c][3]);
            uint32_t a2 = pack_h2(s[2*c+1][0], s[2*c+1][1]);
            uint32_t a3 = pack_h2(s[2*c+1][2], s[2*c+1][3]);
            const uint32_t rowoff = (uint32_t)(c * 16 * HS * 2);
            #pragma unroll
            for (int np = 0; np < 4; np++) {
                uint32_t b00, b01, b10, b11;
                ldmatrix_x4_trans(b00, b01, b10, b11,
                                  sbV + rowoff + (uint32_t)(np * 32));
                mma_f16(o[2*np],   a0, a1, a2, a3, b00, b01);
                mma_f16(o[2*np+1], a0, a1, a2, a3, b10, b11);
            }
        }
        __syncthreads();
    }

    const float inv0 = 1.0f / l0;
    const float inv1 = 1.0f / l1;
    const int r0 = q0 + w16 + grp;
    #pragma unroll
    for (int nf = 0; nf < 8; nf++) {
        const int d0 = nf * 8 + t4 * 2;
        *(uint32_t*)&ctx[base + (size_t)r0 * DIM + d0] =
            pack_h2(o[nf][0] * inv0, o[nf][1] * inv0);
        *(uint32_t*)&ctx[base + (size_t)(r0 + 8) * DIM + d0] =
            pack_h2(o[nf][2] * inv1, o[nf][3] * inv1);
    }
}

// ---------------- residual + LayerNorm (float4) ----------------
template<int HOUT>
__global__ void ln_residual_kernel(const float* __restrict__ a,
                                   const float* __restrict__ r,
                                   const float* __restrict__ gamma,
                                   const float* __restrict__ beta,
                                   float* __restrict__ out,
                                   __half* __restrict__ out_t) {
    const int row = blockIdx.x;
    const int tid = threadIdx.x;
    const float* pa = a + (size_t)row * DIM;
    const float* pr = r + (size_t)row * DIM;

    float4 va = ((const float4*)pa)[tid];
    float4 vr = ((const float4*)pr)[tid];
    float v[4] = { va.x + vr.x, va.y + vr.y, va.z + vr.z, va.w + vr.w };
    float sum = v[0] + v[1] + v[2] + v[3];
    float sq  = v[0]*v[0] + v[1]*v[1] + v[2]*v[2] + v[3]*v[3];

    #pragma unroll
    for (int off = 16; off >= 1; off >>= 1) {
        sum += __shfl_xor_sync(0xffffffffu, sum, off);
        sq  += __shfl_xor_sync(0xffffffffu, sq,  off);
    }
    __shared__ float ssum[8], ssq[8];
    int warp = tid >> 5, lane = tid & 31;
    if (lane == 0) { ssum[warp] = sum; ssq[warp] = sq; }
    __syncthreads();
    sum = 0.0f; sq = 0.0f;
    #pragma unroll
    for (int i = 0; i < 8; i++) { sum += ssum[i]; sq += ssq[i]; }

    const float invN = 1.0f / (float)DIM;
    float mu  = sum * invN;
    float var = fmaxf(sq * invN - mu * mu, 0.0f);
    float rstd = rsqrtf(var + 1e-12f);

    float4 g4 = ((const float4*)gamma)[tid];
    float4 b4 = ((const float4*)beta)[tid];
    float4 o4;
    o4.x = (v[0] - mu) * rstd * g4.x + b4.x;
    o4.y = (v[1] - mu) * rstd * g4.y + b4.y;
    o4.z = (v[2] - mu) * rstd * g4.z + b4.z;
    o4.w = (v[3] - mu) * rstd * g4.w + b4.w;
    ((float4*)(out + (size_t)row * DIM))[tid] = o4;
    if (HOUT) {
        uint2 u;
        u.x = pack_h2(o4.x, o4.y);
        u.y = pack_h2(o4.z, o4.w);
        ((uint2*)(out_t + (size_t)row * DIM))[tid] = u;
    }
}

// ---------------- launch ----------------
extern "C" void kernel_launch(void* const* d_in, const int* in_sizes, int n_in,
                              void* d_out, int out_size) {
    const float* x    = (const float*)d_in[0];
    const int*   mask = (const int*)  d_in[1];
    const float* Wq   = (const float*)d_in[2];
    const float* bq   = (const float*)d_in[3];
    const float* Wk   = (const float*)d_in[4];
    const float* bk   = (const float*)d_in[5];
    const float* Wv   = (const float*)d_in[6];
    const float* bv   = (const float*)d_in[7];
    const float* Wo   = (const float*)d_in[8];
    const float* bo   = (const float*)d_in[9];
    const float* ln1g = (const float*)d_in[10];
    const float* ln1b = (const float*)d_in[11];
    const float* W1   = (const float*)d_in[12];
    const float* b1   = (const float*)d_in[13];
    const float* W2   = (const float*)d_in[14];
    const float* b2   = (const float*)d_in[15];
    const float* ln2g = (const float*)d_in[16];
    const float* ln2b = (const float*)d_in[17];
    float* out = (float*)d_out;

    __half *q, *k, *v, *ctx, *h1t, *ffn, *xt, *wqh, *wkh, *wvh, *woh, *w1h, *w2h;
    float *sa, *h1, *f2;
    cudaGetSymbolAddress((void**)&q,   g_q);
    cudaGetSymbolAddress((void**)&k,   g_k);
    cudaGetSymbolAddress((void**)&v,   g_v);
    cudaGetSymbolAddress((void**)&ctx, g_ctx);
    cudaGetSymbolAddress((void**)&h1t, g_h1t);
    cudaGetSymbolAddress((void**)&ffn, g_ffn);
    cudaGetSymbolAddress((void**)&xt,  g_xt);
    cudaGetSymbolAddress((void**)&wqh, g_wqh);
    cudaGetSymbolAddress((void**)&wkh, g_wkh);
    cudaGetSymbolAddress((void**)&wvh, g_wvh);
    cudaGetSymbolAddress((void**)&woh, g_woh);
    cudaGetSymbolAddress((void**)&w1h, g_w1h);
    cudaGetSymbolAddress((void**)&w2h, g_w2h);
    cudaGetSymbolAddress((void**)&sa,  g_sa);
    cudaGetSymbolAddress((void**)&h1,  g_h1);
    cudaGetSymbolAddress((void**)&f2,  g_f2);

    cudaFuncSetAttribute(qkv_gemm,      cudaFuncAttributeMaxDynamicSharedMemorySize, GEMM_SMEM_BYTES);
    cudaFuncSetAttribute(gemm_cp<0,0>,  cudaFuncAttributeMaxDynamicSharedMemorySize, GEMM_SMEM_BYTES);
    cudaFuncSetAttribute(gemm_cp<1,1>,  cudaFuncAttributeMaxDynamicSharedMemorySize, GEMM_SMEM_BYTES);
    cudaFuncSetAttribute(attn_mma,      cudaFuncAttributeMaxDynamicSharedMemorySize, ATTN_SMEM_BYTES);

    {
        const int thr = 256;
        cvt_h_kernel<<<(MROWS*DIM/4 + thr-1)/thr, thr>>>(x,  xt,  MROWS*DIM/4);
        cvt_h_kernel<<<(DIM*DIM/4   + thr-1)/thr, thr>>>(Wq, wqh, DIM*DIM/4);
        cvt_h_kernel<<<(DIM*DIM/4   + thr-1)/thr, thr>>>(Wk, wkh, DIM*DIM/4);
        cvt_h_kernel<<<(DIM*DIM/4   + thr-1)/thr, thr>>>(Wv, wvh, DIM*DIM/4);
        cvt_h_kernel<<<(DIM*DIM/4   + thr-1)/thr, thr>>>(Wo, woh, DIM*DIM/4);
        cvt_h_kernel<<<(DIM*HID/4   + thr-1)/thr, thr>>>(W1, w1h, DIM*HID/4);
        cvt_h_kernel<<<(HID*DIM/4   + thr-1)/thr, thr>>>(W2, w2h, HID*DIM/4);
    }

    // fused QKV (fp16 out; q pre-scaled by 0.125)
    qkv_gemm<<<dim3(24, MROWS/128), 256, GEMM_SMEM_BYTES>>>(xt, wqh, wkh, wvh, bq, bk, bv, q, k, v);

    // attention (fp16 in/out)
    attn_mma<<<dim3(SEQ/128, NH, BS), 256, ATTN_SMEM_BYTES>>>(q, k, v, mask, ctx);

    // Wo projection -> sa_out fp32
    gemm_cp<0,0><<<dim3(DIM/128, MROWS/128), 256, GEMM_SMEM_BYTES>>>(ctx, woh, bo, sa, DIM, DIM);

    // LN1(sa + x) -> h1 fp32 + h1t fp16
    ln_residual_kernel<1><<<MROWS, 256>>>(sa, x, ln1g, ln1b, h1, h1t);

    // FFN1 (gelu, fp16 out), FFN2 (fp32 out)
    gemm_cp<1,1><<<dim3(HID/128, MROWS/128), 256, GEMM_SMEM_BYTES>>>(h1t, w1h, b1, ffn, DIM, HID);
    gemm_cp<0,0><<<dim3(DIM/128, MROWS/128), 256, GEMM_SMEM_BYTES>>>(ffn, w2h, b2, f2, HID, DIM);

    // LN2(f2 + h1) -> out
    ln_residual_kernel<0><<<MROWS, 256>>>(f2, h1, ln2g, ln2b, out, nullptr);
}

// round 12
// speedup vs baseline: 7.4701x; 1.0371x over previous
#include <cuda_runtime.h>
#include <cuda_fp16.h>
#include <math.h>
#include <stdint.h>

#define BS   2
#define SEQ  2048
#define DIM  1024
#define HID  4096
#define NH   16
#define DPH  64
#define MROWS (BS*SEQ)   // 4096

// ---------------- scratch (no allocation allowed) ----------------
__device__ __half g_q  [MROWS*DIM];
__device__ __half g_k  [MROWS*DIM];
__device__ __half g_v  [MROWS*DIM];
__device__ __half g_ctx[MROWS*DIM];
__device__ __half g_h1t[MROWS*DIM];
__device__ __half g_ffn[MROWS*HID];
__device__ __half g_xt [MROWS*DIM];
__device__ __half g_wqh[DIM*DIM];
__device__ __half g_wkh[DIM*DIM];
__device__ __half g_wvh[DIM*DIM];
__device__ __half g_woh[DIM*DIM];
__device__ __half g_w1h[DIM*HID];
__device__ __half g_w2h[HID*DIM];
__device__ float  g_sa [MROWS*DIM];
__device__ float  g_h1 [MROWS*DIM];
__device__ float  g_f2 [MROWS*DIM];

__device__ __forceinline__ uint32_t smem_u32(const void* p) {
    uint32_t a;
    asm("{ .reg .u64 t; cvta.to.shared.u64 t, %1; cvt.u32.u64 %0, t; }" : "=r"(a) : "l"(p));
    return a;
}
__device__ __forceinline__ void cp_async16(uint32_t dst, const void* src) {
    asm volatile("cp.async.cg.shared.global [%0], [%1], 16;" :: "r"(dst), "l"(src));
}
#define CP_COMMIT() asm volatile("cp.async.commit_group;" ::: "memory")
#define CP_WAIT(n)  asm volatile("cp.async.wait_group %0;" :: "n"(n) : "memory")

__device__ __forceinline__ void ldmatrix_x4(uint32_t& r0, uint32_t& r1, uint32_t& r2, uint32_t& r3,
                                            uint32_t addr) {
    asm volatile("ldmatrix.sync.aligned.m8n8.x4.shared.b16 {%0,%1,%2,%3}, [%4];"
        : "=r"(r0), "=r"(r1), "=r"(r2), "=r"(r3) : "r"(addr));
}
__device__ __forceinline__ void ldmatrix_x4_trans(uint32_t& r0, uint32_t& r1, uint32_t& r2, uint32_t& r3,
                                                  uint32_t addr) {
    asm volatile("ldmatrix.sync.aligned.m8n8.x4.trans.shared.b16 {%0,%1,%2,%3}, [%4];"
        : "=r"(r0), "=r"(r1), "=r"(r2), "=r"(r3) : "r"(addr));
}

__device__ __forceinline__ void mma_f16(float* d,
                                        uint32_t a0, uint32_t a1, uint32_t a2, uint32_t a3,
                                        uint32_t b0, uint32_t b1) {
    asm volatile(
        "mma.sync.aligned.m16n8k16.row.col.f32.f16.f16.f32 "
        "{%0,%1,%2,%3}, {%4,%5,%6,%7}, {%8,%9}, {%0,%1,%2,%3};"
        : "+f"(d[0]), "+f"(d[1]), "+f"(d[2]), "+f"(d[3])
        : "r"(a0), "r"(a1), "r"(a2), "r"(a3), "r"(b0), "r"(b1));
}

__device__ __forceinline__ uint32_t pack_h2(float a, float b) {
    __half2 h = __floats2half2_rn(a, b);
    return *(uint32_t*)&h;
}

__device__ __forceinline__ float gelu_f(float x) {
    return 0.5f * x * (1.0f + erff(x * 0.70710678118654752f));
}

// ---------------- merged prep: fp32 -> fp16 for x + all 6 weights ----------------
// flat float4 index space; compile-time segment boundaries
#define C_X  (MROWS*DIM/4)               // 1048576
#define C_W  (DIM*DIM/4)                 // 262144
#define C_F  (DIM*HID/4)                 // 1048576
#define CB1  (C_X)
#define CB2  (CB1 + C_W)
#define CB3  (CB2 + C_W)
#define CB4  (CB3 + C_W)
#define CB5  (CB4 + C_W)
#define CB6  (CB5 + C_F)
#define CB7  (CB6 + C_F)                 // total 4,194,304

__global__ void cvt_all_kernel(const float* __restrict__ x,
                               const float* __restrict__ wq, const float* __restrict__ wk,
                               const float* __restrict__ wv, const float* __restrict__ wo,
                               const float* __restrict__ w1, const float* __restrict__ w2,
                               __half* __restrict__ xt,
                               __half* __restrict__ wqh, __half* __restrict__ wkh,
                               __half* __restrict__ wvh, __half* __restrict__ woh,
                               __half* __restrict__ w1h, __half* __restrict__ w2h) {
    for (int i = blockIdx.x * blockDim.x + threadIdx.x; i < CB7; i += gridDim.x * blockDim.x) {
        const float* in;
        __half* out;
        int off;
        if      (i < CB1) { in = x;  out = xt;  off = i; }
        else if (i < CB2) { in = wq; out = wqh; off = i - CB1; }
        else if (i < CB3) { in = wk; out = wkh; off = i - CB2; }
        else if (i < CB4) { in = wv; out = wvh; off = i - CB3; }
        else if (i < CB5) { in = wo; out = woh; off = i - CB4; }
        else if (i < CB6) { in = w1; out = w1h; off = i - CB5; }
        else              { in = w2; out = w2h; off = i - CB6; }
        float4 v = ((const float4*)in)[off];
        uint2 u;
        u.x = pack_h2(v.x, v.y);
        u.y = pack_h2(v.z, v.w);
        ((uint2*)out)[off] = u;
    }
}

// ---------------- fp16 GEMM: A [m][k], W row-major [k][n] (trans ldmatrix B) ----------------
// CTA 128x128, BK=64, 3-stage cp.async (unchanged from R11).
#define AS 72
#define BT 136
#define A_TILE_BYTES (128 * AS * 2)
#define B_TILE_BYTES (64 * BT * 2)
#define G_STAGE_BYTES (A_TILE_BYTES + B_TILE_BYTES)
#define GEMM_SMEM_BYTES (3 * G_STAGE_BYTES)

template<int ACT, int HOUT>
__device__ __forceinline__ void gemm_body(const __half* __restrict__ A,
                                          const __half* __restrict__ W,
                                          const float* __restrict__ bias,
                                          void* __restrict__ Cv,
                                          int K, int N, int m0, int n0, float oscale) {
    extern __shared__ uint32_t dsm[];
    const uint32_t sb = smem_u32(dsm);

    const int tid  = threadIdx.x;
    const int lane = tid & 31;
    const int wid  = tid >> 5;
    const int grp  = lane >> 2;
    const int t4   = lane & 3;
    const int ts   = lane >> 3;
    const int r8   = lane & 7;
    const int wm = (wid & 3) * 32;
    const int wn = (wid >> 2) * 64;

    const uint32_t a_loff = (uint32_t)((((ts & 1) * 8 + r8) * AS) * 2 + (ts >> 1) * 16);
    const uint32_t b_loff = (uint32_t)((((ts & 1) * 8 + r8) * BT) * 2 + (ts >> 1) * 16);

    float acc[2][8][4];
    #pragma unroll
    for (int i = 0; i < 2; i++)
        #pragma unroll
        for (int j = 0; j < 8; j++)
            #pragma unroll
            for (int c = 0; c < 4; c++) acc[i][j][c] = 0.0f;

    const int nit = K / 64;

    auto load_stage = [&](int s, int it) {
        const uint32_t base = sb + (uint32_t)s * G_STAGE_BYTES;
        #pragma unroll
        for (int j = 0; j < 4; j++) {
            int idx = tid + j * 256;
            int row = idx >> 3, c = idx & 7;
            cp_async16(base + (uint32_t)(row * AS * 2 + c * 16),
                       A + (size_t)(m0 + row) * K + it * 64 + c * 8);
        }
        #pragma unroll
        for (int j = 0; j < 4; j++) {
            int idx = tid + j * 256;
            int k = idx >> 4, nb = (idx & 15) * 8;
            cp_async16(base + (uint32_t)A_TILE_BYTES + (uint32_t)(k * BT * 2 + nb * 2),
                       W + (size_t)(it * 64 + k) * N + n0 + nb);
        }
    };

    load_stage(0, 0);
    CP_COMMIT();
    if (nit > 1) { load_stage(1, 1); }
    CP_COMMIT();

    for (int it = 0; it < nit; it++) {
        const int s = it % 3;
        CP_WAIT(1);
        __syncthreads();
        if (it + 2 < nit) load_stage((it + 2) % 3, it + 2);
        CP_COMMIT();

        const uint32_t sA = sb + (uint32_t)s * G_STAGE_BYTES + (uint32_t)(wm * AS * 2) + a_loff;
        const uint32_t sB = sb + (uint32_t)s * G_STAGE_BYTES + (uint32_t)A_TILE_BYTES
                          + (uint32_t)(wn * 2) + b_loff;
        #pragma unroll
        for (int kk = 0; kk < 4; kk++) {
            uint32_t afr[2][4];
            #pragma unroll
            for (int mt = 0; mt < 2; mt++)
                ldmatrix_x4(afr[mt][0], afr[mt][1], afr[mt][2], afr[mt][3],
                            sA + (uint32_t)(mt * 16 * AS * 2) + (uint32_t)(kk * 32));
            uint32_t bfr[8][2];
            #pragma unroll
            for (int np = 0; np < 4; np++)
                ldmatrix_x4_trans(bfr[2*np][0], bfr[2*np][1], bfr[2*np+1][0], bfr[2*np+1][1],
                                  sB + (uint32_t)(kk * 16 * BT * 2) + (uint32_t)(np * 32));
            #pragma unroll
            for (int mt = 0; mt < 2; mt++)
                #pragma unroll
                for (int nt = 0; nt < 8; nt++)
                    mma_f16(acc[mt][nt], afr[mt][0], afr[mt][1], afr[mt][2], afr[mt][3],
                            bfr[nt][0], bfr[nt][1]);
        }
    }

    #pragma unroll
    for (int mt = 0; mt < 2; mt++) {
        #pragma unroll
        for (int nt = 0; nt < 8; nt++) {
            const int col = n0 + wn + nt * 8 + t4 * 2;
            const float b0v = bias[col], b1v = bias[col + 1];
            const int r0 = m0 + wm + mt * 16 + grp;
            float v0 = (acc[mt][nt][0] + b0v) * oscale;
            float v1 = (acc[mt][nt][1] + b1v) * oscale;
            float v2 = (acc[mt][nt][2] + b0v) * oscale;
            float v3 = (acc[mt][nt][3] + b1v) * oscale;
            if (ACT == 1) { v0 = gelu_f(v0); v1 = gelu_f(v1); v2 = gelu_f(v2); v3 = gelu_f(v3); }
            if (HOUT) {
                __half* Ch = (__half*)Cv;
                *(uint32_t*)&Ch[(size_t)r0 * N + col]       = pack_h2(v0, v1);
                *(uint32_t*)&Ch[(size_t)(r0 + 8) * N + col] = pack_h2(v2, v3);
            } else {
                float* Cf = (float*)Cv;
                *(float2*)&Cf[(size_t)r0 * N + col]       = make_float2(v0, v1);
                *(float2*)&Cf[(size_t)(r0 + 8) * N + col] = make_float2(v2, v3);
            }
        }
    }
}

template<int ACT, int HOUT>
__global__ void __launch_bounds__(256, 2)
gemm_cp(const __half* __restrict__ A, const __half* __restrict__ W,
        const float* __restrict__ bias, void* __restrict__ C, int K, int N) {
    gemm_body<ACT, HOUT>(A, W, bias, C, K, N, blockIdx.y * 128, blockIdx.x * 128, 1.0f);
}

__global__ void __launch_bounds__(256, 2)
qkv_gemm(const __half* __restrict__ xt,
         const __half* __restrict__ wq, const __half* __restrict__ wk, const __half* __restrict__ wv,
         const float* __restrict__ bq, const float* __restrict__ bk, const float* __restrict__ bv,
         __half* __restrict__ q, __half* __restrict__ k, __half* __restrict__ v) {
    const int sel = blockIdx.x >> 3;
    const __half* W   = (sel == 0) ? wq : (sel == 1) ? wk : wv;
    const float* bias = (sel == 0) ? bq : (sel == 1) ? bk : bv;
    __half*      C    = (sel == 0) ? q  : (sel == 1) ? k  : v;
    const float scale = (sel == 0) ? 0.125f : 1.0f;
    gemm_body<0, 1>(xt, W, bias, C, DIM, DIM, blockIdx.y * 128, (blockIdx.x & 7) * 128, scale);
}

// ---------------- fp16 flash attention: 3-stage K/V pipeline, 1 sync/tile ----------------
#define HS 72
#define AT_QB  (128 * HS * 2)            // 18432 B
#define AT_TB  (64 * HS * 2)             // 9216 B
#define AT_STAGE (2 * AT_TB)             // K+V per stage = 18432 B
#define ATTN_SMEM_BYTES (AT_QB + 3 * AT_STAGE + 768)   // 74496 B

__global__ void __launch_bounds__(256, 2)
attn_mma(const __half* __restrict__ Q, const __half* __restrict__ K,
         const __half* __restrict__ V, const int* __restrict__ mask,
         __half* __restrict__ ctx) {
    extern __shared__ uint32_t asm_[];
    const uint32_t sb = smem_u32(asm_);
    float* smaskb = (float*)((char*)asm_ + AT_QB + 3 * AT_STAGE);   // [3][64]

    const int tid  = threadIdx.x;
    const int lane = tid & 31;
    const int wid  = tid >> 5;
    const int grp  = lane >> 2;
    const int t4   = lane & 3;
    const int ts   = lane >> 3;
    const int r8   = lane & 7;
    const int w16  = wid * 16;
    const int q0 = blockIdx.x * 128;
    const int h  = blockIdx.y;
    const int b  = blockIdx.z;
    const size_t base = (size_t)b * SEQ * DIM + h * DPH;

    const uint32_t q_loff = (uint32_t)(((w16 + (ts & 1) * 8 + r8) * HS) * 2 + (ts >> 1) * 16);
    const uint32_t k_loff = (uint32_t)((((ts >> 1) * 8 + r8) * HS) * 2 + (ts & 1) * 16);
    const uint32_t v_loff = (uint32_t)((((ts & 1) * 8 + r8) * HS) * 2 + (ts >> 1) * 16);

    float o[8][4];
    #pragma unroll
    for (int nf = 0; nf < 8; nf++)
        #pragma unroll
        for (int c = 0; c < 4; c++) o[nf][c] = 0.0f;
    float mrow0 = -INFINITY, mrow1 = -INFINITY;
    float l0 = 0.0f, l1 = 0.0f;

    auto load_kv = [&](int s, int it) {
        const uint32_t kb = sb + (uint32_t)AT_QB + (uint32_t)s * AT_STAGE;
        const int kv0 = it * 64;
        #pragma unroll
        for (int j = 0; j < 2; j++) {
            int idx = tid + j * 256;
            int row = idx >> 3, c = idx & 7;
            size_t g = base + (size_t)(kv0 + row) * DIM + c * 8;
            cp_async16(kb + (uint32_t)(row * HS * 2 + c * 16), K + g);
            cp_async16(kb + (uint32_t)AT_TB + (uint32_t)(row * HS * 2 + c * 16), V + g);
        }
        if (tid < 64)
            smaskb[s * 64 + tid] = (mask[b * SEQ + kv0 + tid] == 0) ? -INFINITY : 0.0f;
    };

    // prologue: Q + stage 0 in group 0; stage 1 in group 1
    {
        #pragma unroll
        for (int j = 0; j < 4; j++) {
            int idx = tid + j * 256;
            int row = idx >> 3, c = idx & 7;
            cp_async16(sb + (uint32_t)(row * HS * 2 + c * 16),
                       Q + base + (size_t)(q0 + row) * DIM + c * 8);
        }
        load_kv(0, 0);
        CP_COMMIT();
        load_kv(1, 1);
        CP_COMMIT();
    }

    const int nt_tiles = SEQ / 64;
    for (int it = 0; it < nt_tiles; it++) {
        const int s = it % 3;
        CP_WAIT(1);
        __syncthreads();
        if (it + 2 < nt_tiles) load_kv((it + 2) % 3, it + 2);
        CP_COMMIT();

        const uint32_t sbK = sb + (uint32_t)AT_QB + (uint32_t)s * AT_STAGE + k_loff;
        const uint32_t sbV = sb + (uint32_t)AT_QB + (uint32_t)s * AT_STAGE + (uint32_t)AT_TB + v_loff;
        const float* smask = smaskb + s * 64;

        float sacc[8][4];
        #pragma unroll
        for (int nf = 0; nf < 8; nf++)
            #pragma unroll
            for (int c = 0; c < 4; c++) sacc[nf][c] = 0.0f;
        #pragma unroll
        for (int kk = 0; kk < 4; kk++) {
            const uint32_t kb = kk * 32;
            uint32_t qa0, qa1, qa2, qa3;
            ldmatrix_x4(qa0, qa1, qa2, qa3, sb + q_loff + kb);
            #pragma unroll
            for (int np = 0; np < 4; np++) {
                uint32_t b00, b01, b10, b11;
                ldmatrix_x4(b00, b01, b10, b11,
                            sbK + (uint32_t)(np * 16 * HS * 2) + kb);
                mma_f16(sacc[2*np],   qa0, qa1, qa2, qa3, b00, b01);
                mma_f16(sacc[2*np+1], qa0, qa1, qa2, qa3, b10, b11);
            }
        }

        #pragma unroll
        for (int nf = 0; nf < 8; nf++) {
            float mv0 = smask[nf * 8 + t4 * 2];
            float mv1 = smask[nf * 8 + t4 * 2 + 1];
            sacc[nf][0] += mv0; sacc[nf][1] += mv1;
            sacc[nf][2] += mv0; sacc[nf][3] += mv1;
        }

        float mt0 = -INFINITY, mt1 = -INFINITY;
        #pragma unroll
        for (int nf = 0; nf < 8; nf++) {
            mt0 = fmaxf(mt0, fmaxf(sacc[nf][0], sacc[nf][1]));
            mt1 = fmaxf(mt1, fmaxf(sacc[nf][2], sacc[nf][3]));
        }
        mt0 = fmaxf(mt0, __shfl_xor_sync(0xffffffffu, mt0, 1));
        mt0 = fmaxf(mt0, __shfl_xor_sync(0xffffffffu, mt0, 2));
        mt1 = fmaxf(mt1, __shfl_xor_sync(0xffffffffu, mt1, 1));
        mt1 = fmaxf(mt1, __shfl_xor_sync(0xffffffffu, mt1, 2));
        float mnew0 = fmaxf(mrow0, mt0);
        float mnew1 = fmaxf(mrow1, mt1);
        float alpha0 = __expf(mrow0 - mnew0);
        float alpha1 = __expf(mrow1 - mnew1);
        float lsum0 = 0.0f, lsum1 = 0.0f;
        #pragma unroll
        for (int nf = 0; nf < 8; nf++) {
            sacc[nf][0] = __expf(sacc[nf][0] - mnew0);
            sacc[nf][1] = __expf(sacc[nf][1] - mnew0);
            sacc[nf][2] = __expf(sacc[nf][2] - mnew1);
            sacc[nf][3] = __expf(sacc[nf][3] - mnew1);
            lsum0 += sacc[nf][0] + sacc[nf][1];
            lsum1 += sacc[nf][2] + sacc[nf][3];
        }
        lsum0 += __shfl_xor_sync(0xffffffffu, lsum0, 1);
        lsum0 += __shfl_xor_sync(0xffffffffu, lsum0, 2);
        lsum1 += __shfl_xor_sync(0xffffffffu, lsum1, 1);
        lsum1 += __shfl_xor_sync(0xffffffffu, lsum1, 2);
        l0 = l0 * alpha0 + lsum0;
        l1 = l1 * alpha1 + lsum1;
        mrow0 = mnew0; mrow1 = mnew1;
        #pragma unroll
        for (int nf = 0; nf < 8; nf++) {
            o[nf][0] *= alpha0; o[nf][1] *= alpha0;
            o[nf][2] *= alpha1; o[nf][3] *= alpha1;
        }

        #pragma unroll
        for (int c = 0; c < 4; c++) {
            uint32_t a0 = pack_h2(sacc[2*c][0],   sacc[2*c][1]);
            uint32_t a1 = pack_h2(sacc[2*c][2],   sacc[2*c][3]);
            uint32_t a2 = pack_h2(sacc[2*c+1][0], sacc[2*c+1][1]);
            uint32_t a3 = pack_h2(sacc[2*c+1][2], sacc[2*c+1][3]);
            const uint32_t rowoff = (uint32_t)(c * 16 * HS * 2);
            #pragma unroll
            for (int np = 0; np < 4; np++) {
                uint32_t b00, b01, b10, b11;
                ldmatrix_x4_trans(b00, b01, b10, b11,
                                  sbV + rowoff + (uint32_t)(np * 32));
                mma_f16(o[2*np],   a0, a1, a2, a3, b00, b01);
                mma_f16(o[2*np+1], a0, a1, a2, a3, b10, b11);
            }
        }
    }

    const float inv0 = 1.0f / l0;
    const float inv1 = 1.0f / l1;
    const int r0 = q0 + w16 + grp;
    #pragma unroll
    for (int nf = 0; nf < 8; nf++) {
        const int d0 = nf * 8 + t4 * 2;
        *(uint32_t*)&ctx[base + (size_t)r0 * DIM + d0] =
            pack_h2(o[nf][0] * inv0, o[nf][1] * inv0);
        *(uint32_t*)&ctx[base + (size_t)(r0 + 8) * DIM + d0] =
            pack_h2(o[nf][2] * inv1, o[nf][3] * inv1);
    }
}

// ---------------- residual + LayerNorm (float4) ----------------
template<int HOUT>
__global__ void ln_residual_kernel(const float* __restrict__ a,
                                   const float* __restrict__ r,
                                   const float* __restrict__ gamma,
                                   const float* __restrict__ beta,
                                   float* __restrict__ out,
                                   __half* __restrict__ out_t) {
    const int row = blockIdx.x;
    const int tid = threadIdx.x;
    const float* pa = a + (size_t)row * DIM;
    const float* pr = r + (size_t)row * DIM;

    float4 va = ((const float4*)pa)[tid];
    float4 vr = ((const float4*)pr)[tid];
    float v[4] = { va.x + vr.x, va.y + vr.y, va.z + vr.z, va.w + vr.w };
    float sum = v[0] + v[1] + v[2] + v[3];
    float sq  = v[0]*v[0] + v[1]*v[1] + v[2]*v[2] + v[3]*v[3];

    #pragma unroll
    for (int off = 16; off >= 1; off >>= 1) {
        sum += __shfl_xor_sync(0xffffffffu, sum, off);
        sq  += __shfl_xor_sync(0xffffffffu, sq,  off);
    }
    __shared__ float ssum[8], ssq[8];
    int warp = tid >> 5, lane = tid & 31;
    if (lane == 0) { ssum[warp] = sum; ssq[warp] = sq; }
    __syncthreads();
    sum = 0.0f; sq = 0.0f;
    #pragma unroll
    for (int i = 0; i < 8; i++) { sum += ssum[i]; sq += ssq[i]; }

    const float invN = 1.0f / (float)DIM;
    float mu  = sum * invN;
    float var = fmaxf(sq * invN - mu * mu, 0.0f);
    float rstd = rsqrtf(var + 1e-12f);

    float4 g4 = ((const float4*)gamma)[tid];
    float4 b4 = ((const float4*)beta)[tid];
    float4 o4;
    o4.x = (v[0] - mu) * rstd * g4.x + b4.x;
    o4.y = (v[1] - mu) * rstd * g4.y + b4.y;
    o4.z = (v[2] - mu) * rstd * g4.z + b4.z;
    o4.w = (v[3] - mu) * rstd * g4.w + b4.w;
    ((float4*)(out + (size_t)row * DIM))[tid] = o4;
    if (HOUT) {
        uint2 u;
        u.x = pack_h2(o4.x, o4.y);
        u.y = pack_h2(o4.z, o4.w);
        ((uint2*)(out_t + (size_t)row * DIM))[tid] = u;
    }
}

// ---------------- launch ----------------
extern "C" void kernel_launch(void* const* d_in, const int* in_sizes, int n_in,
                              void* d_out, int out_size) {
    const float* x    = (const float*)d_in[0];
    const int*   mask = (const int*)  d_in[1];
    const float* Wq   = (const float*)d_in[2];
    const float* bq   = (const float*)d_in[3];
    const float* Wk   = (const float*)d_in[4];
    const float* bk   = (const float*)d_in[5];
    const float* Wv   = (const float*)d_in[6];
    const float* bv   = (const float*)d_in[7];
    const float* Wo   = (const float*)d_in[8];
    const float* bo   = (const float*)d_in[9];
    const float* ln1g = (const float*)d_in[10];
    const float* ln1b = (const float*)d_in[11];
    const float* W1   = (const float*)d_in[12];
    const float* b1   = (const float*)d_in[13];
    const float* W2   = (const float*)d_in[14];
    const float* b2   = (const float*)d_in[15];
    const float* ln2g = (const float*)d_in[16];
    const float* ln2b = (const float*)d_in[17];
    float* out = (float*)d_out;

    __half *q, *k, *v, *ctx, *h1t, *ffn, *xt, *wqh, *wkh, *wvh, *woh, *w1h, *w2h;
    float *sa, *h1, *f2;
    cudaGetSymbolAddress((void**)&q,   g_q);
    cudaGetSymbolAddress((void**)&k,   g_k);
    cudaGetSymbolAddress((void**)&v,   g_v);
    cudaGetSymbolAddress((void**)&ctx, g_ctx);
    cudaGetSymbolAddress((void**)&h1t, g_h1t);
    cudaGetSymbolAddress((void**)&ffn, g_ffn);
    cudaGetSymbolAddress((void**)&xt,  g_xt);
    cudaGetSymbolAddress((void**)&wqh, g_wqh);
    cudaGetSymbolAddress((void**)&wkh, g_wkh);
    cudaGetSymbolAddress((void**)&wvh, g_wvh);
    cudaGetSymbolAddress((void**)&woh, g_woh);
    cudaGetSymbolAddress((void**)&w1h, g_w1h);
    cudaGetSymbolAddress((void**)&w2h, g_w2h);
    cudaGetSymbolAddress((void**)&sa,  g_sa);
    cudaGetSymbolAddress((void**)&h1,  g_h1);
    cudaGetSymbolAddress((void**)&f2,  g_f2);

    cudaFuncSetAttribute(qkv_gemm,      cudaFuncAttributeMaxDynamicSharedMemorySize, GEMM_SMEM_BYTES);
    cudaFuncSetAttribute(gemm_cp<0,0>,  cudaFuncAttributeMaxDynamicSharedMemorySize, GEMM_SMEM_BYTES);
    cudaFuncSetAttribute(gemm_cp<1,1>,  cudaFuncAttributeMaxDynamicSharedMemorySize, GEMM_SMEM_BYTES);
    cudaFuncSetAttribute(attn_mma,      cudaFuncAttributeMaxDynamicSharedMemorySize, ATTN_SMEM_BYTES);

    // single merged prep pass
    cvt_all_kernel<<<2048, 256>>>(x, Wq, Wk, Wv, Wo, W1, W2,
                                  xt, wqh, wkh, wvh, woh, w1h, w2h);

    // fused QKV (fp16 out; q pre-scaled by 0.125)
    qkv_gemm<<<dim3(24, MROWS/128), 256, GEMM_SMEM_BYTES>>>(xt, wqh, wkh, wvh, bq, bk, bv, q, k, v);

    // attention (fp16 in/out)
    attn_mma<<<dim3(SEQ/128, NH, BS), 256, ATTN_SMEM_BYTES>>>(q, k, v, mask, ctx);

    // Wo projection -> sa_out fp32
    gemm_cp<0,0><<<dim3(DIM/128, MROWS/128), 256, GEMM_SMEM_BYTES>>>(ctx, woh, bo, sa, DIM, DIM);

    // LN1(sa + x) -> h1 fp32 + h1t fp16
    ln_residual_kernel<1><<<MROWS, 256>>>(sa, x, ln1g, ln1b, h1, h1t);

    // FFN1 (gelu, fp16 out), FFN2 (fp32 out)
    gemm_cp<1,1><<<dim3(HID/128, MROWS/128), 256, GEMM_SMEM_BYTES>>>(h1t, w1h, b1, ffn, DIM, HID);
    gemm_cp<0,0><<<dim3(DIM/128, MROWS/128), 256, GEMM_SMEM_BYTES>>>(ffn, w2h, b2, f2, HID, DIM);

    // LN2(f2 + h1) -> out
    ln_residual_kernel<0><<<MROWS, 256>>>(f2, h1, ln2g, ln2b, out, nullptr);
}